// round 5
// baseline (speedup 1.0000x reference)
#include <cuda_runtime.h>
#include <cstdint>
#include <math.h>

#define BATCH 4
#define SEQ   2048
#define EMB   1024
#define HEADS 16
#define HDIM  64
#define MROWS (BATCH*SEQ)   /* 8192 */
#define L2E   1.4426950408889634f

// Scratch (device globals: allocation-free per harness rules)
__device__ float g_qkv[(size_t)MROWS * 3 * EMB];   // [8192, 3072] rna(tf32), Q pre-scaled
__device__ float g_att[(size_t)MROWS * EMB];       // [8192, 1024] rna(tf32)
__device__ float g_xc [(size_t)MROWS * EMB];       // x, rna(tf32)
__device__ float g_wqt[(size_t)3 * EMB * EMB];     // W_qkv^T, rna
__device__ float g_wot[(size_t)EMB * EMB];         // W_out^T, rna

// ---------------------------------------------------------------------------
// helpers (portable PTX only)
// ---------------------------------------------------------------------------
__device__ __forceinline__ uint32_t smem_u32(const void* p) {
    uint32_t a;
    asm("{ .reg .u64 t; cvta.to.shared.u64 t, %1; cvt.u32.u64 %0, t; }" : "=r"(a) : "l"(p));
    return a;
}
__device__ __forceinline__ float rna_tf32(float v) {
    uint32_t u;
    asm("cvt.rna.tf32.f32 %0, %1;" : "=r"(u) : "f"(v));
    return __uint_as_float(u);
}
__device__ __forceinline__ float fexp2(float x) {
    float y;
    asm("ex2.approx.f32 %0, %1;" : "=f"(y) : "f"(x));
    return y;
}
__device__ __forceinline__ void cp_async16(uint32_t dst, const void* src) {
    asm volatile("cp.async.cg.shared.global [%0], [%1], 16;" :: "r"(dst), "l"(src));
}
__device__ __forceinline__ void cp_commit() {
    asm volatile("cp.async.commit_group;" ::: "memory");
}
template <int N>
__device__ __forceinline__ void cp_wait() {
    asm volatile("cp.async.wait_group %0;" :: "n"(N) : "memory");
}
__device__ __forceinline__ void mma_tf32(float& c0, float& c1, float& c2, float& c3,
                                         uint32_t a0, uint32_t a1, uint32_t a2, uint32_t a3,
                                         uint32_t b0, uint32_t b1) {
    asm volatile(
        "mma.sync.aligned.m16n8k8.row.col.f32.tf32.tf32.f32 "
        "{%0,%1,%2,%3}, {%4,%5,%6,%7}, {%8,%9}, {%0,%1,%2,%3};"
        : "+f"(c0), "+f"(c1), "+f"(c2), "+f"(c3)
        : "r"(a0), "r"(a1), "r"(a2), "r"(a3), "r"(b0), "r"(b1));
}

// ---------------------------------------------------------------------------
__global__ void convert_rna_kernel(const float* __restrict__ src,
                                   float* __restrict__ dst, int n4) {
    int i = blockIdx.x * blockDim.x + threadIdx.x;
    if (i < n4) {
        float4 v = ((const float4*)src)[i];
        v.x = rna_tf32(v.x); v.y = rna_tf32(v.y);
        v.z = rna_tf32(v.z); v.w = rna_tf32(v.w);
        ((float4*)dst)[i] = v;
    }
}

__global__ void transpose_rna_kernel(const float* __restrict__ W,
                                     float* __restrict__ Wt, int K, int N) {
    __shared__ float t[32][33];
    const int n0 = blockIdx.x * 32, k0 = blockIdx.y * 32;
    const int x = threadIdx.x, y = threadIdx.y;  // 32 x 8
    #pragma unroll
    for (int i = 0; i < 4; i++)
        t[y + i * 8][x] = W[(size_t)(k0 + y + i * 8) * N + n0 + x];
    __syncthreads();
    #pragma unroll
    for (int i = 0; i < 4; i++)
        Wt[(size_t)(n0 + y + i * 8) * K + k0 + x] = rna_tf32(t[x][y + i * 8]);
}

// ---------------------------------------------------------------------------
// tf32 mma.sync GEMM: C[M,N] = A[M,K] @ Bt[N,K]^T + bias[N]
// CTA tile 256x128, BK=16, 3-stage cp.async. 8 warps (4x2), warp tile 64x64:
// 32 MMAs vs 32 fragment words per k-step (1.0 LDS-word/MMA, was 1.5).
// mode=1 -> rna output, Q cols (<1024) x0.125.
// ---------------------------------------------------------------------------
#define BK 16
#define SROW 20
#define ATILE_FLOATS (256 * SROW)    /* 5120 */
#define BTILE_FLOATS (128 * SROW)    /* 2560 */
#define STAGE_FLOATS (ATILE_FLOATS + BTILE_FLOATS)
#define NSTAGE 3
#define GEMM_SMEM (NSTAGE * STAGE_FLOATS * 4)   /* 92160 B */

__global__ __launch_bounds__(256, 1)
void gemm_tf32_kernel(const float* __restrict__ A, const float* __restrict__ Bt,
                      const float* __restrict__ bias, float* __restrict__ C,
                      int M, int N, int K, int mode)
{
    extern __shared__ __align__(16) float sm[];

    const int tid  = threadIdx.x;
    const int wid  = tid >> 5;
    const int lane = tid & 31;
    const int wm   = (wid >> 1) * 64;   // 4 warps down M (256)
    const int wn   = (wid & 1) * 64;    // 2 warps across N (128)
    const int lr   = lane >> 2;
    const int lc   = lane & 3;
    const int n0   = blockIdx.x * 128;
    const int m0   = blockIdx.y * 256;
    const uint32_t smb = smem_u32(sm);

    float c[4][8][4];                   // [mt][nt][reg]
    #pragma unroll
    for (int i = 0; i < 4; i++)
        #pragma unroll
        for (int j = 0; j < 8; j++)
            #pragma unroll
            for (int r = 0; r < 4; r++) c[i][j][r] = 0.f;

    auto load_stage = [&](int ch, int s) {
        const float* Ab = A  + (size_t)m0 * K + ch * BK;
        const float* Bb = Bt + (size_t)n0 * K + ch * BK;
        const uint32_t sA = smb + (uint32_t)(s * STAGE_FLOATS) * 4u;
        const uint32_t sB = sA + ATILE_FLOATS * 4u;
        #pragma unroll
        for (int i = 0; i < 4; i++) {               // A: 256 rows x 4 float4
            const int chk = i * 256 + tid;          // 0..1023
            const int row = chk >> 2, c4 = chk & 3;
            const uint32_t off = (uint32_t)(row * SROW + c4 * 4) * 4u;
            cp_async16(sA + off, Ab + (size_t)row * K + c4 * 4);
        }
        #pragma unroll
        for (int i = 0; i < 2; i++) {               // B: 128 rows x 4 float4
            const int chk = i * 256 + tid;          // 0..511
            const int row = chk >> 2, c4 = chk & 3;
            const uint32_t off = (uint32_t)(row * SROW + c4 * 4) * 4u;
            cp_async16(sB + off, Bb + (size_t)row * K + c4 * 4);
        }
    };

    const int NCH = K / BK;

    load_stage(0, 0); cp_commit();
    load_stage(1, 1); cp_commit();

    for (int ch = 0; ch < NCH; ch++) {
        cp_wait<1>();
        __syncthreads();
        if (ch + 2 < NCH) load_stage(ch + 2, (ch + 2) % NSTAGE);
        cp_commit();

        const float* As = sm + (ch % NSTAGE) * STAGE_FLOATS;
        const float* Bs = As + ATILE_FLOATS;

        #pragma unroll
        for (int ks = 0; ks < 2; ks++) {
            const int dk = ks * 8;
            uint32_t af[4][4], bf[8][2];
            #pragma unroll
            for (int mt = 0; mt < 4; mt++) {
                const float* ap = As + (wm + mt * 16 + lr) * SROW + dk + lc;
                af[mt][0] = __float_as_uint(ap[0]);
                af[mt][1] = __float_as_uint(ap[8 * SROW]);
                af[mt][2] = __float_as_uint(ap[4]);
                af[mt][3] = __float_as_uint(ap[8 * SROW + 4]);
            }
            #pragma unroll
            for (int nt = 0; nt < 8; nt++) {
                const float* bp = Bs + (wn + nt * 8 + lr) * SROW + dk + lc;
                bf[nt][0] = __float_as_uint(bp[0]);
                bf[nt][1] = __float_as_uint(bp[4]);
            }
            #pragma unroll
            for (int mt = 0; mt < 4; mt++)
                #pragma unroll
                for (int nt = 0; nt < 8; nt++)
                    mma_tf32(c[mt][nt][0], c[mt][nt][1], c[mt][nt][2], c[mt][nt][3],
                             af[mt][0], af[mt][1], af[mt][2], af[mt][3],
                             bf[nt][0], bf[nt][1]);
        }
        __syncthreads();
    }

    #pragma unroll
    for (int nt = 0; nt < 8; nt++) {
        const int col = n0 + wn + nt * 8 + 2 * lc;
        const float b0 = bias[col], b1 = bias[col + 1];
        const float sc = (mode && col < 1024) ? 0.125f : 1.0f;
        #pragma unroll
        for (int mt = 0; mt < 4; mt++) {
            const size_t r0 = (size_t)(m0 + wm + mt * 16 + lr);
            float v0 = (c[mt][nt][0] + b0) * sc;
            float v1 = (c[mt][nt][1] + b1) * sc;
            float v2 = (c[mt][nt][2] + b0) * sc;
            float v3 = (c[mt][nt][3] + b1) * sc;
            if (mode) {
                v0 = rna_tf32(v0); v1 = rna_tf32(v1);
                v2 = rna_tf32(v2); v3 = rna_tf32(v3);
            }
            *(float2*)(&C[r0 * N + col])       = make_float2(v0, v1);
            *(float2*)(&C[(r0 + 8) * N + col]) = make_float2(v2, v3);
        }
    }
}

// ---------------------------------------------------------------------------
// Flash attention with tf32 mma.sync (unchanged from R4 — near its MMA floor).
// ---------------------------------------------------------------------------
#define QS_OFF 0                 /* Q  [128][68]  */
#define PS_OFF 8704              /* P  [128][132] */
#define KS_OFF 25600             /* K  [128][68]  */
#define VR_OFF 34304             /* V  [128][68]  */
#define VT_OFF 43008             /* Vt [64][132]  */
#define ATT_SMEM ((43008 + 64 * 132) * 4)   /* 205824 B */

__global__ __launch_bounds__(256, 1)
void attn_mma_kernel(const float* __restrict__ qkv, float* __restrict__ out)
{
    extern __shared__ __align__(16) float sa[];

    const int tid  = threadIdx.x;
    const int wid  = tid >> 5;
    const int lane = tid & 31;
    const int lr   = lane >> 2;
    const int lc   = lane & 3;
    const int wm   = wid * 16;
    const int qt   = blockIdx.x;
    const int h    = blockIdx.y;
    const int b    = blockIdx.z;
    const int q0   = qt * 128;
    const float slope = fexp2(-0.5f * (float)(h + 1));
    const uint32_t smb = smem_u32(sa);

    const float* baseQ = qkv + (size_t)b * SEQ * 3072 + h * 64;
    const float* baseK = baseQ + 1024;
    const float* baseV = baseQ + 2048;

    auto load_tile = [&](const float* g, int row0, int soff) {
        #pragma unroll
        for (int i = 0; i < 8; i++) {
            const int chk = i * 256 + tid;          // 0..2047
            const int row = chk >> 4, c4 = chk & 15;
            cp_async16(smb + (uint32_t)(soff + row * 68 + c4 * 4) * 4u,
                       g + (size_t)(row0 + row) * 3072 + c4 * 4);
        }
    };

    load_tile(baseQ, q0, QS_OFF); cp_commit();
    load_tile(baseK, 0,  KS_OFF); cp_commit();
    load_tile(baseV, 0,  VR_OFF); cp_commit();

    float m0 = -1e30f, m1 = -1e30f, l0 = 0.f, l1 = 0.f;
    float o[8][4];
    #pragma unroll
    for (int i = 0; i < 8; i++)
        #pragma unroll
        for (int r = 0; r < 4; r++) o[i][r] = 0.f;

    const int qrow0 = q0 + wm + lr;
    const int qrow1 = qrow0 + 8;

    for (int kt = 0; kt <= qt; kt++) {
        cp_wait<1>();          // K(kt) (and Q) resident; V(kt) may still fly
        __syncthreads();

        // ---- S = Q @ K^T ----
        float c[16][4];
        #pragma unroll
        for (int nt = 0; nt < 16; nt++)
            #pragma unroll
            for (int r = 0; r < 4; r++) c[nt][r] = 0.f;

        #pragma unroll
        for (int dk = 0; dk < 8; dk++) {
            const float* ap = sa + QS_OFF + (wm + lr) * 68 + dk * 8 + lc;
            const uint32_t a0 = __float_as_uint(ap[0]);
            const uint32_t a1 = __float_as_uint(ap[8 * 68]);
            const uint32_t a2 = __float_as_uint(ap[4]);
            const uint32_t a3 = __float_as_uint(ap[8 * 68 + 4]);
            #pragma unroll
            for (int nt = 0; nt < 16; nt++) {
                const float* bp = sa + KS_OFF + (nt * 8 + lr) * 68 + dk * 8 + lc;
                mma_tf32(c[nt][0], c[nt][1], c[nt][2], c[nt][3],
                         a0, a1, a2, a3,
                         __float_as_uint(bp[0]), __float_as_uint(bp[4]));
            }
        }
        __syncthreads();       // done reading Ks
        if (kt < qt) load_tile(baseK, (kt + 1) * 128, KS_OFF);
        cp_commit();

        // ---- ALiBi + (diagonal-only) mask + online softmax ----
        const int kb = kt * 128 + 2 * lc;
        {
            float al0 = slope * (float)(kb - qrow0);
            float al1 = slope * (float)(kb - qrow1);
            const float st8 = 8.f * slope;
            float mx0 = -1e30f, mx1 = -1e30f;
            #pragma unroll
            for (int nt = 0; nt < 16; nt++) {
                float s0 = c[nt][0] + al0;
                float s1 = c[nt][1] + al0 + slope;
                float s2 = c[nt][2] + al1;
                float s3 = c[nt][3] + al1 + slope;
                if (kt == qt) {       // masking only possible on the diagonal tile
                    const int k0c = kb + nt * 8, k1c = k0c + 1;
                    if (k0c > qrow0) s0 = -1e30f;
                    if (k1c > qrow0) s1 = -1e30f;
                    if (k0c > qrow1) s2 = -1e30f;
                    if (k1c > qrow1) s3 = -1e30f;
                }
                c[nt][0] = s0; c[nt][1] = s1; c[nt][2] = s2; c[nt][3] = s3;
                mx0 = fmaxf(mx0, fmaxf(s0, s1));
                mx1 = fmaxf(mx1, fmaxf(s2, s3));
                al0 += st8; al1 += st8;
            }
            mx0 = fmaxf(mx0, __shfl_xor_sync(0xffffffffu, mx0, 1));
            mx0 = fmaxf(mx0, __shfl_xor_sync(0xffffffffu, mx0, 2));
            mx1 = fmaxf(mx1, __shfl_xor_sync(0xffffffffu, mx1, 1));
            mx1 = fmaxf(mx1, __shfl_xor_sync(0xffffffffu, mx1, 2));

            const float mn0 = fmaxf(m0, mx0), mn1 = fmaxf(m1, mx1);
            const float corr0 = fexp2((m0 - mn0) * L2E);
            const float corr1 = fexp2((m1 - mn1) * L2E);
            m0 = mn0; m1 = mn1;

            float ts0 = 0.f, ts1 = 0.f;
            float* p0 = sa + PS_OFF + (wm + lr) * 132 + 2 * lc;
            float* p1 = p0 + 8 * 132;
            #pragma unroll
            for (int nt = 0; nt < 16; nt++) {
                const float e0 = rna_tf32(fexp2((c[nt][0] - mn0) * L2E));
                const float e1 = rna_tf32(fexp2((c[nt][1] - mn0) * L2E));
                const float e2 = rna_tf32(fexp2((c[nt][2] - mn1) * L2E));
                const float e3 = rna_tf32(fexp2((c[nt][3] - mn1) * L2E));
                ts0 += e0 + e1;
                ts1 += e2 + e3;
                *(float2*)(p0 + nt * 8) = make_float2(e0, e1);
                *(float2*)(p1 + nt * 8) = make_float2(e2, e3);
            }
            ts0 += __shfl_xor_sync(0xffffffffu, ts0, 1);
            ts0 += __shfl_xor_sync(0xffffffffu, ts0, 2);
            ts1 += __shfl_xor_sync(0xffffffffu, ts1, 1);
            ts1 += __shfl_xor_sync(0xffffffffu, ts1, 2);
            l0 = l0 * corr0 + ts0;
            l1 = l1 * corr1 + ts1;
            #pragma unroll
            for (int i = 0; i < 8; i++) {
                o[i][0] *= corr0; o[i][1] *= corr0;
                o[i][2] *= corr1; o[i][3] *= corr1;
            }
        }

        cp_wait<1>();          // V(kt) resident; K(kt+1) may still fly
        __syncthreads();

        // ---- transpose V [128][64] -> Vt [64][128] ----
        {
            const int kvr = tid & 127;
            const int dc  = (tid >> 7) * 32;
            #pragma unroll
            for (int j = 0; j < 32; j += 4) {
                float4 v = *(const float4*)(sa + VR_OFF + kvr * 68 + dc + j);
                sa[VT_OFF + (dc + j + 0) * 132 + kvr] = v.x;
                sa[VT_OFF + (dc + j + 1) * 132 + kvr] = v.y;
                sa[VT_OFF + (dc + j + 2) * 132 + kvr] = v.z;
                sa[VT_OFF + (dc + j + 3) * 132 + kvr] = v.w;
            }
        }
        __syncthreads();

        // ---- O += P @ V ----
        #pragma unroll
        for (int dk = 0; dk < 16; dk++) {
            const float* pp = sa + PS_OFF + (wm + lr) * 132 + dk * 8 + lc;
            const uint32_t a0 = __float_as_uint(pp[0]);
            const uint32_t a1 = __float_as_uint(pp[8 * 132]);
            const uint32_t a2 = __float_as_uint(pp[4]);
            const uint32_t a3 = __float_as_uint(pp[8 * 132 + 4]);
            #pragma unroll
            for (int nt2 = 0; nt2 < 8; nt2++) {
                const float* bp = sa + VT_OFF + (nt2 * 8 + lr) * 132 + dk * 8 + lc;
                mma_tf32(o[nt2][0], o[nt2][1], o[nt2][2], o[nt2][3],
                         a0, a1, a2, a3,
                         __float_as_uint(bp[0]), __float_as_uint(bp[4]));
            }
        }
        __syncthreads();       // all warps done with Vt (and Vrm consumed)
        if (kt < qt) load_tile(baseV, (kt + 1) * 128, VR_OFF);
        cp_commit();
    }

    // ---- epilogue: normalize, rna (feeds tf32 out-projection) ----
    const float inv0 = 1.f / l0, inv1 = 1.f / l1;
    float* og = out + ((size_t)b * SEQ + qrow0) * EMB + h * HDIM + 2 * lc;
    #pragma unroll
    for (int nt2 = 0; nt2 < 8; nt2++) {
        *(float2*)(og + nt2 * 8) =
            make_float2(rna_tf32(o[nt2][0] * inv0), rna_tf32(o[nt2][1] * inv0));
        *(float2*)(og + 8 * EMB + nt2 * 8) =
            make_float2(rna_tf32(o[nt2][2] * inv1), rna_tf32(o[nt2][3] * inv1));
    }
}

// ---------------------------------------------------------------------------
extern "C" void kernel_launch(void* const* d_in, const int* in_sizes, int n_in,
                              void* d_out, int out_size)
{
    const float* x    = (const float*)d_in[0];
    // d_in[1] = mask (bool tril) — causality handled analytically
    const float* Wqkv = (const float*)d_in[2];
    const float* bqkv = (const float*)d_in[3];
    const float* Wout = (const float*)d_in[4];
    const float* bout = (const float*)d_in[5];
    float* out = (float*)d_out;

    float *qkv_p, *att_p, *xc_p, *wqt_p, *wot_p;
    cudaGetSymbolAddress((void**)&qkv_p, g_qkv);
    cudaGetSymbolAddress((void**)&att_p, g_att);
    cudaGetSymbolAddress((void**)&xc_p,  g_xc);
    cudaGetSymbolAddress((void**)&wqt_p, g_wqt);
    cudaGetSymbolAddress((void**)&wot_p, g_wot);

    cudaFuncSetAttribute(gemm_tf32_kernel,
                         cudaFuncAttributeMaxDynamicSharedMemorySize, GEMM_SMEM);
    cudaFuncSetAttribute(attn_mma_kernel,
                         cudaFuncAttributeMaxDynamicSharedMemorySize, ATT_SMEM);

    // 0) tf32-round operands
    {
        const int n4 = MROWS * EMB / 4;
        convert_rna_kernel<<<(n4 + 255) / 256, 256>>>(x, xc_p, n4);
    }
    transpose_rna_kernel<<<dim3(3 * EMB / 32, EMB / 32), dim3(32, 8)>>>(Wqkv, wqt_p, EMB, 3 * EMB);
    transpose_rna_kernel<<<dim3(EMB / 32, EMB / 32),     dim3(32, 8)>>>(Wout, wot_p, EMB, EMB);

    // 1) qkv = x @ W_qkv + b_qkv; epilogue rna + Q*0.125 (mode=1)
    gemm_tf32_kernel<<<dim3(3 * EMB / 128, MROWS / 256), 256, GEMM_SMEM>>>(
        xc_p, wqt_p, bqkv, qkv_p, MROWS, 3 * EMB, EMB, 1);

    // 2) attention (tf32 mma.sync, causal + ALiBi fused)
    attn_mma_kernel<<<dim3(SEQ / 128, HEADS, BATCH), 256, ATT_SMEM>>>(qkv_p, att_p);

    // 3) out = att @ W_out + b_out (mode=0: plain fp32 output)
    gemm_tf32_kernel<<<dim3(EMB / 128, MROWS / 256), 256, GEMM_SMEM>>>(
        att_p, wot_p, bout, out, MROWS, EMB, EMB, 0);
}

// round 6
// speedup vs baseline: 1.0498x; 1.0498x over previous
#include <cuda_runtime.h>
#include <cstdint>
#include <math.h>

#define BATCH 4
#define SEQ   2048
#define EMB   1024
#define HEADS 16
#define HDIM  64
#define MROWS (BATCH*SEQ)   /* 8192 */
#define L2E   1.4426950408889634f

// Scratch (device globals: allocation-free per harness rules)
__device__ float g_qkv[(size_t)MROWS * 3 * EMB];   // [8192, 3072] rna(tf32), Q pre-scaled
__device__ float g_att[(size_t)MROWS * EMB];       // [8192, 1024] rna(tf32)
__device__ float g_xc [(size_t)MROWS * EMB];       // x, rna(tf32)
__device__ float g_wqt[(size_t)3 * EMB * EMB];     // W_qkv^T, rna
__device__ float g_wot[(size_t)EMB * EMB];         // W_out^T, rna

// ---------------------------------------------------------------------------
// helpers (portable PTX only)
// ---------------------------------------------------------------------------
__device__ __forceinline__ uint32_t smem_u32(const void* p) {
    uint32_t a;
    asm("{ .reg .u64 t; cvta.to.shared.u64 t, %1; cvt.u32.u64 %0, t; }" : "=r"(a) : "l"(p));
    return a;
}
__device__ __forceinline__ float rna_tf32(float v) {
    uint32_t u;
    asm("cvt.rna.tf32.f32 %0, %1;" : "=r"(u) : "f"(v));
    return __uint_as_float(u);
}
__device__ __forceinline__ float fexp2(float x) {
    float y;
    asm("ex2.approx.f32 %0, %1;" : "=f"(y) : "f"(x));
    return y;
}
__device__ __forceinline__ void cp_async16(uint32_t dst, const void* src) {
    asm volatile("cp.async.cg.shared.global [%0], [%1], 16;" :: "r"(dst), "l"(src));
}
__device__ __forceinline__ void cp_commit() {
    asm volatile("cp.async.commit_group;" ::: "memory");
}
template <int N>
__device__ __forceinline__ void cp_wait() {
    asm volatile("cp.async.wait_group %0;" :: "n"(N) : "memory");
}
__device__ __forceinline__ void mma_tf32(float& c0, float& c1, float& c2, float& c3,
                                         uint32_t a0, uint32_t a1, uint32_t a2, uint32_t a3,
                                         uint32_t b0, uint32_t b1) {
    asm volatile(
        "mma.sync.aligned.m16n8k8.row.col.f32.tf32.tf32.f32 "
        "{%0,%1,%2,%3}, {%4,%5,%6,%7}, {%8,%9}, {%0,%1,%2,%3};"
        : "+f"(c0), "+f"(c1), "+f"(c2), "+f"(c3)
        : "r"(a0), "r"(a1), "r"(a2), "r"(a3), "r"(b0), "r"(b1));
}

// ---------------------------------------------------------------------------
__global__ void convert_rna_kernel(const float* __restrict__ src,
                                   float* __restrict__ dst, int n4) {
    int i = blockIdx.x * blockDim.x + threadIdx.x;
    if (i < n4) {
        float4 v = ((const float4*)src)[i];
        v.x = rna_tf32(v.x); v.y = rna_tf32(v.y);
        v.z = rna_tf32(v.z); v.w = rna_tf32(v.w);
        ((float4*)dst)[i] = v;
    }
}

__global__ void transpose_rna_kernel(const float* __restrict__ W,
                                     float* __restrict__ Wt, int K, int N) {
    __shared__ float t[32][33];
    const int n0 = blockIdx.x * 32, k0 = blockIdx.y * 32;
    const int x = threadIdx.x, y = threadIdx.y;  // 32 x 8
    #pragma unroll
    for (int i = 0; i < 4; i++)
        t[y + i * 8][x] = W[(size_t)(k0 + y + i * 8) * N + n0 + x];
    __syncthreads();
    #pragma unroll
    for (int i = 0; i < 4; i++)
        Wt[(size_t)(n0 + y + i * 8) * K + k0 + x] = rna_tf32(t[x][y + i * 8]);
}

// ---------------------------------------------------------------------------
// tf32 mma.sync GEMM: C[M,N] = A[M,K] @ Bt[N,K]^T + bias[N]
// CTA tile 128x128 (R4 geometry: 8 warps 2x4, warp tile 64x32), BK=32,
// 3-stage cp.async (96 k lookahead), half the barrier rate of BK=16.
// mode=1 -> rna output, Q cols (<1024) x0.125.
// ---------------------------------------------------------------------------
#define BK 32
#define SROW 36                       /* 32 + pad4; bank = 4*lr+lc, conflict-free */
#define TILE_FLOATS (128 * SROW)      /* 4608 */
#define STAGE_FLOATS (2 * TILE_FLOATS)
#define NSTAGE 3
#define GEMM_SMEM (NSTAGE * STAGE_FLOATS * 4)   /* 110592 B */

__global__ __launch_bounds__(256)
void gemm_tf32_kernel(const float* __restrict__ A, const float* __restrict__ Bt,
                      const float* __restrict__ bias, float* __restrict__ C,
                      int M, int N, int K, int mode)
{
    extern __shared__ __align__(16) float sm[];

    const int tid  = threadIdx.x;
    const int wid  = tid >> 5;
    const int lane = tid & 31;
    const int wm   = (wid >> 2) * 64;
    const int wn   = (wid & 3) * 32;
    const int lr   = lane >> 2;
    const int lc   = lane & 3;
    const int n0   = blockIdx.x * 128;
    const int m0   = blockIdx.y * 128;
    const uint32_t smb = smem_u32(sm);

    float c[4][4][4];
    #pragma unroll
    for (int i = 0; i < 4; i++)
        #pragma unroll
        for (int j = 0; j < 4; j++)
            #pragma unroll
            for (int r = 0; r < 4; r++) c[i][j][r] = 0.f;

    auto load_stage = [&](int ch, int s) {
        const float* Ab = A  + (size_t)m0 * K + ch * BK;
        const float* Bb = Bt + (size_t)n0 * K + ch * BK;
        const uint32_t sA = smb + (uint32_t)(s * STAGE_FLOATS) * 4u;
        const uint32_t sB = sA + TILE_FLOATS * 4u;
        #pragma unroll
        for (int i = 0; i < 4; i++) {               // 128 rows x 8 float4 per tile
            const int chk = i * 256 + tid;          // 0..1023
            const int row = chk >> 3, c4 = chk & 7;
            const uint32_t off = (uint32_t)(row * SROW + c4 * 4) * 4u;
            cp_async16(sA + off, Ab + (size_t)row * K + c4 * 4);
            cp_async16(sB + off, Bb + (size_t)row * K + c4 * 4);
        }
    };

    const int NCH = K / BK;

    load_stage(0, 0); cp_commit();
    load_stage(1, 1); cp_commit();

    for (int ch = 0; ch < NCH; ch++) {
        cp_wait<1>();
        __syncthreads();
        if (ch + 2 < NCH) load_stage(ch + 2, (ch + 2) % NSTAGE);
        cp_commit();

        const float* As = sm + (ch % NSTAGE) * STAGE_FLOATS;
        const float* Bs = As + TILE_FLOATS;

        #pragma unroll
        for (int ks = 0; ks < 4; ks++) {
            const int dk = ks * 8;
            uint32_t af[4][4], bf[4][2];
            #pragma unroll
            for (int mt = 0; mt < 4; mt++) {
                const float* ap = As + (wm + mt * 16 + lr) * SROW + dk + lc;
                af[mt][0] = __float_as_uint(ap[0]);
                af[mt][1] = __float_as_uint(ap[8 * SROW]);
                af[mt][2] = __float_as_uint(ap[4]);
                af[mt][3] = __float_as_uint(ap[8 * SROW + 4]);
            }
            #pragma unroll
            for (int nt = 0; nt < 4; nt++) {
                const float* bp = Bs + (wn + nt * 8 + lr) * SROW + dk + lc;
                bf[nt][0] = __float_as_uint(bp[0]);
                bf[nt][1] = __float_as_uint(bp[4]);
            }
            #pragma unroll
            for (int mt = 0; mt < 4; mt++)
                #pragma unroll
                for (int nt = 0; nt < 4; nt++)
                    mma_tf32(c[mt][nt][0], c[mt][nt][1], c[mt][nt][2], c[mt][nt][3],
                             af[mt][0], af[mt][1], af[mt][2], af[mt][3],
                             bf[nt][0], bf[nt][1]);
        }
        __syncthreads();
    }

    #pragma unroll
    for (int nt = 0; nt < 4; nt++) {
        const int col = n0 + wn + nt * 8 + 2 * lc;
        const float b0 = bias[col], b1 = bias[col + 1];
        const float sc = (mode && col < 1024) ? 0.125f : 1.0f;
        #pragma unroll
        for (int mt = 0; mt < 4; mt++) {
            const size_t r0 = (size_t)(m0 + wm + mt * 16 + lr);
            float v0 = (c[mt][nt][0] + b0) * sc;
            float v1 = (c[mt][nt][1] + b1) * sc;
            float v2 = (c[mt][nt][2] + b0) * sc;
            float v3 = (c[mt][nt][3] + b1) * sc;
            if (mode) {
                v0 = rna_tf32(v0); v1 = rna_tf32(v1);
                v2 = rna_tf32(v2); v3 = rna_tf32(v3);
            }
            *(float2*)(&C[r0 * N + col])       = make_float2(v0, v1);
            *(float2*)(&C[(r0 + 8) * N + col]) = make_float2(v2, v3);
        }
    }
}

// ---------------------------------------------------------------------------
// Flash attention with tf32 mma.sync (unchanged from R4 — near its MMA floor).
// ---------------------------------------------------------------------------
#define QS_OFF 0                 /* Q  [128][68]  */
#define PS_OFF 8704              /* P  [128][132] */
#define KS_OFF 25600             /* K  [128][68]  */
#define VR_OFF 34304             /* V  [128][68]  */
#define VT_OFF 43008             /* Vt [64][132]  */
#define ATT_SMEM ((43008 + 64 * 132) * 4)   /* 205824 B */

__global__ __launch_bounds__(256, 1)
void attn_mma_kernel(const float* __restrict__ qkv, float* __restrict__ out)
{
    extern __shared__ __align__(16) float sa[];

    const int tid  = threadIdx.x;
    const int wid  = tid >> 5;
    const int lane = tid & 31;
    const int lr   = lane >> 2;
    const int lc   = lane & 3;
    const int wm   = wid * 16;
    const int qt   = blockIdx.x;
    const int h    = blockIdx.y;
    const int b    = blockIdx.z;
    const int q0   = qt * 128;
    const float slope = fexp2(-0.5f * (float)(h + 1));
    const uint32_t smb = smem_u32(sa);

    const float* baseQ = qkv + (size_t)b * SEQ * 3072 + h * 64;
    const float* baseK = baseQ + 1024;
    const float* baseV = baseQ + 2048;

    auto load_tile = [&](const float* g, int row0, int soff) {
        #pragma unroll
        for (int i = 0; i < 8; i++) {
            const int chk = i * 256 + tid;          // 0..2047
            const int row = chk >> 4, c4 = chk & 15;
            cp_async16(smb + (uint32_t)(soff + row * 68 + c4 * 4) * 4u,
                       g + (size_t)(row0 + row) * 3072 + c4 * 4);
        }
    };

    load_tile(baseQ, q0, QS_OFF); cp_commit();
    load_tile(baseK, 0,  KS_OFF); cp_commit();
    load_tile(baseV, 0,  VR_OFF); cp_commit();

    float m0 = -1e30f, m1 = -1e30f, l0 = 0.f, l1 = 0.f;
    float o[8][4];
    #pragma unroll
    for (int i = 0; i < 8; i++)
        #pragma unroll
        for (int r = 0; r < 4; r++) o[i][r] = 0.f;

    const int qrow0 = q0 + wm + lr;
    const int qrow1 = qrow0 + 8;

    for (int kt = 0; kt <= qt; kt++) {
        cp_wait<1>();          // K(kt) (and Q) resident; V(kt) may still fly
        __syncthreads();

        // ---- S = Q @ K^T ----
        float c[16][4];
        #pragma unroll
        for (int nt = 0; nt < 16; nt++)
            #pragma unroll
            for (int r = 0; r < 4; r++) c[nt][r] = 0.f;

        #pragma unroll
        for (int dk = 0; dk < 8; dk++) {
            const float* ap = sa + QS_OFF + (wm + lr) * 68 + dk * 8 + lc;
            const uint32_t a0 = __float_as_uint(ap[0]);
            const uint32_t a1 = __float_as_uint(ap[8 * 68]);
            const uint32_t a2 = __float_as_uint(ap[4]);
            const uint32_t a3 = __float_as_uint(ap[8 * 68 + 4]);
            #pragma unroll
            for (int nt = 0; nt < 16; nt++) {
                const float* bp = sa + KS_OFF + (nt * 8 + lr) * 68 + dk * 8 + lc;
                mma_tf32(c[nt][0], c[nt][1], c[nt][2], c[nt][3],
                         a0, a1, a2, a3,
                         __float_as_uint(bp[0]), __float_as_uint(bp[4]));
            }
        }
        __syncthreads();       // done reading Ks
        if (kt < qt) load_tile(baseK, (kt + 1) * 128, KS_OFF);
        cp_commit();

        // ---- ALiBi + (diagonal-only) mask + online softmax ----
        const int kb = kt * 128 + 2 * lc;
        {
            float al0 = slope * (float)(kb - qrow0);
            float al1 = slope * (float)(kb - qrow1);
            const float st8 = 8.f * slope;
            float mx0 = -1e30f, mx1 = -1e30f;
            #pragma unroll
            for (int nt = 0; nt < 16; nt++) {
                float s0 = c[nt][0] + al0;
                float s1 = c[nt][1] + al0 + slope;
                float s2 = c[nt][2] + al1;
                float s3 = c[nt][3] + al1 + slope;
                if (kt == qt) {       // masking only possible on the diagonal tile
                    const int k0c = kb + nt * 8, k1c = k0c + 1;
                    if (k0c > qrow0) s0 = -1e30f;
                    if (k1c > qrow0) s1 = -1e30f;
                    if (k0c > qrow1) s2 = -1e30f;
                    if (k1c > qrow1) s3 = -1e30f;
                }
                c[nt][0] = s0; c[nt][1] = s1; c[nt][2] = s2; c[nt][3] = s3;
                mx0 = fmaxf(mx0, fmaxf(s0, s1));
                mx1 = fmaxf(mx1, fmaxf(s2, s3));
                al0 += st8; al1 += st8;
            }
            mx0 = fmaxf(mx0, __shfl_xor_sync(0xffffffffu, mx0, 1));
            mx0 = fmaxf(mx0, __shfl_xor_sync(0xffffffffu, mx0, 2));
            mx1 = fmaxf(mx1, __shfl_xor_sync(0xffffffffu, mx1, 1));
            mx1 = fmaxf(mx1, __shfl_xor_sync(0xffffffffu, mx1, 2));

            const float mn0 = fmaxf(m0, mx0), mn1 = fmaxf(m1, mx1);
            const float corr0 = fexp2((m0 - mn0) * L2E);
            const float corr1 = fexp2((m1 - mn1) * L2E);
            m0 = mn0; m1 = mn1;

            float ts0 = 0.f, ts1 = 0.f;
            float* p0 = sa + PS_OFF + (wm + lr) * 132 + 2 * lc;
            float* p1 = p0 + 8 * 132;
            #pragma unroll
            for (int nt = 0; nt < 16; nt++) {
                const float e0 = rna_tf32(fexp2((c[nt][0] - mn0) * L2E));
                const float e1 = rna_tf32(fexp2((c[nt][1] - mn0) * L2E));
                const float e2 = rna_tf32(fexp2((c[nt][2] - mn1) * L2E));
                const float e3 = rna_tf32(fexp2((c[nt][3] - mn1) * L2E));
                ts0 += e0 + e1;
                ts1 += e2 + e3;
                *(float2*)(p0 + nt * 8) = make_float2(e0, e1);
                *(float2*)(p1 + nt * 8) = make_float2(e2, e3);
            }
            ts0 += __shfl_xor_sync(0xffffffffu, ts0, 1);
            ts0 += __shfl_xor_sync(0xffffffffu, ts0, 2);
            ts1 += __shfl_xor_sync(0xffffffffu, ts1, 1);
            ts1 += __shfl_xor_sync(0xffffffffu, ts1, 2);
            l0 = l0 * corr0 + ts0;
            l1 = l1 * corr1 + ts1;
            #pragma unroll
            for (int i = 0; i < 8; i++) {
                o[i][0] *= corr0; o[i][1] *= corr0;
                o[i][2] *= corr1; o[i][3] *= corr1;
            }
        }

        cp_wait<1>();          // V(kt) resident; K(kt+1) may still fly
        __syncthreads();

        // ---- transpose V [128][64] -> Vt [64][128] ----
        {
            const int kvr = tid & 127;
            const int dc  = (tid >> 7) * 32;
            #pragma unroll
            for (int j = 0; j < 32; j += 4) {
                float4 v = *(const float4*)(sa + VR_OFF + kvr * 68 + dc + j);
                sa[VT_OFF + (dc + j + 0) * 132 + kvr] = v.x;
                sa[VT_OFF + (dc + j + 1) * 132 + kvr] = v.y;
                sa[VT_OFF + (dc + j + 2) * 132 + kvr] = v.z;
                sa[VT_OFF + (dc + j + 3) * 132 + kvr] = v.w;
            }
        }
        __syncthreads();

        // ---- O += P @ V ----
        #pragma unroll
        for (int dk = 0; dk < 16; dk++) {
            const float* pp = sa + PS_OFF + (wm + lr) * 132 + dk * 8 + lc;
            const uint32_t a0 = __float_as_uint(pp[0]);
            const uint32_t a1 = __float_as_uint(pp[8 * 132]);
            const uint32_t a2 = __float_as_uint(pp[4]);
            const uint32_t a3 = __float_as_uint(pp[8 * 132 + 4]);
            #pragma unroll
            for (int nt2 = 0; nt2 < 8; nt2++) {
                const float* bp = sa + VT_OFF + (nt2 * 8 + lr) * 132 + dk * 8 + lc;
                mma_tf32(o[nt2][0], o[nt2][1], o[nt2][2], o[nt2][3],
                         a0, a1, a2, a3,
                         __float_as_uint(bp[0]), __float_as_uint(bp[4]));
            }
        }
        __syncthreads();       // all warps done with Vt (and Vrm consumed)
        if (kt < qt) load_tile(baseV, (kt + 1) * 128, VR_OFF);
        cp_commit();
    }

    // ---- epilogue: normalize, rna (feeds tf32 out-projection) ----
    const float inv0 = 1.f / l0, inv1 = 1.f / l1;
    float* og = out + ((size_t)b * SEQ + qrow0) * EMB + h * HDIM + 2 * lc;
    #pragma unroll
    for (int nt2 = 0; nt2 < 8; nt2++) {
        *(float2*)(og + nt2 * 8) =
            make_float2(rna_tf32(o[nt2][0] * inv0), rna_tf32(o[nt2][1] * inv0));
        *(float2*)(og + 8 * EMB + nt2 * 8) =
            make_float2(rna_tf32(o[nt2][2] * inv1), rna_tf32(o[nt2][3] * inv1));
    }
}

// ---------------------------------------------------------------------------
extern "C" void kernel_launch(void* const* d_in, const int* in_sizes, int n_in,
                              void* d_out, int out_size)
{
    const float* x    = (const float*)d_in[0];
    // d_in[1] = mask (bool tril) — causality handled analytically
    const float* Wqkv = (const float*)d_in[2];
    const float* bqkv = (const float*)d_in[3];
    const float* Wout = (const float*)d_in[4];
    const float* bout = (const float*)d_in[5];
    float* out = (float*)d_out;

    float *qkv_p, *att_p, *xc_p, *wqt_p, *wot_p;
    cudaGetSymbolAddress((void**)&qkv_p, g_qkv);
    cudaGetSymbolAddress((void**)&att_p, g_att);
    cudaGetSymbolAddress((void**)&xc_p,  g_xc);
    cudaGetSymbolAddress((void**)&wqt_p, g_wqt);
    cudaGetSymbolAddress((void**)&wot_p, g_wot);

    cudaFuncSetAttribute(gemm_tf32_kernel,
                         cudaFuncAttributeMaxDynamicSharedMemorySize, GEMM_SMEM);
    cudaFuncSetAttribute(attn_mma_kernel,
                         cudaFuncAttributeMaxDynamicSharedMemorySize, ATT_SMEM);

    // 0) tf32-round operands
    {
        const int n4 = MROWS * EMB / 4;
        convert_rna_kernel<<<(n4 + 255) / 256, 256>>>(x, xc_p, n4);
    }
    transpose_rna_kernel<<<dim3(3 * EMB / 32, EMB / 32), dim3(32, 8)>>>(Wqkv, wqt_p, EMB, 3 * EMB);
    transpose_rna_kernel<<<dim3(EMB / 32, EMB / 32),     dim3(32, 8)>>>(Wout, wot_p, EMB, EMB);

    // 1) qkv = x @ W_qkv + b_qkv; epilogue rna + Q*0.125 (mode=1)
    gemm_tf32_kernel<<<dim3(3 * EMB / 128, MROWS / 128), 256, GEMM_SMEM>>>(
        xc_p, wqt_p, bqkv, qkv_p, MROWS, 3 * EMB, EMB, 1);

    // 2) attention (tf32 mma.sync, causal + ALiBi fused)
    attn_mma_kernel<<<dim3(SEQ / 128, HEADS, BATCH), 256, ATT_SMEM>>>(qkv_p, att_p);

    // 3) out = att @ W_out + b_out (mode=0: plain fp32 output)
    gemm_tf32_kernel<<<dim3(EMB / 128, MROWS / 128), 256, GEMM_SMEM>>>(
        att_p, wot_p, bout, out, MROWS, EMB, EMB, 0);
}

// round 7
// speedup vs baseline: 1.0793x; 1.0281x over previous
#include <cuda_runtime.h>
#include <cstdint>
#include <math.h>

#define BATCH 4
#define SEQ   2048
#define EMB   1024
#define HEADS 16
#define HDIM  64
#define MROWS (BATCH*SEQ)   /* 8192 */
#define L2E   1.4426950408889634f

// K-dim permutation within 8-groups: pos(j) = j<4 ? 2j : 2(j-4)+1
// (fragment pair (lc, lc+4) becomes adjacent -> one 64-bit LDS)

// Scratch (device globals: allocation-free per harness rules)
__device__ float g_qkv[(size_t)MROWS * 3 * EMB];   // [8192, 3072] rna(tf32), Q pre-scaled (natural)
__device__ float g_att[(size_t)MROWS * EMB];       // [8192, 1024] rna(tf32), K-permuted
__device__ float g_xc [(size_t)MROWS * EMB];       // x, rna(tf32), K-permuted
__device__ float g_wqt[(size_t)3 * EMB * EMB];     // W_qkv^T, rna, K-permuted
__device__ float g_wot[(size_t)EMB * EMB];         // W_out^T, rna, K-permuted

// ---------------------------------------------------------------------------
// helpers (portable PTX only)
// ---------------------------------------------------------------------------
__device__ __forceinline__ uint32_t smem_u32(const void* p) {
    uint32_t a;
    asm("{ .reg .u64 t; cvta.to.shared.u64 t, %1; cvt.u32.u64 %0, t; }" : "=r"(a) : "l"(p));
    return a;
}
__device__ __forceinline__ float rna_tf32(float v) {
    uint32_t u;
    asm("cvt.rna.tf32.f32 %0, %1;" : "=r"(u) : "f"(v));
    return __uint_as_float(u);
}
__device__ __forceinline__ float fexp2(float x) {
    float y;
    asm("ex2.approx.f32 %0, %1;" : "=f"(y) : "f"(x));
    return y;
}
__device__ __forceinline__ void cp_async16(uint32_t dst, const void* src) {
    asm volatile("cp.async.cg.shared.global [%0], [%1], 16;" :: "r"(dst), "l"(src));
}
__device__ __forceinline__ void cp_commit() {
    asm volatile("cp.async.commit_group;" ::: "memory");
}
template <int N>
__device__ __forceinline__ void cp_wait() {
    asm volatile("cp.async.wait_group %0;" :: "n"(N) : "memory");
}
__device__ __forceinline__ void mma_tf32(float& c0, float& c1, float& c2, float& c3,
                                         uint32_t a0, uint32_t a1, uint32_t a2, uint32_t a3,
                                         uint32_t b0, uint32_t b1) {
    asm volatile(
        "mma.sync.aligned.m16n8k8.row.col.f32.tf32.tf32.f32 "
        "{%0,%1,%2,%3}, {%4,%5,%6,%7}, {%8,%9}, {%0,%1,%2,%3};"
        : "+f"(c0), "+f"(c1), "+f"(c2), "+f"(c3)
        : "r"(a0), "r"(a1), "r"(a2), "r"(a3), "r"(b0), "r"(b1));
}

// ---------------------------------------------------------------------------
// rna(tf32) + K-permute: dst[row, 8g + pos(j)] = rna(src[row, 8g + j])
// Each thread handles a float4 = half an 8-group (j = 0..3 or 4..7).
// ---------------------------------------------------------------------------
__global__ void convert_rna_perm_kernel(const float* __restrict__ src,
                                        float* __restrict__ dst, int n4) {
    int i = blockIdx.x * blockDim.x + threadIdx.x;
    if (i < n4) {
        float4 v = ((const float4*)src)[i];
        const int i4 = i * 4;
        const int base = (i4 & ~7) | ((i4 & 4) ? 1 : 0);   // 8g (+1 if j>=4)
        dst[base + 0] = rna_tf32(v.x);
        dst[base + 2] = rna_tf32(v.y);
        dst[base + 4] = rna_tf32(v.z);
        dst[base + 6] = rna_tf32(v.w);
    }
}

// ---------------------------------------------------------------------------
// transpose + rna + K-permute: Wt[n][k0 + perm(x)] = rna(W[k0+x][n])
// ---------------------------------------------------------------------------
__global__ void transpose_rna_perm_kernel(const float* __restrict__ W,
                                          float* __restrict__ Wt, int K, int N) {
    __shared__ float t[32][33];
    const int n0 = blockIdx.x * 32, k0 = blockIdx.y * 32;
    const int x = threadIdx.x, y = threadIdx.y;  // 32 x 8
    #pragma unroll
    for (int i = 0; i < 4; i++)
        t[y + i * 8][x] = W[(size_t)(k0 + y + i * 8) * N + n0 + x];
    __syncthreads();
    const int j  = x & 7;
    const int px = (x & ~7) | ((j < 4) ? (2 * j) : (2 * (j - 4) + 1));
    #pragma unroll
    for (int i = 0; i < 4; i++)
        Wt[(size_t)(n0 + y + i * 8) * K + k0 + px] = rna_tf32(t[x][y + i * 8]);
}

// ---------------------------------------------------------------------------
// tf32 mma.sync GEMM: C[M,N] = A[M,K] @ Bt[N,K]^T + bias[N]
// A, Bt K-PERMUTED row-major. 128x128 CTA, 8 warps (2x4), warp 64x32, BK=32.
// Fragment loads are 64-bit (pair lc/lc+4 adjacent): 12 LDS vs 16 MMA / k-step.
// mode=1 -> rna output, Q cols (<1024) x0.125 (output stays NATURAL order).
// ---------------------------------------------------------------------------
#define BK 32
#define SROW 40                       /* pad8: LDS.64 conflict-free per 16-lane phase */
#define TILE_FLOATS (128 * SROW)      /* 5120 */
#define STAGE_FLOATS (2 * TILE_FLOATS)
#define NSTAGE 3
#define GEMM_SMEM (NSTAGE * STAGE_FLOATS * 4)   /* 122880 B */

__global__ __launch_bounds__(256)
void gemm_tf32_kernel(const float* __restrict__ A, const float* __restrict__ Bt,
                      const float* __restrict__ bias, float* __restrict__ C,
                      int M, int N, int K, int mode)
{
    extern __shared__ __align__(16) float sm[];

    const int tid  = threadIdx.x;
    const int wid  = tid >> 5;
    const int lane = tid & 31;
    const int wm   = (wid >> 2) * 64;
    const int wn   = (wid & 3) * 32;
    const int lr   = lane >> 2;
    const int lc   = lane & 3;
    const int n0   = blockIdx.x * 128;
    const int m0   = blockIdx.y * 128;
    const uint32_t smb = smem_u32(sm);

    float c[4][4][4];
    #pragma unroll
    for (int i = 0; i < 4; i++)
        #pragma unroll
        for (int j = 0; j < 4; j++)
            #pragma unroll
            for (int r = 0; r < 4; r++) c[i][j][r] = 0.f;

    auto load_stage = [&](int ch, int s) {
        const float* Ab = A  + (size_t)m0 * K + ch * BK;
        const float* Bb = Bt + (size_t)n0 * K + ch * BK;
        const uint32_t sA = smb + (uint32_t)(s * STAGE_FLOATS) * 4u;
        const uint32_t sB = sA + TILE_FLOATS * 4u;
        #pragma unroll
        for (int i = 0; i < 4; i++) {               // 128 rows x 8 float4 per tile
            const int chk = i * 256 + tid;          // 0..1023
            const int row = chk >> 3, c4 = chk & 7;
            const uint32_t off = (uint32_t)(row * SROW + c4 * 4) * 4u;
            cp_async16(sA + off, Ab + (size_t)row * K + c4 * 4);
            cp_async16(sB + off, Bb + (size_t)row * K + c4 * 4);
        }
    };

    const int NCH = K / BK;

    load_stage(0, 0); cp_commit();
    load_stage(1, 1); cp_commit();

    for (int ch = 0; ch < NCH; ch++) {
        cp_wait<1>();
        __syncthreads();
        if (ch + 2 < NCH) load_stage(ch + 2, (ch + 2) % NSTAGE);
        cp_commit();

        const float* As = sm + (ch % NSTAGE) * STAGE_FLOATS;
        const float* Bs = As + TILE_FLOATS;

        #pragma unroll
        for (int ks = 0; ks < 4; ks++) {
            const int dk = ks * 8 + 2 * lc;        // permuted: (lc, lc+4) adjacent
            uint32_t af[4][4], bf[4][2];
            #pragma unroll
            for (int mt = 0; mt < 4; mt++) {
                const float2 a02 = *(const float2*)(As + (wm + mt * 16 + lr) * SROW + dk);
                const float2 a13 = *(const float2*)(As + (wm + mt * 16 + lr + 8) * SROW + dk);
                af[mt][0] = __float_as_uint(a02.x);
                af[mt][1] = __float_as_uint(a13.x);
                af[mt][2] = __float_as_uint(a02.y);
                af[mt][3] = __float_as_uint(a13.y);
            }
            #pragma unroll
            for (int nt = 0; nt < 4; nt++) {
                const float2 b01 = *(const float2*)(Bs + (wn + nt * 8 + lr) * SROW + dk);
                bf[nt][0] = __float_as_uint(b01.x);
                bf[nt][1] = __float_as_uint(b01.y);
            }
            #pragma unroll
            for (int mt = 0; mt < 4; mt++)
                #pragma unroll
                for (int nt = 0; nt < 4; nt++)
                    mma_tf32(c[mt][nt][0], c[mt][nt][1], c[mt][nt][2], c[mt][nt][3],
                             af[mt][0], af[mt][1], af[mt][2], af[mt][3],
                             bf[nt][0], bf[nt][1]);
        }
        __syncthreads();
    }

    #pragma unroll
    for (int nt = 0; nt < 4; nt++) {
        const int col = n0 + wn + nt * 8 + 2 * lc;
        const float b0 = bias[col], b1 = bias[col + 1];
        const float sc = (mode && col < 1024) ? 0.125f : 1.0f;
        #pragma unroll
        for (int mt = 0; mt < 4; mt++) {
            const size_t r0 = (size_t)(m0 + wm + mt * 16 + lr);
            float v0 = (c[mt][nt][0] + b0) * sc;
            float v1 = (c[mt][nt][1] + b1) * sc;
            float v2 = (c[mt][nt][2] + b0) * sc;
            float v3 = (c[mt][nt][3] + b1) * sc;
            if (mode) {
                v0 = rna_tf32(v0); v1 = rna_tf32(v1);
                v2 = rna_tf32(v2); v3 = rna_tf32(v3);
            }
            *(float2*)(&C[r0 * N + col])       = make_float2(v0, v1);
            *(float2*)(&C[(r0 + 8) * N + col]) = make_float2(v2, v3);
        }
    }
}

// ---------------------------------------------------------------------------
// Flash attention with tf32 mma.sync (logic unchanged from R4).
// Epilogue now writes g_att K-PERMUTED (feeds the permuted GEMM2).
// ---------------------------------------------------------------------------
#define QS_OFF 0                 /* Q  [128][68]  */
#define PS_OFF 8704              /* P  [128][132] */
#define KS_OFF 25600             /* K  [128][68]  */
#define VR_OFF 34304             /* V  [128][68]  */
#define VT_OFF 43008             /* Vt [64][132]  */
#define ATT_SMEM ((43008 + 64 * 132) * 4)   /* 205824 B */

__global__ __launch_bounds__(256, 1)
void attn_mma_kernel(const float* __restrict__ qkv, float* __restrict__ out)
{
    extern __shared__ __align__(16) float sa[];

    const int tid  = threadIdx.x;
    const int wid  = tid >> 5;
    const int lane = tid & 31;
    const int lr   = lane >> 2;
    const int lc   = lane & 3;
    const int wm   = wid * 16;
    const int qt   = blockIdx.x;
    const int h    = blockIdx.y;
    const int b    = blockIdx.z;
    const int q0   = qt * 128;
    const float slope = fexp2(-0.5f * (float)(h + 1));
    const uint32_t smb = smem_u32(sa);

    const float* baseQ = qkv + (size_t)b * SEQ * 3072 + h * 64;
    const float* baseK = baseQ + 1024;
    const float* baseV = baseQ + 2048;

    auto load_tile = [&](const float* g, int row0, int soff) {
        #pragma unroll
        for (int i = 0; i < 8; i++) {
            const int chk = i * 256 + tid;          // 0..2047
            const int row = chk >> 4, c4 = chk & 15;
            cp_async16(smb + (uint32_t)(soff + row * 68 + c4 * 4) * 4u,
                       g + (size_t)(row0 + row) * 3072 + c4 * 4);
        }
    };

    load_tile(baseQ, q0, QS_OFF); cp_commit();
    load_tile(baseK, 0,  KS_OFF); cp_commit();
    load_tile(baseV, 0,  VR_OFF); cp_commit();

    float m0 = -1e30f, m1 = -1e30f, l0 = 0.f, l1 = 0.f;
    float o[8][4];
    #pragma unroll
    for (int i = 0; i < 8; i++)
        #pragma unroll
        for (int r = 0; r < 4; r++) o[i][r] = 0.f;

    const int qrow0 = q0 + wm + lr;
    const int qrow1 = qrow0 + 8;

    for (int kt = 0; kt <= qt; kt++) {
        cp_wait<1>();          // K(kt) (and Q) resident; V(kt) may still fly
        __syncthreads();

        // ---- S = Q @ K^T ----
        float c[16][4];
        #pragma unroll
        for (int nt = 0; nt < 16; nt++)
            #pragma unroll
            for (int r = 0; r < 4; r++) c[nt][r] = 0.f;

        #pragma unroll
        for (int dk = 0; dk < 8; dk++) {
            const float* ap = sa + QS_OFF + (wm + lr) * 68 + dk * 8 + lc;
            const uint32_t a0 = __float_as_uint(ap[0]);
            const uint32_t a1 = __float_as_uint(ap[8 * 68]);
            const uint32_t a2 = __float_as_uint(ap[4]);
            const uint32_t a3 = __float_as_uint(ap[8 * 68 + 4]);
            #pragma unroll
            for (int nt = 0; nt < 16; nt++) {
                const float* bp = sa + KS_OFF + (nt * 8 + lr) * 68 + dk * 8 + lc;
                mma_tf32(c[nt][0], c[nt][1], c[nt][2], c[nt][3],
                         a0, a1, a2, a3,
                         __float_as_uint(bp[0]), __float_as_uint(bp[4]));
            }
        }
        __syncthreads();       // done reading Ks
        if (kt < qt) load_tile(baseK, (kt + 1) * 128, KS_OFF);
        cp_commit();

        // ---- ALiBi + (diagonal-only) mask + online softmax ----
        const int kb = kt * 128 + 2 * lc;
        {
            float al0 = slope * (float)(kb - qrow0);
            float al1 = slope * (float)(kb - qrow1);
            const float st8 = 8.f * slope;
            float mx0 = -1e30f, mx1 = -1e30f;
            #pragma unroll
            for (int nt = 0; nt < 16; nt++) {
                float s0 = c[nt][0] + al0;
                float s1 = c[nt][1] + al0 + slope;
                float s2 = c[nt][2] + al1;
                float s3 = c[nt][3] + al1 + slope;
                if (kt == qt) {       // masking only possible on the diagonal tile
                    const int k0c = kb + nt * 8, k1c = k0c + 1;
                    if (k0c > qrow0) s0 = -1e30f;
                    if (k1c > qrow0) s1 = -1e30f;
                    if (k0c > qrow1) s2 = -1e30f;
                    if (k1c > qrow1) s3 = -1e30f;
                }
                c[nt][0] = s0; c[nt][1] = s1; c[nt][2] = s2; c[nt][3] = s3;
                mx0 = fmaxf(mx0, fmaxf(s0, s1));
                mx1 = fmaxf(mx1, fmaxf(s2, s3));
                al0 += st8; al1 += st8;
            }
            mx0 = fmaxf(mx0, __shfl_xor_sync(0xffffffffu, mx0, 1));
            mx0 = fmaxf(mx0, __shfl_xor_sync(0xffffffffu, mx0, 2));
            mx1 = fmaxf(mx1, __shfl_xor_sync(0xffffffffu, mx1, 1));
            mx1 = fmaxf(mx1, __shfl_xor_sync(0xffffffffu, mx1, 2));

            const float mn0 = fmaxf(m0, mx0), mn1 = fmaxf(m1, mx1);
            const float corr0 = fexp2((m0 - mn0) * L2E);
            const float corr1 = fexp2((m1 - mn1) * L2E);
            m0 = mn0; m1 = mn1;

            float ts0 = 0.f, ts1 = 0.f;
            float* p0 = sa + PS_OFF + (wm + lr) * 132 + 2 * lc;
            float* p1 = p0 + 8 * 132;
            #pragma unroll
            for (int nt = 0; nt < 16; nt++) {
                const float e0 = rna_tf32(fexp2((c[nt][0] - mn0) * L2E));
                const float e1 = rna_tf32(fexp2((c[nt][1] - mn0) * L2E));
                const float e2 = rna_tf32(fexp2((c[nt][2] - mn1) * L2E));
                const float e3 = rna_tf32(fexp2((c[nt][3] - mn1) * L2E));
                ts0 += e0 + e1;
                ts1 += e2 + e3;
                *(float2*)(p0 + nt * 8) = make_float2(e0, e1);
                *(float2*)(p1 + nt * 8) = make_float2(e2, e3);
            }
            ts0 += __shfl_xor_sync(0xffffffffu, ts0, 1);
            ts0 += __shfl_xor_sync(0xffffffffu, ts0, 2);
            ts1 += __shfl_xor_sync(0xffffffffu, ts1, 1);
            ts1 += __shfl_xor_sync(0xffffffffu, ts1, 2);
            l0 = l0 * corr0 + ts0;
            l1 = l1 * corr1 + ts1;
            #pragma unroll
            for (int i = 0; i < 8; i++) {
                o[i][0] *= corr0; o[i][1] *= corr0;
                o[i][2] *= corr1; o[i][3] *= corr1;
            }
        }

        cp_wait<1>();          // V(kt) resident; K(kt+1) may still fly
        __syncthreads();

        // ---- transpose V [128][64] -> Vt [64][128] ----
        {
            const int kvr = tid & 127;
            const int dc  = (tid >> 7) * 32;
            #pragma unroll
            for (int j = 0; j < 32; j += 4) {
                float4 v = *(const float4*)(sa + VR_OFF + kvr * 68 + dc + j);
                sa[VT_OFF + (dc + j + 0) * 132 + kvr] = v.x;
                sa[VT_OFF + (dc + j + 1) * 132 + kvr] = v.y;
                sa[VT_OFF + (dc + j + 2) * 132 + kvr] = v.z;
                sa[VT_OFF + (dc + j + 3) * 132 + kvr] = v.w;
            }
        }
        __syncthreads();

        // ---- O += P @ V ----
        #pragma unroll
        for (int dk = 0; dk < 16; dk++) {
            const float* pp = sa + PS_OFF + (wm + lr) * 132 + dk * 8 + lc;
            const uint32_t a0 = __float_as_uint(pp[0]);
            const uint32_t a1 = __float_as_uint(pp[8 * 132]);
            const uint32_t a2 = __float_as_uint(pp[4]);
            const uint32_t a3 = __float_as_uint(pp[8 * 132 + 4]);
            #pragma unroll
            for (int nt2 = 0; nt2 < 8; nt2++) {
                const float* bp = sa + VT_OFF + (nt2 * 8 + lr) * 132 + dk * 8 + lc;
                mma_tf32(o[nt2][0], o[nt2][1], o[nt2][2], o[nt2][3],
                         a0, a1, a2, a3,
                         __float_as_uint(bp[0]), __float_as_uint(bp[4]));
            }
        }
        __syncthreads();       // all warps done with Vt (and Vrm consumed)
        if (kt < qt) load_tile(baseV, (kt + 1) * 128, VR_OFF);
        cp_commit();
    }

    // ---- epilogue: normalize, rna, write K-PERMUTED (feeds permuted GEMM2) ----
    // d-in-group j = 2*lc -> perm pos p0 = (lc<2) ? 4*lc : 4*lc-7; j+1 -> p0+2.
    const float inv0 = 1.f / l0, inv1 = 1.f / l1;
    const int p0 = (lc < 2) ? (4 * lc) : (4 * lc - 7);
    float* og = out + ((size_t)b * SEQ + qrow0) * EMB + h * HDIM;
    #pragma unroll
    for (int nt2 = 0; nt2 < 8; nt2++) {
        og[nt2 * 8 + p0]         = rna_tf32(o[nt2][0] * inv0);
        og[nt2 * 8 + p0 + 2]     = rna_tf32(o[nt2][1] * inv0);
        og[8 * EMB + nt2 * 8 + p0]     = rna_tf32(o[nt2][2] * inv1);
        og[8 * EMB + nt2 * 8 + p0 + 2] = rna_tf32(o[nt2][3] * inv1);
    }
}

// ---------------------------------------------------------------------------
extern "C" void kernel_launch(void* const* d_in, const int* in_sizes, int n_in,
                              void* d_out, int out_size)
{
    const float* x    = (const float*)d_in[0];
    // d_in[1] = mask (bool tril) — causality handled analytically
    const float* Wqkv = (const float*)d_in[2];
    const float* bqkv = (const float*)d_in[3];
    const float* Wout = (const float*)d_in[4];
    const float* bout = (const float*)d_in[5];
    float* out = (float*)d_out;

    float *qkv_p, *att_p, *xc_p, *wqt_p, *wot_p;
    cudaGetSymbolAddress((void**)&qkv_p, g_qkv);
    cudaGetSymbolAddress((void**)&att_p, g_att);
    cudaGetSymbolAddress((void**)&xc_p,  g_xc);
    cudaGetSymbolAddress((void**)&wqt_p, g_wqt);
    cudaGetSymbolAddress((void**)&wot_p, g_wot);

    cudaFuncSetAttribute(gemm_tf32_kernel,
                         cudaFuncAttributeMaxDynamicSharedMemorySize, GEMM_SMEM);
    cudaFuncSetAttribute(attn_mma_kernel,
                         cudaFuncAttributeMaxDynamicSharedMemorySize, ATT_SMEM);

    // 0) tf32-round operands (K-permuted layouts for the GEMMs)
    {
        const int n4 = MROWS * EMB / 4;
        convert_rna_perm_kernel<<<(n4 + 255) / 256, 256>>>(x, xc_p, n4);
    }
    transpose_rna_perm_kernel<<<dim3(3 * EMB / 32, EMB / 32), dim3(32, 8)>>>(Wqkv, wqt_p, EMB, 3 * EMB);
    transpose_rna_perm_kernel<<<dim3(EMB / 32, EMB / 32),     dim3(32, 8)>>>(Wout, wot_p, EMB, EMB);

    // 1) qkv = x @ W_qkv + b_qkv; epilogue rna + Q*0.125 (mode=1), natural output
    gemm_tf32_kernel<<<dim3(3 * EMB / 128, MROWS / 128), 256, GEMM_SMEM>>>(
        xc_p, wqt_p, bqkv, qkv_p, MROWS, 3 * EMB, EMB, 1);

    // 2) attention (tf32 mma.sync); epilogue writes K-permuted g_att
    attn_mma_kernel<<<dim3(SEQ / 128, HEADS, BATCH), 256, ATT_SMEM>>>(qkv_p, att_p);

    // 3) out = att @ W_out + b_out (mode=0: plain fp32, natural output)
    gemm_tf32_kernel<<<dim3(EMB / 128, MROWS / 128), 256, GEMM_SMEM>>>(
        att_p, wot_p, bout, out, MROWS, EMB, EMB, 0);
}

// round 8
// speedup vs baseline: 1.0798x; 1.0005x over previous
#include <cuda_runtime.h>
#include <cstdint>
#include <math.h>

#define BATCH 4
#define SEQ   2048
#define EMB   1024
#define HEADS 16
#define HDIM  64
#define MROWS (BATCH*SEQ)   /* 8192 */
#define L2E   1.4426950408889634f

// K-dim permutation within 8-groups: pos(j) = j<4 ? 2j : 2(j-4)+1
// (fragment pair (lc, lc+4) becomes adjacent -> one 64-bit LDS)

// Scratch (device globals: allocation-free per harness rules)
__device__ float g_qkv[(size_t)MROWS * 3 * EMB];   // [8192, 3072] rna(tf32), Q pre-scaled (natural)
__device__ float g_att[(size_t)MROWS * EMB];       // [8192, 1024] rna(tf32), K-permuted
__device__ float g_xc [(size_t)MROWS * EMB];       // x, rna(tf32), K-permuted
__device__ float g_wqt[(size_t)3 * EMB * EMB];     // W_qkv^T, rna, K-permuted
__device__ float g_wot[(size_t)EMB * EMB];         // W_out^T, rna, K-permuted

// ---------------------------------------------------------------------------
// helpers (portable PTX only)
// ---------------------------------------------------------------------------
__device__ __forceinline__ uint32_t smem_u32(const void* p) {
    uint32_t a;
    asm("{ .reg .u64 t; cvta.to.shared.u64 t, %1; cvt.u32.u64 %0, t; }" : "=r"(a) : "l"(p));
    return a;
}
__device__ __forceinline__ float rna_tf32(float v) {
    uint32_t u;
    asm("cvt.rna.tf32.f32 %0, %1;" : "=r"(u) : "f"(v));
    return __uint_as_float(u);
}
__device__ __forceinline__ float fexp2(float x) {
    float y;
    asm("ex2.approx.f32 %0, %1;" : "=f"(y) : "f"(x));
    return y;
}
__device__ __forceinline__ void cp_async16(uint32_t dst, const void* src) {
    asm volatile("cp.async.cg.shared.global [%0], [%1], 16;" :: "r"(dst), "l"(src));
}
__device__ __forceinline__ void cp_commit() {
    asm volatile("cp.async.commit_group;" ::: "memory");
}
template <int N>
__device__ __forceinline__ void cp_wait() {
    asm volatile("cp.async.wait_group %0;" :: "n"(N) : "memory");
}
__device__ __forceinline__ void mma_tf32(float& c0, float& c1, float& c2, float& c3,
                                         uint32_t a0, uint32_t a1, uint32_t a2, uint32_t a3,
                                         uint32_t b0, uint32_t b1) {
    asm volatile(
        "mma.sync.aligned.m16n8k8.row.col.f32.tf32.tf32.f32 "
        "{%0,%1,%2,%3}, {%4,%5,%6,%7}, {%8,%9}, {%0,%1,%2,%3};"
        : "+f"(c0), "+f"(c1), "+f"(c2), "+f"(c3)
        : "r"(a0), "r"(a1), "r"(a2), "r"(a3), "r"(b0), "r"(b1));
}

// ---------------------------------------------------------------------------
// rna(tf32) + K-permute: dst[row, 8g + pos(j)] = rna(src[row, 8g + j])
// Each thread handles a float4 = half an 8-group (j = 0..3 or 4..7).
// ---------------------------------------------------------------------------
__global__ void convert_rna_perm_kernel(const float* __restrict__ src,
                                        float* __restrict__ dst, int n4) {
    int i = blockIdx.x * blockDim.x + threadIdx.x;
    if (i < n4) {
        float4 v = ((const float4*)src)[i];
        const int i4 = i * 4;
        const int base = (i4 & ~7) | ((i4 & 4) ? 1 : 0);   // 8g (+1 if j>=4)
        dst[base + 0] = rna_tf32(v.x);
        dst[base + 2] = rna_tf32(v.y);
        dst[base + 4] = rna_tf32(v.z);
        dst[base + 6] = rna_tf32(v.w);
    }
}

// ---------------------------------------------------------------------------
// transpose + rna + K-permute: Wt[n][k0 + perm(x)] = rna(W[k0+x][n])
// ---------------------------------------------------------------------------
__global__ void transpose_rna_perm_kernel(const float* __restrict__ W,
                                          float* __restrict__ Wt, int K, int N) {
    __shared__ float t[32][33];
    const int n0 = blockIdx.x * 32, k0 = blockIdx.y * 32;
    const int x = threadIdx.x, y = threadIdx.y;  // 32 x 8
    #pragma unroll
    for (int i = 0; i < 4; i++)
        t[y + i * 8][x] = W[(size_t)(k0 + y + i * 8) * N + n0 + x];
    __syncthreads();
    const int j  = x & 7;
    const int px = (x & ~7) | ((j < 4) ? (2 * j) : (2 * (j - 4) + 1));
    #pragma unroll
    for (int i = 0; i < 4; i++)
        Wt[(size_t)(n0 + y + i * 8) * K + k0 + px] = rna_tf32(t[x][y + i * 8]);
}

// ---------------------------------------------------------------------------
// tf32 mma.sync GEMM: C[M,N] = A[M,K] @ Bt[N,K]^T + bias[N]
// A, Bt K-PERMUTED row-major. 128x128 CTA, 8 warps (2x4), warp 64x32, BK=32.
// Fragment loads are 64-bit (pair lc/lc+4 adjacent): 12 LDS vs 16 MMA / k-step.
// mode=1 -> rna output, Q cols (<1024) x0.125 (output stays NATURAL order).
// ---------------------------------------------------------------------------
#define BK 32
#define SROW 40                       /* pad8: LDS.64 conflict-free per 16-lane phase */
#define TILE_FLOATS (128 * SROW)      /* 5120 */
#define STAGE_FLOATS (2 * TILE_FLOATS)
#define NSTAGE 3
#define GEMM_SMEM (NSTAGE * STAGE_FLOATS * 4)   /* 122880 B */

__global__ __launch_bounds__(256)
void gemm_tf32_kernel(const float* __restrict__ A, const float* __restrict__ Bt,
                      const float* __restrict__ bias, float* __restrict__ C,
                      int M, int N, int K, int mode)
{
    extern __shared__ __align__(16) float sm[];

    const int tid  = threadIdx.x;
    const int wid  = tid >> 5;
    const int lane = tid & 31;
    const int wm   = (wid >> 2) * 64;
    const int wn   = (wid & 3) * 32;
    const int lr   = lane >> 2;
    const int lc   = lane & 3;
    const int n0   = blockIdx.x * 128;
    const int m0   = blockIdx.y * 128;
    const uint32_t smb = smem_u32(sm);

    float c[4][4][4];
    #pragma unroll
    for (int i = 0; i < 4; i++)
        #pragma unroll
        for (int j = 0; j < 4; j++)
            #pragma unroll
            for (int r = 0; r < 4; r++) c[i][j][r] = 0.f;

    auto load_stage = [&](int ch, int s) {
        const float* Ab = A  + (size_t)m0 * K + ch * BK;
        const float* Bb = Bt + (size_t)n0 * K + ch * BK;
        const uint32_t sA = smb + (uint32_t)(s * STAGE_FLOATS) * 4u;
        const uint32_t sB = sA + TILE_FLOATS * 4u;
        #pragma unroll
        for (int i = 0; i < 4; i++) {               // 128 rows x 8 float4 per tile
            const int chk = i * 256 + tid;          // 0..1023
            const int row = chk >> 3, c4 = chk & 7;
            const uint32_t off = (uint32_t)(row * SROW + c4 * 4) * 4u;
            cp_async16(sA + off, Ab + (size_t)row * K + c4 * 4);
            cp_async16(sB + off, Bb + (size_t)row * K + c4 * 4);
        }
    };

    const int NCH = K / BK;

    load_stage(0, 0); cp_commit();
    load_stage(1, 1); cp_commit();

    for (int ch = 0; ch < NCH; ch++) {
        cp_wait<1>();
        __syncthreads();
        if (ch + 2 < NCH) load_stage(ch + 2, (ch + 2) % NSTAGE);
        cp_commit();

        const float* As = sm + (ch % NSTAGE) * STAGE_FLOATS;
        const float* Bs = As + TILE_FLOATS;

        #pragma unroll
        for (int ks = 0; ks < 4; ks++) {
            const int dk = ks * 8 + 2 * lc;        // permuted: (lc, lc+4) adjacent
            uint32_t af[4][4], bf[4][2];
            #pragma unroll
            for (int mt = 0; mt < 4; mt++) {
                const float2 a02 = *(const float2*)(As + (wm + mt * 16 + lr) * SROW + dk);
                const float2 a13 = *(const float2*)(As + (wm + mt * 16 + lr + 8) * SROW + dk);
                af[mt][0] = __float_as_uint(a02.x);
                af[mt][1] = __float_as_uint(a13.x);
                af[mt][2] = __float_as_uint(a02.y);
                af[mt][3] = __float_as_uint(a13.y);
            }
            #pragma unroll
            for (int nt = 0; nt < 4; nt++) {
                const float2 b01 = *(const float2*)(Bs + (wn + nt * 8 + lr) * SROW + dk);
                bf[nt][0] = __float_as_uint(b01.x);
                bf[nt][1] = __float_as_uint(b01.y);
            }
            #pragma unroll
            for (int mt = 0; mt < 4; mt++)
                #pragma unroll
                for (int nt = 0; nt < 4; nt++)
                    mma_tf32(c[mt][nt][0], c[mt][nt][1], c[mt][nt][2], c[mt][nt][3],
                             af[mt][0], af[mt][1], af[mt][2], af[mt][3],
                             bf[nt][0], bf[nt][1]);
        }
        __syncthreads();
    }

    #pragma unroll
    for (int nt = 0; nt < 4; nt++) {
        const int col = n0 + wn + nt * 8 + 2 * lc;
        const float b0 = bias[col], b1 = bias[col + 1];
        const float sc = (mode && col < 1024) ? 0.125f : 1.0f;
        #pragma unroll
        for (int mt = 0; mt < 4; mt++) {
            const size_t r0 = (size_t)(m0 + wm + mt * 16 + lr);
            float v0 = (c[mt][nt][0] + b0) * sc;
            float v1 = (c[mt][nt][1] + b1) * sc;
            float v2 = (c[mt][nt][2] + b0) * sc;
            float v3 = (c[mt][nt][3] + b1) * sc;
            if (mode) {
                v0 = rna_tf32(v0); v1 = rna_tf32(v1);
                v2 = rna_tf32(v2); v3 = rna_tf32(v3);
            }
            *(float2*)(&C[r0 * N + col])       = make_float2(v0, v1);
            *(float2*)(&C[(r0 + 8) * N + col]) = make_float2(v2, v3);
        }
    }
}

// ---------------------------------------------------------------------------
// Flash attention with tf32 mma.sync (logic unchanged from R4).
// Epilogue now writes g_att K-PERMUTED (feeds the permuted GEMM2).
// ---------------------------------------------------------------------------
#define QS_OFF 0                 /* Q  [128][68]  */
#define PS_OFF 8704              /* P  [128][132] */
#define KS_OFF 25600             /* K  [128][68]  */
#define VR_OFF 34304             /* V  [128][68]  */
#define VT_OFF 43008             /* Vt [64][132]  */
#define ATT_SMEM ((43008 + 64 * 132) * 4)   /* 205824 B */

__global__ __launch_bounds__(256, 1)
void attn_mma_kernel(const float* __restrict__ qkv, float* __restrict__ out)
{
    extern __shared__ __align__(16) float sa[];

    const int tid  = threadIdx.x;
    const int wid  = tid >> 5;
    const int lane = tid & 31;
    const int lr   = lane >> 2;
    const int lc   = lane & 3;
    const int wm   = wid * 16;
    const int qt   = blockIdx.x;
    const int h    = blockIdx.y;
    const int b    = blockIdx.z;
    const int q0   = qt * 128;
    const float slope = fexp2(-0.5f * (float)(h + 1));
    const uint32_t smb = smem_u32(sa);

    const float* baseQ = qkv + (size_t)b * SEQ * 3072 + h * 64;
    const float* baseK = baseQ + 1024;
    const float* baseV = baseQ + 2048;

    auto load_tile = [&](const float* g, int row0, int soff) {
        #pragma unroll
        for (int i = 0; i < 8; i++) {
            const int chk = i * 256 + tid;          // 0..2047
            const int row = chk >> 4, c4 = chk & 15;
            cp_async16(smb + (uint32_t)(soff + row * 68 + c4 * 4) * 4u,
                       g + (size_t)(row0 + row) * 3072 + c4 * 4);
        }
    };

    load_tile(baseQ, q0, QS_OFF); cp_commit();
    load_tile(baseK, 0,  KS_OFF); cp_commit();
    load_tile(baseV, 0,  VR_OFF); cp_commit();

    float m0 = -1e30f, m1 = -1e30f, l0 = 0.f, l1 = 0.f;
    float o[8][4];
    #pragma unroll
    for (int i = 0; i < 8; i++)
        #pragma unroll
        for (int r = 0; r < 4; r++) o[i][r] = 0.f;

    const int qrow0 = q0 + wm + lr;
    const int qrow1 = qrow0 + 8;

    for (int kt = 0; kt <= qt; kt++) {
        cp_wait<1>();          // K(kt) (and Q) resident; V(kt) may still fly
        __syncthreads();

        // ---- S = Q @ K^T ----
        float c[16][4];
        #pragma unroll
        for (int nt = 0; nt < 16; nt++)
            #pragma unroll
            for (int r = 0; r < 4; r++) c[nt][r] = 0.f;

        #pragma unroll
        for (int dk = 0; dk < 8; dk++) {
            const float* ap = sa + QS_OFF + (wm + lr) * 68 + dk * 8 + lc;
            const uint32_t a0 = __float_as_uint(ap[0]);
            const uint32_t a1 = __float_as_uint(ap[8 * 68]);
            const uint32_t a2 = __float_as_uint(ap[4]);
            const uint32_t a3 = __float_as_uint(ap[8 * 68 + 4]);
            #pragma unroll
            for (int nt = 0; nt < 16; nt++) {
                const float* bp = sa + KS_OFF + (nt * 8 + lr) * 68 + dk * 8 + lc;
                mma_tf32(c[nt][0], c[nt][1], c[nt][2], c[nt][3],
                         a0, a1, a2, a3,
                         __float_as_uint(bp[0]), __float_as_uint(bp[4]));
            }
        }
        __syncthreads();       // done reading Ks
        if (kt < qt) load_tile(baseK, (kt + 1) * 128, KS_OFF);
        cp_commit();

        // ---- ALiBi + (diagonal-only) mask + online softmax ----
        const int kb = kt * 128 + 2 * lc;
        {
            float al0 = slope * (float)(kb - qrow0);
            float al1 = slope * (float)(kb - qrow1);
            const float st8 = 8.f * slope;
            float mx0 = -1e30f, mx1 = -1e30f;
            #pragma unroll
            for (int nt = 0; nt < 16; nt++) {
                float s0 = c[nt][0] + al0;
                float s1 = c[nt][1] + al0 + slope;
                float s2 = c[nt][2] + al1;
                float s3 = c[nt][3] + al1 + slope;
                if (kt == qt) {       // masking only possible on the diagonal tile
                    const int k0c = kb + nt * 8, k1c = k0c + 1;
                    if (k0c > qrow0) s0 = -1e30f;
                    if (k1c > qrow0) s1 = -1e30f;
                    if (k0c > qrow1) s2 = -1e30f;
                    if (k1c > qrow1) s3 = -1e30f;
                }
                c[nt][0] = s0; c[nt][1] = s1; c[nt][2] = s2; c[nt][3] = s3;
                mx0 = fmaxf(mx0, fmaxf(s0, s1));
                mx1 = fmaxf(mx1, fmaxf(s2, s3));
                al0 += st8; al1 += st8;
            }
            mx0 = fmaxf(mx0, __shfl_xor_sync(0xffffffffu, mx0, 1));
            mx0 = fmaxf(mx0, __shfl_xor_sync(0xffffffffu, mx0, 2));
            mx1 = fmaxf(mx1, __shfl_xor_sync(0xffffffffu, mx1, 1));
            mx1 = fmaxf(mx1, __shfl_xor_sync(0xffffffffu, mx1, 2));

            const float mn0 = fmaxf(m0, mx0), mn1 = fmaxf(m1, mx1);
            const float corr0 = fexp2((m0 - mn0) * L2E);
            const float corr1 = fexp2((m1 - mn1) * L2E);
            m0 = mn0; m1 = mn1;

            float ts0 = 0.f, ts1 = 0.f;
            float* p0 = sa + PS_OFF + (wm + lr) * 132 + 2 * lc;
            float* p1 = p0 + 8 * 132;
            #pragma unroll
            for (int nt = 0; nt < 16; nt++) {
                const float e0 = rna_tf32(fexp2((c[nt][0] - mn0) * L2E));
                const float e1 = rna_tf32(fexp2((c[nt][1] - mn0) * L2E));
                const float e2 = rna_tf32(fexp2((c[nt][2] - mn1) * L2E));
                const float e3 = rna_tf32(fexp2((c[nt][3] - mn1) * L2E));
                ts0 += e0 + e1;
                ts1 += e2 + e3;
                *(float2*)(p0 + nt * 8) = make_float2(e0, e1);
                *(float2*)(p1 + nt * 8) = make_float2(e2, e3);
            }
            ts0 += __shfl_xor_sync(0xffffffffu, ts0, 1);
            ts0 += __shfl_xor_sync(0xffffffffu, ts0, 2);
            ts1 += __shfl_xor_sync(0xffffffffu, ts1, 1);
            ts1 += __shfl_xor_sync(0xffffffffu, ts1, 2);
            l0 = l0 * corr0 + ts0;
            l1 = l1 * corr1 + ts1;
            #pragma unroll
            for (int i = 0; i < 8; i++) {
                o[i][0] *= corr0; o[i][1] *= corr0;
                o[i][2] *= corr1; o[i][3] *= corr1;
            }
        }

        cp_wait<1>();          // V(kt) resident; K(kt+1) may still fly
        __syncthreads();

        // ---- transpose V [128][64] -> Vt [64][128] ----
        {
            const int kvr = tid & 127;
            const int dc  = (tid >> 7) * 32;
            #pragma unroll
            for (int j = 0; j < 32; j += 4) {
                float4 v = *(const float4*)(sa + VR_OFF + kvr * 68 + dc + j);
                sa[VT_OFF + (dc + j + 0) * 132 + kvr] = v.x;
                sa[VT_OFF + (dc + j + 1) * 132 + kvr] = v.y;
                sa[VT_OFF + (dc + j + 2) * 132 + kvr] = v.z;
                sa[VT_OFF + (dc + j + 3) * 132 + kvr] = v.w;
            }
        }
        __syncthreads();

        // ---- O += P @ V ----
        #pragma unroll
        for (int dk = 0; dk < 16; dk++) {
            const float* pp = sa + PS_OFF + (wm + lr) * 132 + dk * 8 + lc;
            const uint32_t a0 = __float_as_uint(pp[0]);
            const uint32_t a1 = __float_as_uint(pp[8 * 132]);
            const uint32_t a2 = __float_as_uint(pp[4]);
            const uint32_t a3 = __float_as_uint(pp[8 * 132 + 4]);
            #pragma unroll
            for (int nt2 = 0; nt2 < 8; nt2++) {
                const float* bp = sa + VT_OFF + (nt2 * 8 + lr) * 132 + dk * 8 + lc;
                mma_tf32(o[nt2][0], o[nt2][1], o[nt2][2], o[nt2][3],
                         a0, a1, a2, a3,
                         __float_as_uint(bp[0]), __float_as_uint(bp[4]));
            }
        }
        __syncthreads();       // all warps done with Vt (and Vrm consumed)
        if (kt < qt) load_tile(baseV, (kt + 1) * 128, VR_OFF);
        cp_commit();
    }

    // ---- epilogue: normalize, rna, write K-PERMUTED (feeds permuted GEMM2) ----
    // d-in-group j = 2*lc -> perm pos p0 = (lc<2) ? 4*lc : 4*lc-7; j+1 -> p0+2.
    const float inv0 = 1.f / l0, inv1 = 1.f / l1;
    const int p0 = (lc < 2) ? (4 * lc) : (4 * lc - 7);
    float* og = out + ((size_t)b * SEQ + qrow0) * EMB + h * HDIM;
    #pragma unroll
    for (int nt2 = 0; nt2 < 8; nt2++) {
        og[nt2 * 8 + p0]         = rna_tf32(o[nt2][0] * inv0);
        og[nt2 * 8 + p0 + 2]     = rna_tf32(o[nt2][1] * inv0);
        og[8 * EMB + nt2 * 8 + p0]     = rna_tf32(o[nt2][2] * inv1);
        og[8 * EMB + nt2 * 8 + p0 + 2] = rna_tf32(o[nt2][3] * inv1);
    }
}

// ---------------------------------------------------------------------------
extern "C" void kernel_launch(void* const* d_in, const int* in_sizes, int n_in,
                              void* d_out, int out_size)
{
    const float* x    = (const float*)d_in[0];
    // d_in[1] = mask (bool tril) — causality handled analytically
    const float* Wqkv = (const float*)d_in[2];
    const float* bqkv = (const float*)d_in[3];
    const float* Wout = (const float*)d_in[4];
    const float* bout = (const float*)d_in[5];
    float* out = (float*)d_out;

    float *qkv_p, *att_p, *xc_p, *wqt_p, *wot_p;
    cudaGetSymbolAddress((void**)&qkv_p, g_qkv);
    cudaGetSymbolAddress((void**)&att_p, g_att);
    cudaGetSymbolAddress((void**)&xc_p,  g_xc);
    cudaGetSymbolAddress((void**)&wqt_p, g_wqt);
    cudaGetSymbolAddress((void**)&wot_p, g_wot);

    cudaFuncSetAttribute(gemm_tf32_kernel,
                         cudaFuncAttributeMaxDynamicSharedMemorySize, GEMM_SMEM);
    cudaFuncSetAttribute(attn_mma_kernel,
                         cudaFuncAttributeMaxDynamicSharedMemorySize, ATT_SMEM);

    // 0) tf32-round operands (K-permuted layouts for the GEMMs)
    {
        const int n4 = MROWS * EMB / 4;
        convert_rna_perm_kernel<<<(n4 + 255) / 256, 256>>>(x, xc_p, n4);
    }
    transpose_rna_perm_kernel<<<dim3(3 * EMB / 32, EMB / 32), dim3(32, 8)>>>(Wqkv, wqt_p, EMB, 3 * EMB);
    transpose_rna_perm_kernel<<<dim3(EMB / 32, EMB / 32),     dim3(32, 8)>>>(Wout, wot_p, EMB, EMB);

    // 1) qkv = x @ W_qkv + b_qkv; epilogue rna + Q*0.125 (mode=1), natural output
    gemm_tf32_kernel<<<dim3(3 * EMB / 128, MROWS / 128), 256, GEMM_SMEM>>>(
        xc_p, wqt_p, bqkv, qkv_p, MROWS, 3 * EMB, EMB, 1);

    // 2) attention (tf32 mma.sync); epilogue writes K-permuted g_att
    attn_mma_kernel<<<dim3(SEQ / 128, HEADS, BATCH), 256, ATT_SMEM>>>(qkv_p, att_p);

    // 3) out = att @ W_out + b_out (mode=0: plain fp32, natural output)
    gemm_tf32_kernel<<<dim3(EMB / 128, MROWS / 128), 256, GEMM_SMEM>>>(
        att_p, wot_p, bout, out, MROWS, EMB, EMB, 0);
}

// round 9
// speedup vs baseline: 1.2045x; 1.1155x over previous
#include <cuda_runtime.h>
#include <cstdint>
#include <math.h>

#define BATCH 4
#define SEQ   2048
#define EMB   1024
#define HEADS 16
#define HDIM  64
#define MROWS (BATCH*SEQ)   /* 8192 */
#define L2E   1.4426950408889634f

// K-dim permutation within 8-groups: pos(j) = j<4 ? 2j : 2(j-4)+1
// (fragment pair (lc, lc+4) becomes adjacent -> one 64-bit LDS)

// Scratch (device globals: allocation-free per harness rules)
__device__ float g_qkv[(size_t)MROWS * 3 * EMB];   // q,k d-permuted + Q scaled; v natural
__device__ float g_att[(size_t)MROWS * EMB];       // [8192, 1024] rna(tf32), K-permuted
__device__ float g_xc [(size_t)MROWS * EMB];       // x, rna(tf32), K-permuted
__device__ float g_wqt[(size_t)3 * EMB * EMB];     // W_qkv^T, rna, K-permuted
__device__ float g_wot[(size_t)EMB * EMB];         // W_out^T, rna, K-permuted

// ---------------------------------------------------------------------------
// helpers (portable PTX only)
// ---------------------------------------------------------------------------
__device__ __forceinline__ uint32_t smem_u32(const void* p) {
    uint32_t a;
    asm("{ .reg .u64 t; cvta.to.shared.u64 t, %1; cvt.u32.u64 %0, t; }" : "=r"(a) : "l"(p));
    return a;
}
__device__ __forceinline__ float rna_tf32(float v) {
    uint32_t u;
    asm("cvt.rna.tf32.f32 %0, %1;" : "=r"(u) : "f"(v));
    return __uint_as_float(u);
}
__device__ __forceinline__ float fexp2(float x) {
    float y;
    asm("ex2.approx.f32 %0, %1;" : "=f"(y) : "f"(x));
    return y;
}
__device__ __forceinline__ void cp_async16(uint32_t dst, const void* src) {
    asm volatile("cp.async.cg.shared.global [%0], [%1], 16;" :: "r"(dst), "l"(src));
}
__device__ __forceinline__ void cp_commit() {
    asm volatile("cp.async.commit_group;" ::: "memory");
}
template <int N>
__device__ __forceinline__ void cp_wait() {
    asm volatile("cp.async.wait_group %0;" :: "n"(N) : "memory");
}
__device__ __forceinline__ void mma_tf32(float& c0, float& c1, float& c2, float& c3,
                                         uint32_t a0, uint32_t a1, uint32_t a2, uint32_t a3,
                                         uint32_t b0, uint32_t b1) {
    asm volatile(
        "mma.sync.aligned.m16n8k8.row.col.f32.tf32.tf32.f32 "
        "{%0,%1,%2,%3}, {%4,%5,%6,%7}, {%8,%9}, {%0,%1,%2,%3};"
        : "+f"(c0), "+f"(c1), "+f"(c2), "+f"(c3)
        : "r"(a0), "r"(a1), "r"(a2), "r"(a3), "r"(b0), "r"(b1));
}

// ---------------------------------------------------------------------------
// rna(tf32) + K-permute: dst[row, 8g + pos(j)] = rna(src[row, 8g + j])
// ---------------------------------------------------------------------------
__global__ void convert_rna_perm_kernel(const float* __restrict__ src,
                                        float* __restrict__ dst, int n4) {
    int i = blockIdx.x * blockDim.x + threadIdx.x;
    if (i < n4) {
        float4 v = ((const float4*)src)[i];
        const int i4 = i * 4;
        const int base = (i4 & ~7) | ((i4 & 4) ? 1 : 0);
        dst[base + 0] = rna_tf32(v.x);
        dst[base + 2] = rna_tf32(v.y);
        dst[base + 4] = rna_tf32(v.z);
        dst[base + 6] = rna_tf32(v.w);
    }
}

// ---------------------------------------------------------------------------
// transpose + rna + K-permute: Wt[n][k0 + perm(x)] = rna(W[k0+x][n])
// ---------------------------------------------------------------------------
__global__ void transpose_rna_perm_kernel(const float* __restrict__ W,
                                          float* __restrict__ Wt, int K, int N) {
    __shared__ float t[32][33];
    const int n0 = blockIdx.x * 32, k0 = blockIdx.y * 32;
    const int x = threadIdx.x, y = threadIdx.y;  // 32 x 8
    #pragma unroll
    for (int i = 0; i < 4; i++)
        t[y + i * 8][x] = W[(size_t)(k0 + y + i * 8) * N + n0 + x];
    __syncthreads();
    const int j  = x & 7;
    const int px = (x & ~7) | ((j < 4) ? (2 * j) : (2 * (j - 4) + 1));
    #pragma unroll
    for (int i = 0; i < 4; i++)
        Wt[(size_t)(n0 + y + i * 8) * K + k0 + px] = rna_tf32(t[x][y + i * 8]);
}

// ---------------------------------------------------------------------------
// tf32 mma.sync GEMM: C[M,N] = A[M,K] @ Bt[N,K]^T + bias[N]
// A, Bt K-PERMUTED. 128x128 CTA, 8 warps (2x4), warp 64x32, BK=32.
// XOR-swizzled smem (8-float groups, row&3): SROW=32 exactly -> 98.3KB,
// 2 CTAs/SM; fragment LDS.64 conflict-free; XOR is per-thread constant.
// mode=1: rna output, Q(cols<1024) x0.125, q/k cols (<2048) d-PERMUTED.
// ---------------------------------------------------------------------------
#define BK 32
#define SROW 32
#define TILE_FLOATS (128 * SROW)      /* 4096 */
#define STAGE_FLOATS (2 * TILE_FLOATS)
#define NSTAGE 3
#define GEMM_SMEM (NSTAGE * STAGE_FLOATS * 4)   /* 98304 B */

__global__ __launch_bounds__(256, 2)
void gemm_tf32_kernel(const float* __restrict__ A, const float* __restrict__ Bt,
                      const float* __restrict__ bias, float* __restrict__ C,
                      int M, int N, int K, int mode)
{
    extern __shared__ __align__(16) float sm[];

    const int tid  = threadIdx.x;
    const int wid  = tid >> 5;
    const int lane = tid & 31;
    const int wm   = (wid >> 2) * 64;
    const int wn   = (wid & 3) * 32;
    const int lr   = lane >> 2;
    const int lc   = lane & 3;
    const int lxr  = lr & 3;
    const int n0   = blockIdx.x * 128;
    const int m0   = blockIdx.y * 128;
    const uint32_t smb = smem_u32(sm);

    float c[4][4][4];
    #pragma unroll
    for (int i = 0; i < 4; i++)
        #pragma unroll
        for (int j = 0; j < 4; j++)
            #pragma unroll
            for (int r = 0; r < 4; r++) c[i][j][r] = 0.f;

    auto load_stage = [&](int ch, int s) {
        const float* Ab = A  + (size_t)m0 * K + ch * BK;
        const float* Bb = Bt + (size_t)n0 * K + ch * BK;
        const uint32_t sA = smb + (uint32_t)(s * STAGE_FLOATS) * 4u;
        const uint32_t sB = sA + TILE_FLOATS * 4u;
        #pragma unroll
        for (int i = 0; i < 4; i++) {               // 128 rows x 8 float4 per tile
            const int chk = i * 256 + tid;          // 0..1023
            const int row = chk >> 3, c4 = chk & 7;
            const int sw4 = (((c4 >> 1) ^ (row & 3)) << 1) | (c4 & 1);  // XOR swizzle
            const uint32_t off = (uint32_t)(row * SROW + sw4 * 4) * 4u;
            cp_async16(sA + off, Ab + (size_t)row * K + c4 * 4);
            cp_async16(sB + off, Bb + (size_t)row * K + c4 * 4);
        }
    };

    const int NCH = K / BK;

    load_stage(0, 0); cp_commit();
    load_stage(1, 1); cp_commit();

    for (int ch = 0; ch < NCH; ch++) {
        cp_wait<1>();
        __syncthreads();
        if (ch + 2 < NCH) load_stage(ch + 2, (ch + 2) % NSTAGE);
        cp_commit();

        const float* As = sm + (ch % NSTAGE) * STAGE_FLOATS;
        const float* Bs = As + TILE_FLOATS;

        #pragma unroll
        for (int ks = 0; ks < 4; ks++) {
            const int ko = ((ks ^ lxr) << 3) + 2 * lc;   // swizzled group offset
            uint32_t af[4][4], bf[4][2];
            #pragma unroll
            for (int mt = 0; mt < 4; mt++) {
                const float2 a02 = *(const float2*)(As + (wm + mt * 16 + lr) * SROW + ko);
                const float2 a13 = *(const float2*)(As + (wm + mt * 16 + lr + 8) * SROW + ko);
                af[mt][0] = __float_as_uint(a02.x);
                af[mt][1] = __float_as_uint(a13.x);
                af[mt][2] = __float_as_uint(a02.y);
                af[mt][3] = __float_as_uint(a13.y);
            }
            #pragma unroll
            for (int nt = 0; nt < 4; nt++) {
                const float2 b01 = *(const float2*)(Bs + (wn + nt * 8 + lr) * SROW + ko);
                bf[nt][0] = __float_as_uint(b01.x);
                bf[nt][1] = __float_as_uint(b01.y);
            }
            #pragma unroll
            for (int mt = 0; mt < 4; mt++)
                #pragma unroll
                for (int nt = 0; nt < 4; nt++)
                    mma_tf32(c[mt][nt][0], c[mt][nt][1], c[mt][nt][2], c[mt][nt][3],
                             af[mt][0], af[mt][1], af[mt][2], af[mt][3],
                             bf[nt][0], bf[nt][1]);
        }
        __syncthreads();
    }

    const int p0 = (lc < 2) ? (4 * lc) : (4 * lc - 7);   // perm pos of j=2lc (j+1 -> p0+2)
    #pragma unroll
    for (int nt = 0; nt < 4; nt++) {
        const int col = n0 + wn + nt * 8 + 2 * lc;
        const float b0 = bias[col], b1 = bias[col + 1];
        const float sc = (mode && col < 1024) ? 0.125f : 1.0f;
        #pragma unroll
        for (int mt = 0; mt < 4; mt++) {
            const size_t r0 = (size_t)(m0 + wm + mt * 16 + lr);
            float v0 = (c[mt][nt][0] + b0) * sc;
            float v1 = (c[mt][nt][1] + b1) * sc;
            float v2 = (c[mt][nt][2] + b0) * sc;
            float v3 = (c[mt][nt][3] + b1) * sc;
            if (mode) {
                v0 = rna_tf32(v0); v1 = rna_tf32(v1);
                v2 = rna_tf32(v2); v3 = rna_tf32(v3);
            }
            if (mode && col < 2048) {
                // q,k: write d-PERMUTED (attention loads 64-bit fragments)
                const int cb = col & ~7;
                C[r0 * N + cb + p0]           = v0;
                C[r0 * N + cb + p0 + 2]       = v1;
                C[(r0 + 8) * N + cb + p0]     = v2;
                C[(r0 + 8) * N + cb + p0 + 2] = v3;
            } else {
                *(float2*)(&C[r0 * N + col])       = make_float2(v0, v1);
                *(float2*)(&C[(r0 + 8) * N + col]) = make_float2(v2, v3);
            }
        }
    }
}

// ---------------------------------------------------------------------------
// Flash attention, tf32 mma.sync, 64-bit fragment loads everywhere.
// Q,K arrive d-permuted (GEMM1); P and Vt stored seq-permuted here.
// Strides: Q/K 72, V 68, P/Vt 136 (stride mod 32 == 8 -> LDS.64 conflict-free).
// ---------------------------------------------------------------------------
#define QS_OFF 0                 /* Q  [128][72]  */
#define KS_OFF 9216              /* K  [128][72]  */
#define VR_OFF 18432             /* V  [128][68]  */
#define PS_OFF 27136             /* P  [128][136] */
#define VT_OFF 44544             /* Vt [64][136]  */
#define ATT_SMEM ((44544 + 64 * 136) * 4)   /* 212992 B */

__global__ __launch_bounds__(256, 1)
void attn_mma_kernel(const float* __restrict__ qkv, float* __restrict__ out)
{
    extern __shared__ __align__(16) float sa[];

    const int tid  = threadIdx.x;
    const int wid  = tid >> 5;
    const int lane = tid & 31;
    const int lr   = lane >> 2;
    const int lc   = lane & 3;
    const int wm   = wid * 16;
    const int qt   = blockIdx.x;
    const int h    = blockIdx.y;
    const int b    = blockIdx.z;
    const int q0   = qt * 128;
    const float slope = fexp2(-0.5f * (float)(h + 1));
    const uint32_t smb = smem_u32(sa);
    const int p0 = (lc < 2) ? (4 * lc) : (4 * lc - 7);

    const float* baseQ = qkv + (size_t)b * SEQ * 3072 + h * 64;
    const float* baseK = baseQ + 1024;
    const float* baseV = baseQ + 2048;

    auto load_tile = [&](const float* g, int row0, int soff, int stride) {
        #pragma unroll
        for (int i = 0; i < 8; i++) {
            const int chk = i * 256 + tid;          // 0..2047
            const int row = chk >> 4, c4 = chk & 15;
            cp_async16(smb + (uint32_t)(soff + row * stride + c4 * 4) * 4u,
                       g + (size_t)(row0 + row) * 3072 + c4 * 4);
        }
    };

    load_tile(baseQ, q0, QS_OFF, 72); cp_commit();
    load_tile(baseK, 0,  KS_OFF, 72); cp_commit();
    load_tile(baseV, 0,  VR_OFF, 68); cp_commit();

    float m0 = -1e30f, m1 = -1e30f, l0 = 0.f, l1 = 0.f;
    float o[8][4];
    #pragma unroll
    for (int i = 0; i < 8; i++)
        #pragma unroll
        for (int r = 0; r < 4; r++) o[i][r] = 0.f;

    const int qrow0 = q0 + wm + lr;
    const int qrow1 = qrow0 + 8;

    for (int kt = 0; kt <= qt; kt++) {
        cp_wait<1>();          // K(kt) (and Q) resident; V(kt) may still fly
        __syncthreads();

        // ---- S = Q @ K^T  (d-permuted: fragments are LDS.64) ----
        float c[16][4];
        #pragma unroll
        for (int nt = 0; nt < 16; nt++)
            #pragma unroll
            for (int r = 0; r < 4; r++) c[nt][r] = 0.f;

        #pragma unroll
        for (int dk = 0; dk < 8; dk++) {
            const int ko = dk * 8 + 2 * lc;
            const float2 qa = *(const float2*)(sa + QS_OFF + (wm + lr) * 72 + ko);
            const float2 qb = *(const float2*)(sa + QS_OFF + (wm + lr + 8) * 72 + ko);
            const uint32_t a0 = __float_as_uint(qa.x);
            const uint32_t a1 = __float_as_uint(qb.x);
            const uint32_t a2 = __float_as_uint(qa.y);
            const uint32_t a3 = __float_as_uint(qb.y);
            #pragma unroll
            for (int nt = 0; nt < 16; nt++) {
                const float2 kb2 = *(const float2*)(sa + KS_OFF + (nt * 8 + lr) * 72 + ko);
                mma_tf32(c[nt][0], c[nt][1], c[nt][2], c[nt][3],
                         a0, a1, a2, a3,
                         __float_as_uint(kb2.x), __float_as_uint(kb2.y));
            }
        }
        __syncthreads();       // done reading Ks
        if (kt < qt) load_tile(baseK, (kt + 1) * 128, KS_OFF, 72);
        cp_commit();

        // ---- ALiBi + (diagonal-only) mask + online softmax ----
        const int kb = kt * 128 + 2 * lc;
        {
            float al0 = slope * (float)(kb - qrow0);
            float al1 = slope * (float)(kb - qrow1);
            const float st8 = 8.f * slope;
            float mx0 = -1e30f, mx1 = -1e30f;
            #pragma unroll
            for (int nt = 0; nt < 16; nt++) {
                float s0 = c[nt][0] + al0;
                float s1 = c[nt][1] + al0 + slope;
                float s2 = c[nt][2] + al1;
                float s3 = c[nt][3] + al1 + slope;
                if (kt == qt) {
                    const int k0c = kb + nt * 8, k1c = k0c + 1;
                    if (k0c > qrow0) s0 = -1e30f;
                    if (k1c > qrow0) s1 = -1e30f;
                    if (k0c > qrow1) s2 = -1e30f;
                    if (k1c > qrow1) s3 = -1e30f;
                }
                c[nt][0] = s0; c[nt][1] = s1; c[nt][2] = s2; c[nt][3] = s3;
                mx0 = fmaxf(mx0, fmaxf(s0, s1));
                mx1 = fmaxf(mx1, fmaxf(s2, s3));
                al0 += st8; al1 += st8;
            }
            mx0 = fmaxf(mx0, __shfl_xor_sync(0xffffffffu, mx0, 1));
            mx0 = fmaxf(mx0, __shfl_xor_sync(0xffffffffu, mx0, 2));
            mx1 = fmaxf(mx1, __shfl_xor_sync(0xffffffffu, mx1, 1));
            mx1 = fmaxf(mx1, __shfl_xor_sync(0xffffffffu, mx1, 2));

            const float mn0 = fmaxf(m0, mx0), mn1 = fmaxf(m1, mx1);
            const float corr0 = fexp2((m0 - mn0) * L2E);
            const float corr1 = fexp2((m1 - mn1) * L2E);
            m0 = mn0; m1 = mn1;

            float ts0 = 0.f, ts1 = 0.f;
            float* prow0 = sa + PS_OFF + (wm + lr) * 136;
            float* prow1 = prow0 + 8 * 136;
            #pragma unroll
            for (int nt = 0; nt < 16; nt++) {
                const float e0 = rna_tf32(fexp2((c[nt][0] - mn0) * L2E));
                const float e1 = rna_tf32(fexp2((c[nt][1] - mn0) * L2E));
                const float e2 = rna_tf32(fexp2((c[nt][2] - mn1) * L2E));
                const float e3 = rna_tf32(fexp2((c[nt][3] - mn1) * L2E));
                ts0 += e0 + e1;
                ts1 += e2 + e3;
                prow0[nt * 8 + p0]     = e0;   // seq-PERMUTED P
                prow0[nt * 8 + p0 + 2] = e1;
                prow1[nt * 8 + p0]     = e2;
                prow1[nt * 8 + p0 + 2] = e3;
            }
            ts0 += __shfl_xor_sync(0xffffffffu, ts0, 1);
            ts0 += __shfl_xor_sync(0xffffffffu, ts0, 2);
            ts1 += __shfl_xor_sync(0xffffffffu, ts1, 1);
            ts1 += __shfl_xor_sync(0xffffffffu, ts1, 2);
            l0 = l0 * corr0 + ts0;
            l1 = l1 * corr1 + ts1;
            #pragma unroll
            for (int i = 0; i < 8; i++) {
                o[i][0] *= corr0; o[i][1] *= corr0;
                o[i][2] *= corr1; o[i][3] *= corr1;
            }
        }

        cp_wait<1>();          // V(kt) resident; K(kt+1) may still fly
        __syncthreads();

        // ---- transpose V [128][64] -> Vt [64][136], seq-PERMUTED columns ----
        {
            const int kvr = tid & 127;
            const int dc  = (tid >> 7) * 32;
            const int jv  = kvr & 7;
            const int pc  = (kvr & ~7) | ((jv < 4) ? (2 * jv) : (2 * (jv - 4) + 1));
            #pragma unroll
            for (int j = 0; j < 32; j += 4) {
                float4 v = *(const float4*)(sa + VR_OFF + kvr * 68 + dc + j);
                sa[VT_OFF + (dc + j + 0) * 136 + pc] = v.x;
                sa[VT_OFF + (dc + j + 1) * 136 + pc] = v.y;
                sa[VT_OFF + (dc + j + 2) * 136 + pc] = v.z;
                sa[VT_OFF + (dc + j + 3) * 136 + pc] = v.w;
            }
        }
        __syncthreads();

        // ---- O += P @ V  (seq-permuted: fragments are LDS.64) ----
        #pragma unroll
        for (int dk = 0; dk < 16; dk++) {
            const int ko = dk * 8 + 2 * lc;
            const float2 pa0 = *(const float2*)(sa + PS_OFF + (wm + lr) * 136 + ko);
            const float2 pa1 = *(const float2*)(sa + PS_OFF + (wm + lr + 8) * 136 + ko);
            const uint32_t a0 = __float_as_uint(pa0.x);
            const uint32_t a1 = __float_as_uint(pa1.x);
            const uint32_t a2 = __float_as_uint(pa0.y);
            const uint32_t a3 = __float_as_uint(pa1.y);
            #pragma unroll
            for (int nt2 = 0; nt2 < 8; nt2++) {
                const float2 vb = *(const float2*)(sa + VT_OFF + (nt2 * 8 + lr) * 136 + ko);
                mma_tf32(o[nt2][0], o[nt2][1], o[nt2][2], o[nt2][3],
                         a0, a1, a2, a3,
                         __float_as_uint(vb.x), __float_as_uint(vb.y));
            }
        }
        __syncthreads();       // all warps done with Vt (and Vrm consumed)
        if (kt < qt) load_tile(baseV, (kt + 1) * 128, VR_OFF, 68);
        cp_commit();
    }

    // ---- epilogue: normalize, rna, write K-PERMUTED (feeds permuted GEMM2) ----
    const float inv0 = 1.f / l0, inv1 = 1.f / l1;
    float* og = out + ((size_t)b * SEQ + qrow0) * EMB + h * HDIM;
    #pragma unroll
    for (int nt2 = 0; nt2 < 8; nt2++) {
        og[nt2 * 8 + p0]               = rna_tf32(o[nt2][0] * inv0);
        og[nt2 * 8 + p0 + 2]           = rna_tf32(o[nt2][1] * inv0);
        og[8 * EMB + nt2 * 8 + p0]     = rna_tf32(o[nt2][2] * inv1);
        og[8 * EMB + nt2 * 8 + p0 + 2] = rna_tf32(o[nt2][3] * inv1);
    }
}

// ---------------------------------------------------------------------------
extern "C" void kernel_launch(void* const* d_in, const int* in_sizes, int n_in,
                              void* d_out, int out_size)
{
    const float* x    = (const float*)d_in[0];
    // d_in[1] = mask (bool tril) — causality handled analytically
    const float* Wqkv = (const float*)d_in[2];
    const float* bqkv = (const float*)d_in[3];
    const float* Wout = (const float*)d_in[4];
    const float* bout = (const float*)d_in[5];
    float* out = (float*)d_out;

    float *qkv_p, *att_p, *xc_p, *wqt_p, *wot_p;
    cudaGetSymbolAddress((void**)&qkv_p, g_qkv);
    cudaGetSymbolAddress((void**)&att_p, g_att);
    cudaGetSymbolAddress((void**)&xc_p,  g_xc);
    cudaGetSymbolAddress((void**)&wqt_p, g_wqt);
    cudaGetSymbolAddress((void**)&wot_p, g_wot);

    cudaFuncSetAttribute(gemm_tf32_kernel,
                         cudaFuncAttributeMaxDynamicSharedMemorySize, GEMM_SMEM);
    cudaFuncSetAttribute(attn_mma_kernel,
                         cudaFuncAttributeMaxDynamicSharedMemorySize, ATT_SMEM);

    // 0) tf32-round operands (K-permuted layouts for the GEMMs)
    {
        const int n4 = MROWS * EMB / 4;
        convert_rna_perm_kernel<<<(n4 + 255) / 256, 256>>>(x, xc_p, n4);
    }
    transpose_rna_perm_kernel<<<dim3(3 * EMB / 32, EMB / 32), dim3(32, 8)>>>(Wqkv, wqt_p, EMB, 3 * EMB);
    transpose_rna_perm_kernel<<<dim3(EMB / 32, EMB / 32),     dim3(32, 8)>>>(Wout, wot_p, EMB, EMB);

    // 1) qkv = x @ W_qkv + b_qkv; rna + Q*0.125; q,k d-permuted, v natural
    gemm_tf32_kernel<<<dim3(3 * EMB / 128, MROWS / 128), 256, GEMM_SMEM>>>(
        xc_p, wqt_p, bqkv, qkv_p, MROWS, 3 * EMB, EMB, 1);

    // 2) attention (tf32 mma.sync); epilogue writes K-permuted g_att
    attn_mma_kernel<<<dim3(SEQ / 128, HEADS, BATCH), 256, ATT_SMEM>>>(qkv_p, att_p);

    // 3) out = att @ W_out + b_out (mode=0: plain fp32, natural output)
    gemm_tf32_kernel<<<dim3(EMB / 128, MROWS / 128), 256, GEMM_SMEM>>>(
        att_p, wot_p, bout, out, MROWS, EMB, EMB, 0);
}

// round 10
// speedup vs baseline: 1.7571x; 1.4587x over previous
#include <cuda_runtime.h>
#include <cuda_fp16.h>
#include <cstdint>
#include <math.h>

#define BATCH 4
#define SEQ   2048
#define EMB   1024
#define HEADS 16
#define HDIM  64
#define MROWS (BATCH*SEQ)   /* 8192 */
#define L2E   1.4426950408889634f

// Pair-permute within 16-half groups: pair p -> pos (p<4 ? 2p : 2(p-4)+1).
// Thread lc's two fragment pairs (lc, lc+4) land adjacent -> one LDS.64.

// Scratch (device globals: allocation-free per harness rules)
__device__ __align__(16) __half g_qk [(size_t)MROWS * 2 * EMB];          // q|k, d-permuted, q scaled
__device__ __align__(16) __half g_vt [(size_t)BATCH * HEADS * HDIM * SEQ]; // V^T, seq-permuted
__device__ __align__(16) __half g_att[(size_t)MROWS * EMB];              // attn out, k-permuted
__device__ __align__(16) __half g_xc [(size_t)MROWS * EMB];              // x, k-permuted
__device__ __align__(16) __half g_wqt[(size_t)3 * EMB * EMB];            // W_qkv^T, k-permuted
__device__ __align__(16) __half g_wot[(size_t)EMB * EMB];                // W_out^T, k-permuted

// ---------------------------------------------------------------------------
// helpers (portable PTX only)
// ---------------------------------------------------------------------------
__device__ __forceinline__ uint32_t smem_u32(const void* p) {
    uint32_t a;
    asm("{ .reg .u64 t; cvta.to.shared.u64 t, %1; cvt.u32.u64 %0, t; }" : "=r"(a) : "l"(p));
    return a;
}
__device__ __forceinline__ float fexp2(float x) {
    float y;
    asm("ex2.approx.f32 %0, %1;" : "=f"(y) : "f"(x));
    return y;
}
__device__ __forceinline__ void cp_async16(uint32_t dst, const void* src) {
    asm volatile("cp.async.cg.shared.global [%0], [%1], 16;" :: "r"(dst), "l"(src));
}
__device__ __forceinline__ void cp_commit() {
    asm volatile("cp.async.commit_group;" ::: "memory");
}
template <int N>
__device__ __forceinline__ void cp_wait() {
    asm volatile("cp.async.wait_group %0;" :: "n"(N) : "memory");
}
__device__ __forceinline__ void mma_f16(float& c0, float& c1, float& c2, float& c3,
                                        uint32_t a0, uint32_t a1, uint32_t a2, uint32_t a3,
                                        uint32_t b0, uint32_t b1) {
    asm volatile(
        "mma.sync.aligned.m16n8k16.row.col.f32.f16.f16.f32 "
        "{%0,%1,%2,%3}, {%4,%5,%6,%7}, {%8,%9}, {%0,%1,%2,%3};"
        : "+f"(c0), "+f"(c1), "+f"(c2), "+f"(c3)
        : "r"(a0), "r"(a1), "r"(a2), "r"(a3), "r"(b0), "r"(b1));
}
__device__ __forceinline__ int perm16h(int j) {   // half index j (0..15) -> permuted pos
    const int p = j >> 1;
    return ((p < 4) ? 4 * p : 4 * p - 14) + (j & 1);
}

// ---------------------------------------------------------------------------
// fp32 -> fp16, pair-permuted per 16-half group (one thread per group)
// ---------------------------------------------------------------------------
__global__ void convert_half_perm_kernel(const float* __restrict__ src,
                                         __half* __restrict__ dst, int ngroups) {
    int g = blockIdx.x * blockDim.x + threadIdx.x;
    if (g >= ngroups) return;
    const float* s = src + (size_t)g * 16;
    __half2 o[8];
    #pragma unroll
    for (int pp = 0; pp < 8; pp++) {
        const int p = (pp & 1) ? ((pp >> 1) + 4) : (pp >> 1);
        o[pp] = __floats2half2_rn(s[2 * p], s[2 * p + 1]);
    }
    *(uint4*)(dst + (size_t)g * 16)     = *(uint4*)(o);
    *(uint4*)(dst + (size_t)g * 16 + 8) = *(uint4*)(o + 4);
}

// ---------------------------------------------------------------------------
// transpose + fp16 + pair-permute: Wt[n][perm(k)] = h(W[k][n])
// ---------------------------------------------------------------------------
__global__ void transpose_half_perm_kernel(const float* __restrict__ W,
                                           __half* __restrict__ Wt, int K, int N) {
    __shared__ float t[32][33];
    const int n0 = blockIdx.x * 32, k0 = blockIdx.y * 32;
    const int x = threadIdx.x, y = threadIdx.y;  // 32 x 8
    #pragma unroll
    for (int i = 0; i < 4; i++)
        t[y + i * 8][x] = W[(size_t)(k0 + y + i * 8) * N + n0 + x];
    __syncthreads();
    const int px = (x & 16) + perm16h(x & 15);
    #pragma unroll
    for (int i = 0; i < 4; i++)
        Wt[(size_t)(n0 + y + i * 8) * K + k0 + px] = __float2half_rn(t[x][y + i * 8]);
}

// ---------------------------------------------------------------------------
// fp16 mma.sync GEMM: C[M,N] = A[M,K] @ Bt[N,K]^T + bias[N]
// A, Bt half, pair-permuted. 128x128 CTA, 8 warps (2x4), warp 64x32, BK=64.
// smem tiles [4 k16][128][16 halfs] -- conflict-free STS(cp.async) and LDS.64.
// mode=1: q cols scaled 0.125; q,k -> g_qk (d-permuted half2);
//         v -> g_vt transposed (seq-permuted). mode=0: fp32 natural + bias.
// ---------------------------------------------------------------------------
#define BKH 64
#define TILE_HALFS (4 * 128 * 16)     /* 8192 */
#define STAGE_HALFS (2 * TILE_HALFS)
#define NSTAGE 3
#define GEMM_SMEM (NSTAGE * STAGE_HALFS * 2)   /* 98304 B */

__global__ __launch_bounds__(256, 2)
void gemm_f16_kernel(const __half* __restrict__ A, const __half* __restrict__ Bt,
                     const float* __restrict__ bias, float* __restrict__ Cf,
                     int M, int N, int K, int mode)
{
    extern __shared__ __align__(16) __half sh[];

    const int tid  = threadIdx.x;
    const int wid  = tid >> 5;
    const int lane = tid & 31;
    const int wm   = (wid >> 2) * 64;
    const int wn   = (wid & 3) * 32;
    const int lr   = lane >> 2;
    const int lc   = lane & 3;
    const int n0   = blockIdx.x * 128;
    const int m0   = blockIdx.y * 128;
    const uint32_t smb = smem_u32(sh);

    float c[4][4][4];
    #pragma unroll
    for (int i = 0; i < 4; i++)
        #pragma unroll
        for (int j = 0; j < 4; j++)
            #pragma unroll
            for (int r = 0; r < 4; r++) c[i][j][r] = 0.f;

    auto load_stage = [&](int ch, int s) {
        const __half* Ab = A  + (size_t)m0 * K + ch * BKH;
        const __half* Bb = Bt + (size_t)n0 * K + ch * BKH;
        const uint32_t sA = smb + (uint32_t)(s * STAGE_HALFS) * 2u;
        const uint32_t sB = sA + TILE_HALFS * 2u;
        #pragma unroll
        for (int i = 0; i < 4; i++) {
            const int chk = i * 256 + tid;            // 0..1023
            const int hh = chk & 1, row = (chk >> 1) & 127, ss = chk >> 8;
            const uint32_t off = (uint32_t)(((ss * 128 + row) * 16 + hh * 8) * 2);
            const size_t gofs = (size_t)row * K + ss * 16 + hh * 8;
            cp_async16(sA + off, Ab + gofs);
            cp_async16(sB + off, Bb + gofs);
        }
    };

    const int NCH = K / BKH;

    load_stage(0, 0); cp_commit();
    load_stage(1, 1); cp_commit();

    for (int ch = 0; ch < NCH; ch++) {
        cp_wait<1>();
        __syncthreads();
        if (ch + 2 < NCH) load_stage(ch + 2, (ch + 2) % NSTAGE);
        cp_commit();

        const __half* As = sh + (ch % NSTAGE) * STAGE_HALFS;
        const __half* Bs = As + TILE_HALFS;

        #pragma unroll
        for (int s = 0; s < 4; s++) {
            uint2 af[4][2];
            uint2 bf[4];
            #pragma unroll
            for (int mt = 0; mt < 4; mt++) {
                af[mt][0] = *(const uint2*)(As + ((s * 128 + wm + mt * 16 + lr) << 4) + 4 * lc);
                af[mt][1] = *(const uint2*)(As + ((s * 128 + wm + mt * 16 + lr + 8) << 4) + 4 * lc);
            }
            #pragma unroll
            for (int nt = 0; nt < 4; nt++)
                bf[nt] = *(const uint2*)(Bs + ((s * 128 + wn + nt * 8 + lr) << 4) + 4 * lc);
            #pragma unroll
            for (int mt = 0; mt < 4; mt++)
                #pragma unroll
                for (int nt = 0; nt < 4; nt++)
                    mma_f16(c[mt][nt][0], c[mt][nt][1], c[mt][nt][2], c[mt][nt][3],
                            af[mt][0].x, af[mt][1].x, af[mt][0].y, af[mt][1].y,
                            bf[nt].x, bf[nt].y);
        }
        __syncthreads();
    }

    if (mode == 1) {
        const int region = n0 >> 10;               // 0=q, 1=k, 2=v
        const float sc = (region == 0) ? 0.125f : 1.0f;
        #pragma unroll
        for (int nt = 0; nt < 4; nt++) {
            const int col = n0 + wn + nt * 8 + 2 * lc;
            const float b0v = bias[col], b1v = bias[col + 1];
            #pragma unroll
            for (int mt = 0; mt < 4; mt++) {
                const int r0 = m0 + wm + mt * 16 + lr;
                const float v0 = (c[mt][nt][0] + b0v) * sc;
                const float v1 = (c[mt][nt][1] + b1v) * sc;
                const float v2 = (c[mt][nt][2] + b0v) * sc;
                const float v3 = (c[mt][nt][3] + b1v) * sc;
                if (region < 2) {
                    const int cp2 = (col & ~15) + perm16h(col & 15);
                    *(__half2*)(&g_qk[(size_t)r0 * 2048 + cp2])       = __floats2half2_rn(v0, v1);
                    *(__half2*)(&g_qk[(size_t)(r0 + 8) * 2048 + cp2]) = __floats2half2_rn(v2, v3);
                } else {
                    const int d = col - 2048, hh = d >> 6, dd = d & 63;
                    const int bb = r0 >> 11, seq = r0 & 2047;
                    const int sg = seq & ~15, sj = seq & 15;
                    const int sp  = sg + perm16h(sj);
                    const int sp8 = sg + perm16h(sj + 8);
                    __half* vb = g_vt + ((size_t)(bb * HEADS + hh) * 64 + dd) * 2048;
                    vb[sp]  = __float2half_rn(v0);
                    vb[sp8] = __float2half_rn(v2);
                    vb += 2048;                    // dd+1
                    vb[sp]  = __float2half_rn(v1);
                    vb[sp8] = __float2half_rn(v3);
                }
            }
        }
    } else {
        #pragma unroll
        for (int nt = 0; nt < 4; nt++) {
            const int col = n0 + wn + nt * 8 + 2 * lc;
            const float b0v = bias[col], b1v = bias[col + 1];
            #pragma unroll
            for (int mt = 0; mt < 4; mt++) {
                const size_t r0 = (size_t)(m0 + wm + mt * 16 + lr);
                *(float2*)(&Cf[r0 * N + col]) =
                    make_float2(c[mt][nt][0] + b0v, c[mt][nt][1] + b1v);
                *(float2*)(&Cf[(r0 + 8) * N + col]) =
                    make_float2(c[mt][nt][2] + b0v, c[mt][nt][3] + b1v);
            }
        }
    }
}

// ---------------------------------------------------------------------------
// Flash attention, fp16 mma.sync m16n8k16. Q/K d-permuted, Vt pre-transposed
// seq-permuted (no in-kernel transpose). K/Vt double-buffered cp.async.
// smem halfs: QS[4][128][16] | KS 2x[4][128][16] | VT 2x[8][64][16] | PS[8][128][16]
// ---------------------------------------------------------------------------
#define QS_OFF 0
#define KS_OFF 8192
#define VT_OFF 24576
#define PS_OFF 40960
#define ATT_SMEM ((40960 + 16384) * 2)   /* 114688 B */

__global__ __launch_bounds__(256, 1)
void attn_f16_kernel(const __half* __restrict__ qk, const __half* __restrict__ vt,
                     __half* __restrict__ out)
{
    extern __shared__ __align__(16) __half sa[];

    const int tid  = threadIdx.x;
    const int wid  = tid >> 5;
    const int lane = tid & 31;
    const int lr   = lane >> 2;
    const int lc   = lane & 3;
    const int wm   = wid * 16;
    const int qt   = blockIdx.x;
    const int h    = blockIdx.y;
    const int b    = blockIdx.z;
    const int q0   = qt * 128;
    const float slope = fexp2(-0.5f * (float)(h + 1));
    const uint32_t smb = smem_u32(sa);

    const __half* baseQ = qk + (size_t)b * SEQ * 2048 + h * 64;
    const __half* baseK = baseQ + 1024;
    const __half* baseV = vt + (size_t)(b * HEADS + h) * 64 * 2048;

    auto load_qk = [&](const __half* g, int row0, int soff) {   // [4][128][16]
        #pragma unroll
        for (int i = 0; i < 4; i++) {
            const int chk = i * 256 + tid;
            const int hh = chk & 1, row = (chk >> 1) & 127, ss = chk >> 8;
            cp_async16(smb + (uint32_t)((soff + (ss * 128 + row) * 16 + hh * 8) * 2),
                       g + (size_t)(row0 + row) * 2048 + ss * 16 + hh * 8);
        }
    };
    auto load_vt = [&](int kt, int soff) {                      // [8][64][16]
        #pragma unroll
        for (int i = 0; i < 4; i++) {
            const int chk = i * 256 + tid;
            const int hh = chk & 1, d = (chk >> 1) & 63, ss = chk >> 7;
            cp_async16(smb + (uint32_t)((soff + (ss * 64 + d) * 16 + hh * 8) * 2),
                       baseV + (size_t)d * 2048 + kt * 128 + ss * 16 + hh * 8);
        }
    };

    load_qk(baseQ, q0, QS_OFF);
    load_qk(baseK, 0, KS_OFF);
    load_vt(0, VT_OFF);
    cp_commit();

    float m0 = -1e30f, m1 = -1e30f, l0 = 0.f, l1 = 0.f;
    float o[8][4];
    #pragma unroll
    for (int i = 0; i < 8; i++)
        #pragma unroll
        for (int r = 0; r < 4; r++) o[i][r] = 0.f;

    const int qrow0 = q0 + wm + lr;
    const int qrow1 = qrow0 + 8;

    for (int kt = 0; kt <= qt; kt++) {
        const int buf = kt & 1;
        if (kt < qt) {
            load_qk(baseK, (kt + 1) * 128, KS_OFF + (buf ^ 1) * 8192);
            load_vt(kt + 1, VT_OFF + (buf ^ 1) * 8192);
        }
        cp_commit();
        cp_wait<1>();
        __syncthreads();

        // ---- S = Q @ K^T ----
        const __half* Ks = sa + KS_OFF + buf * 8192;
        float c[16][4];
        #pragma unroll
        for (int nt = 0; nt < 16; nt++)
            #pragma unroll
            for (int r = 0; r < 4; r++) c[nt][r] = 0.f;

        #pragma unroll
        for (int s = 0; s < 4; s++) {
            const uint2 qa = *(const uint2*)(sa + QS_OFF + ((s * 128 + wm + lr) << 4) + 4 * lc);
            const uint2 qb = *(const uint2*)(sa + QS_OFF + ((s * 128 + wm + lr + 8) << 4) + 4 * lc);
            #pragma unroll
            for (int nt = 0; nt < 16; nt++) {
                const uint2 kb2 = *(const uint2*)(Ks + ((s * 128 + nt * 8 + lr) << 4) + 4 * lc);
                mma_f16(c[nt][0], c[nt][1], c[nt][2], c[nt][3],
                        qa.x, qb.x, qa.y, qb.y, kb2.x, kb2.y);
            }
        }

        // ---- ALiBi + (diagonal-only) mask + online softmax ----
        const int kb = kt * 128 + 2 * lc;
        {
            float al0 = slope * (float)(kb - qrow0);
            float al1 = slope * (float)(kb - qrow1);
            const float st8 = 8.f * slope;
            float mx0 = -1e30f, mx1 = -1e30f;
            #pragma unroll
            for (int nt = 0; nt < 16; nt++) {
                float s0 = c[nt][0] + al0;
                float s1 = c[nt][1] + al0 + slope;
                float s2 = c[nt][2] + al1;
                float s3 = c[nt][3] + al1 + slope;
                if (kt == qt) {
                    const int k0c = kb + nt * 8, k1c = k0c + 1;
                    if (k0c > qrow0) s0 = -1e30f;
                    if (k1c > qrow0) s1 = -1e30f;
                    if (k0c > qrow1) s2 = -1e30f;
                    if (k1c > qrow1) s3 = -1e30f;
                }
                c[nt][0] = s0; c[nt][1] = s1; c[nt][2] = s2; c[nt][3] = s3;
                mx0 = fmaxf(mx0, fmaxf(s0, s1));
                mx1 = fmaxf(mx1, fmaxf(s2, s3));
                al0 += st8; al1 += st8;
            }
            mx0 = fmaxf(mx0, __shfl_xor_sync(0xffffffffu, mx0, 1));
            mx0 = fmaxf(mx0, __shfl_xor_sync(0xffffffffu, mx0, 2));
            mx1 = fmaxf(mx1, __shfl_xor_sync(0xffffffffu, mx1, 1));
            mx1 = fmaxf(mx1, __shfl_xor_sync(0xffffffffu, mx1, 2));

            const float mn0 = fmaxf(m0, mx0), mn1 = fmaxf(m1, mx1);
            const float corr0 = fexp2((m0 - mn0) * L2E);
            const float corr1 = fexp2((m1 - mn1) * L2E);
            m0 = mn0; m1 = mn1;

            float ts0 = 0.f, ts1 = 0.f;
            __half* prow0 = sa + PS_OFF + (wm + lr) * 16 + 4 * lc;
            __half* prow1 = prow0 + 8 * 16;
            #pragma unroll
            for (int nt = 0; nt < 16; nt++) {
                const float e0 = fexp2((c[nt][0] - mn0) * L2E);
                const float e1 = fexp2((c[nt][1] - mn0) * L2E);
                const float e2 = fexp2((c[nt][2] - mn1) * L2E);
                const float e3 = fexp2((c[nt][3] - mn1) * L2E);
                ts0 += e0 + e1;
                ts1 += e2 + e3;
                const int po = (nt >> 1) * 2048 + 2 * (nt & 1);
                *(__half2*)(prow0 + po) = __floats2half2_rn(e0, e1);
                *(__half2*)(prow1 + po) = __floats2half2_rn(e2, e3);
            }
            ts0 += __shfl_xor_sync(0xffffffffu, ts0, 1);
            ts0 += __shfl_xor_sync(0xffffffffu, ts0, 2);
            ts1 += __shfl_xor_sync(0xffffffffu, ts1, 1);
            ts1 += __shfl_xor_sync(0xffffffffu, ts1, 2);
            l0 = l0 * corr0 + ts0;
            l1 = l1 * corr1 + ts1;
            #pragma unroll
            for (int i = 0; i < 8; i++) {
                o[i][0] *= corr0; o[i][1] *= corr0;
                o[i][2] *= corr1; o[i][3] *= corr1;
            }
        }
        __syncthreads();       // P visible to all warps

        // ---- O += P @ V ----
        const __half* Vs = sa + VT_OFF + buf * 8192;
        #pragma unroll
        for (int s = 0; s < 8; s++) {
            const uint2 pa = *(const uint2*)(sa + PS_OFF + ((s * 128 + wm + lr) << 4) + 4 * lc);
            const uint2 pb = *(const uint2*)(sa + PS_OFF + ((s * 128 + wm + lr + 8) << 4) + 4 * lc);
            #pragma unroll
            for (int nt2 = 0; nt2 < 8; nt2++) {
                const uint2 vb = *(const uint2*)(Vs + ((s * 64 + nt2 * 8 + lr) << 4) + 4 * lc);
                mma_f16(o[nt2][0], o[nt2][1], o[nt2][2], o[nt2][3],
                        pa.x, pb.x, pa.y, pb.y, vb.x, vb.y);
            }
        }
        __syncthreads();       // all reads of KS/VT[buf] + PS done before reuse
    }

    // ---- epilogue: normalize, write k-permuted half2 (feeds GEMM2) ----
    const float inv0 = 1.f / l0, inv1 = 1.f / l1;
    __half* og = out + ((size_t)b * SEQ + qrow0) * 1024 + h * 64;
    #pragma unroll
    for (int nt2 = 0; nt2 < 8; nt2++) {
        const int col = nt2 * 8 + 2 * lc;                       // 0..63 within head
        const int cp2 = (col & ~15) + perm16h(col & 15);
        *(__half2*)(og + cp2) = __floats2half2_rn(o[nt2][0] * inv0, o[nt2][1] * inv0);
        *(__half2*)(og + 8 * 1024 + cp2) = __floats2half2_rn(o[nt2][2] * inv1, o[nt2][3] * inv1);
    }
}

// ---------------------------------------------------------------------------
extern "C" void kernel_launch(void* const* d_in, const int* in_sizes, int n_in,
                              void* d_out, int out_size)
{
    const float* x    = (const float*)d_in[0];
    // d_in[1] = mask (bool tril) — causality handled analytically
    const float* Wqkv = (const float*)d_in[2];
    const float* bqkv = (const float*)d_in[3];
    const float* Wout = (const float*)d_in[4];
    const float* bout = (const float*)d_in[5];
    float* out = (float*)d_out;

    __half *qk_p, *vt_p, *att_p, *xc_p, *wqt_p, *wot_p;
    cudaGetSymbolAddress((void**)&qk_p,  g_qk);
    cudaGetSymbolAddress((void**)&vt_p,  g_vt);
    cudaGetSymbolAddress((void**)&att_p, g_att);
    cudaGetSymbolAddress((void**)&xc_p,  g_xc);
    cudaGetSymbolAddress((void**)&wqt_p, g_wqt);
    cudaGetSymbolAddress((void**)&wot_p, g_wot);

    cudaFuncSetAttribute(gemm_f16_kernel,
                         cudaFuncAttributeMaxDynamicSharedMemorySize, GEMM_SMEM);
    cudaFuncSetAttribute(attn_f16_kernel,
                         cudaFuncAttributeMaxDynamicSharedMemorySize, ATT_SMEM);

    // 0) fp16 + pair-permute operands
    {
        const int ng = MROWS * EMB / 16;
        convert_half_perm_kernel<<<ng / 256, 256>>>(x, xc_p, ng);
    }
    transpose_half_perm_kernel<<<dim3(3 * EMB / 32, EMB / 32), dim3(32, 8)>>>(Wqkv, wqt_p, EMB, 3 * EMB);
    transpose_half_perm_kernel<<<dim3(EMB / 32, EMB / 32),     dim3(32, 8)>>>(Wout, wot_p, EMB, EMB);

    // 1) qkv = x @ W_qkv + b_qkv; q scaled+d-permuted, k d-permuted, v transposed
    gemm_f16_kernel<<<dim3(3 * EMB / 128, MROWS / 128), 256, GEMM_SMEM>>>(
        xc_p, wqt_p, bqkv, nullptr, MROWS, 3 * EMB, EMB, 1);

    // 2) attention (fp16 mma.sync, causal + ALiBi, double-buffered K/V)
    attn_f16_kernel<<<dim3(SEQ / 128, HEADS, BATCH), 256, ATT_SMEM>>>(qk_p, vt_p, att_p);

    // 3) out = att @ W_out + b_out (fp32 natural output)
    gemm_f16_kernel<<<dim3(EMB / 128, MROWS / 128), 256, GEMM_SMEM>>>(
        att_p, wot_p, bout, out, MROWS, EMB, EMB, 0);
}

// round 11
// speedup vs baseline: 1.7751x; 1.0102x over previous
#include <cuda_runtime.h>
#include <cuda_fp16.h>
#include <cstdint>
#include <math.h>

#define BATCH 4
#define SEQ   2048
#define EMB   1024
#define HEADS 16
#define HDIM  64
#define MROWS (BATCH*SEQ)   /* 8192 */
#define L2E   1.4426950408889634f

// Pair-permute within 16-half groups: pair p -> pos (p<4 ? 2p : 2(p-4)+1).
// Thread lc's two fragment pairs (lc, lc+4) land adjacent -> one LDS.64.

// Scratch (device globals: allocation-free per harness rules)
__device__ __align__(16) __half g_qk [(size_t)MROWS * 2 * EMB];          // q|k, d-permuted, q scaled
__device__ __align__(16) __half g_vt [(size_t)BATCH * HEADS * HDIM * SEQ]; // V^T, seq-permuted
__device__ __align__(16) __half g_att[(size_t)MROWS * EMB];              // attn out, k-permuted
__device__ __align__(16) __half g_xc [(size_t)MROWS * EMB];              // x, k-permuted
__device__ __align__(16) __half g_wqt[(size_t)3 * EMB * EMB];            // W_qkv^T, k-permuted
__device__ __align__(16) __half g_wot[(size_t)EMB * EMB];                // W_out^T, k-permuted

// ---------------------------------------------------------------------------
// helpers (portable PTX only)
// ---------------------------------------------------------------------------
__device__ __forceinline__ uint32_t smem_u32(const void* p) {
    uint32_t a;
    asm("{ .reg .u64 t; cvta.to.shared.u64 t, %1; cvt.u32.u64 %0, t; }" : "=r"(a) : "l"(p));
    return a;
}
__device__ __forceinline__ float fexp2(float x) {
    float y;
    asm("ex2.approx.f32 %0, %1;" : "=f"(y) : "f"(x));
    return y;
}
__device__ __forceinline__ void cp_async16(uint32_t dst, const void* src) {
    asm volatile("cp.async.cg.shared.global [%0], [%1], 16;" :: "r"(dst), "l"(src));
}
__device__ __forceinline__ void cp_commit() {
    asm volatile("cp.async.commit_group;" ::: "memory");
}
template <int N>
__device__ __forceinline__ void cp_wait() {
    asm volatile("cp.async.wait_group %0;" :: "n"(N) : "memory");
}
__device__ __forceinline__ void mma_f16(float& c0, float& c1, float& c2, float& c3,
                                        uint32_t a0, uint32_t a1, uint32_t a2, uint32_t a3,
                                        uint32_t b0, uint32_t b1) {
    asm volatile(
        "mma.sync.aligned.m16n8k16.row.col.f32.f16.f16.f32 "
        "{%0,%1,%2,%3}, {%4,%5,%6,%7}, {%8,%9}, {%0,%1,%2,%3};"
        : "+f"(c0), "+f"(c1), "+f"(c2), "+f"(c3)
        : "r"(a0), "r"(a1), "r"(a2), "r"(a3), "r"(b0), "r"(b1));
}
__device__ __forceinline__ int perm16h(int j) {   // half index j (0..15) -> permuted pos
    const int p = j >> 1;
    return ((p < 4) ? 4 * p : 4 * p - 14) + (j & 1);
}

// ---------------------------------------------------------------------------
// fp32 -> fp16, pair-permuted per 16-half group (one thread per group)
// ---------------------------------------------------------------------------
__global__ void convert_half_perm_kernel(const float* __restrict__ src,
                                         __half* __restrict__ dst, int ngroups) {
    int g = blockIdx.x * blockDim.x + threadIdx.x;
    if (g >= ngroups) return;
    const float* s = src + (size_t)g * 16;
    __half2 o[8];
    #pragma unroll
    for (int pp = 0; pp < 8; pp++) {
        const int p = (pp & 1) ? ((pp >> 1) + 4) : (pp >> 1);
        o[pp] = __floats2half2_rn(s[2 * p], s[2 * p + 1]);
    }
    *(uint4*)(dst + (size_t)g * 16)     = *(uint4*)(o);
    *(uint4*)(dst + (size_t)g * 16 + 8) = *(uint4*)(o + 4);
}

// ---------------------------------------------------------------------------
// transpose + fp16 + pair-permute: Wt[n][perm(k)] = h(W[k][n])
// ---------------------------------------------------------------------------
__global__ void transpose_half_perm_kernel(const float* __restrict__ W,
                                           __half* __restrict__ Wt, int K, int N) {
    __shared__ float t[32][33];
    const int n0 = blockIdx.x * 32, k0 = blockIdx.y * 32;
    const int x = threadIdx.x, y = threadIdx.y;  // 32 x 8
    #pragma unroll
    for (int i = 0; i < 4; i++)
        t[y + i * 8][x] = W[(size_t)(k0 + y + i * 8) * N + n0 + x];
    __syncthreads();
    const int px = (x & 16) + perm16h(x & 15);
    #pragma unroll
    for (int i = 0; i < 4; i++)
        Wt[(size_t)(n0 + y + i * 8) * K + k0 + px] = __float2half_rn(t[x][y + i * 8]);
}

// ---------------------------------------------------------------------------
// fp16 mma.sync GEMM: C[M,N] = A[M,K] @ Bt[N,K]^T + bias[N]
// A, Bt half, pair-permuted. 128x128 CTA, 4 warps (2x2), warp tile 64x64:
// 16 LDS.64 per 32 MMAs (0.5 loads/MMA). 128 threads, 2 CTAs/SM. BK=64.
// smem tiles [4 k16][128][16 halfs] -- conflict-free STS(cp.async) and LDS.64.
// mode=1: q cols scaled 0.125; q,k -> g_qk (d-permuted half2);
//         v -> g_vt transposed (seq-permuted). mode=0: fp32 natural + bias.
// ---------------------------------------------------------------------------
#define BKH 64
#define TILE_HALFS (4 * 128 * 16)     /* 8192 */
#define STAGE_HALFS (2 * TILE_HALFS)
#define NSTAGE 3
#define GEMM_SMEM (NSTAGE * STAGE_HALFS * 2)   /* 98304 B */

__global__ __launch_bounds__(128, 2)
void gemm_f16_kernel(const __half* __restrict__ A, const __half* __restrict__ Bt,
                     const float* __restrict__ bias, float* __restrict__ Cf,
                     int M, int N, int K, int mode)
{
    extern __shared__ __align__(16) __half sh[];

    const int tid  = threadIdx.x;
    const int wid  = tid >> 5;
    const int lane = tid & 31;
    const int wm   = (wid >> 1) * 64;   // 2 warps down M
    const int wn   = (wid & 1) * 64;    // 2 warps across N
    const int lr   = lane >> 2;
    const int lc   = lane & 3;
    const int n0   = blockIdx.x * 128;
    const int m0   = blockIdx.y * 128;
    const uint32_t smb = smem_u32(sh);

    float c[4][8][4];                   // [mt][nt][reg]
    #pragma unroll
    for (int i = 0; i < 4; i++)
        #pragma unroll
        for (int j = 0; j < 8; j++)
            #pragma unroll
            for (int r = 0; r < 4; r++) c[i][j][r] = 0.f;

    auto load_stage = [&](int ch, int s) {
        const __half* Ab = A  + (size_t)m0 * K + ch * BKH;
        const __half* Bb = Bt + (size_t)n0 * K + ch * BKH;
        const uint32_t sA = smb + (uint32_t)(s * STAGE_HALFS) * 2u;
        const uint32_t sB = sA + TILE_HALFS * 2u;
        #pragma unroll
        for (int i = 0; i < 8; i++) {
            const int chk = i * 128 + tid;            // 0..1023
            const int hh = chk & 1, row = (chk >> 1) & 127, ss = chk >> 8;
            const uint32_t off = (uint32_t)(((ss * 128 + row) * 16 + hh * 8) * 2);
            const size_t gofs = (size_t)row * K + ss * 16 + hh * 8;
            cp_async16(sA + off, Ab + gofs);
            cp_async16(sB + off, Bb + gofs);
        }
    };

    const int NCH = K / BKH;

    load_stage(0, 0); cp_commit();
    load_stage(1, 1); cp_commit();

    for (int ch = 0; ch < NCH; ch++) {
        cp_wait<1>();
        __syncthreads();
        if (ch + 2 < NCH) load_stage(ch + 2, (ch + 2) % NSTAGE);
        cp_commit();

        const __half* As = sh + (ch % NSTAGE) * STAGE_HALFS;
        const __half* Bs = As + TILE_HALFS;

        #pragma unroll
        for (int s = 0; s < 4; s++) {
            uint2 af[4][2];
            uint2 bf[8];
            #pragma unroll
            for (int mt = 0; mt < 4; mt++) {
                af[mt][0] = *(const uint2*)(As + ((s * 128 + wm + mt * 16 + lr) << 4) + 4 * lc);
                af[mt][1] = *(const uint2*)(As + ((s * 128 + wm + mt * 16 + lr + 8) << 4) + 4 * lc);
            }
            #pragma unroll
            for (int nt = 0; nt < 8; nt++)
                bf[nt] = *(const uint2*)(Bs + ((s * 128 + wn + nt * 8 + lr) << 4) + 4 * lc);
            #pragma unroll
            for (int mt = 0; mt < 4; mt++)
                #pragma unroll
                for (int nt = 0; nt < 8; nt++)
                    mma_f16(c[mt][nt][0], c[mt][nt][1], c[mt][nt][2], c[mt][nt][3],
                            af[mt][0].x, af[mt][1].x, af[mt][0].y, af[mt][1].y,
                            bf[nt].x, bf[nt].y);
        }
        __syncthreads();
    }

    if (mode == 1) {
        const int region = n0 >> 10;               // 0=q, 1=k, 2=v
        const float sc = (region == 0) ? 0.125f : 1.0f;
        #pragma unroll
        for (int nt = 0; nt < 8; nt++) {
            const int col = n0 + wn + nt * 8 + 2 * lc;
            const float b0v = bias[col], b1v = bias[col + 1];
            #pragma unroll
            for (int mt = 0; mt < 4; mt++) {
                const int r0 = m0 + wm + mt * 16 + lr;
                const float v0 = (c[mt][nt][0] + b0v) * sc;
                const float v1 = (c[mt][nt][1] + b1v) * sc;
                const float v2 = (c[mt][nt][2] + b0v) * sc;
                const float v3 = (c[mt][nt][3] + b1v) * sc;
                if (region < 2) {
                    const int cp2 = (col & ~15) + perm16h(col & 15);
                    *(__half2*)(&g_qk[(size_t)r0 * 2048 + cp2])       = __floats2half2_rn(v0, v1);
                    *(__half2*)(&g_qk[(size_t)(r0 + 8) * 2048 + cp2]) = __floats2half2_rn(v2, v3);
                } else {
                    const int d = col - 2048, hh = d >> 6, dd = d & 63;
                    const int bb = r0 >> 11, seq = r0 & 2047;
                    const int sg = seq & ~15, sj = seq & 15;
                    const int sp  = sg + perm16h(sj);
                    const int sp8 = sg + perm16h(sj + 8);
                    __half* vb = g_vt + ((size_t)(bb * HEADS + hh) * 64 + dd) * 2048;
                    vb[sp]  = __float2half_rn(v0);
                    vb[sp8] = __float2half_rn(v2);
                    vb += 2048;                    // dd+1
                    vb[sp]  = __float2half_rn(v1);
                    vb[sp8] = __float2half_rn(v3);
                }
            }
        }
    } else {
        #pragma unroll
        for (int nt = 0; nt < 8; nt++) {
            const int col = n0 + wn + nt * 8 + 2 * lc;
            const float b0v = bias[col], b1v = bias[col + 1];
            #pragma unroll
            for (int mt = 0; mt < 4; mt++) {
                const size_t r0 = (size_t)(m0 + wm + mt * 16 + lr);
                *(float2*)(&Cf[r0 * N + col]) =
                    make_float2(c[mt][nt][0] + b0v, c[mt][nt][1] + b1v);
                *(float2*)(&Cf[(r0 + 8) * N + col]) =
                    make_float2(c[mt][nt][2] + b0v, c[mt][nt][3] + b1v);
            }
        }
    }
}

// ---------------------------------------------------------------------------
// Flash attention, fp16 mma.sync m16n8k16 (unchanged from R10).
// ---------------------------------------------------------------------------
#define QS_OFF 0
#define KS_OFF 8192
#define VT_OFF 24576
#define PS_OFF 40960
#define ATT_SMEM ((40960 + 16384) * 2)   /* 114688 B */

__global__ __launch_bounds__(256, 1)
void attn_f16_kernel(const __half* __restrict__ qk, const __half* __restrict__ vt,
                     __half* __restrict__ out)
{
    extern __shared__ __align__(16) __half sa[];

    const int tid  = threadIdx.x;
    const int wid  = tid >> 5;
    const int lane = tid & 31;
    const int lr   = lane >> 2;
    const int lc   = lane & 3;
    const int wm   = wid * 16;
    const int qt   = blockIdx.x;
    const int h    = blockIdx.y;
    const int b    = blockIdx.z;
    const int q0   = qt * 128;
    const float slope = fexp2(-0.5f * (float)(h + 1));
    const uint32_t smb = smem_u32(sa);

    const __half* baseQ = qk + (size_t)b * SEQ * 2048 + h * 64;
    const __half* baseK = baseQ + 1024;
    const __half* baseV = vt + (size_t)(b * HEADS + h) * 64 * 2048;

    auto load_qk = [&](const __half* g, int row0, int soff) {   // [4][128][16]
        #pragma unroll
        for (int i = 0; i < 4; i++) {
            const int chk = i * 256 + tid;
            const int hh = chk & 1, row = (chk >> 1) & 127, ss = chk >> 8;
            cp_async16(smb + (uint32_t)((soff + (ss * 128 + row) * 16 + hh * 8) * 2),
                       g + (size_t)(row0 + row) * 2048 + ss * 16 + hh * 8);
        }
    };
    auto load_vt = [&](int kt, int soff) {                      // [8][64][16]
        #pragma unroll
        for (int i = 0; i < 4; i++) {
            const int chk = i * 256 + tid;
            const int hh = chk & 1, d = (chk >> 1) & 63, ss = chk >> 7;
            cp_async16(smb + (uint32_t)((soff + (ss * 64 + d) * 16 + hh * 8) * 2),
                       baseV + (size_t)d * 2048 + kt * 128 + ss * 16 + hh * 8);
        }
    };

    load_qk(baseQ, q0, QS_OFF);
    load_qk(baseK, 0, KS_OFF);
    load_vt(0, VT_OFF);
    cp_commit();

    float m0 = -1e30f, m1 = -1e30f, l0 = 0.f, l1 = 0.f;
    float o[8][4];
    #pragma unroll
    for (int i = 0; i < 8; i++)
        #pragma unroll
        for (int r = 0; r < 4; r++) o[i][r] = 0.f;

    const int qrow0 = q0 + wm + lr;
    const int qrow1 = qrow0 + 8;

    for (int kt = 0; kt <= qt; kt++) {
        const int buf = kt & 1;
        if (kt < qt) {
            load_qk(baseK, (kt + 1) * 128, KS_OFF + (buf ^ 1) * 8192);
            load_vt(kt + 1, VT_OFF + (buf ^ 1) * 8192);
        }
        cp_commit();
        cp_wait<1>();
        __syncthreads();

        // ---- S = Q @ K^T ----
        const __half* Ks = sa + KS_OFF + buf * 8192;
        float c[16][4];
        #pragma unroll
        for (int nt = 0; nt < 16; nt++)
            #pragma unroll
            for (int r = 0; r < 4; r++) c[nt][r] = 0.f;

        #pragma unroll
        for (int s = 0; s < 4; s++) {
            const uint2 qa = *(const uint2*)(sa + QS_OFF + ((s * 128 + wm + lr) << 4) + 4 * lc);
            const uint2 qb = *(const uint2*)(sa + QS_OFF + ((s * 128 + wm + lr + 8) << 4) + 4 * lc);
            #pragma unroll
            for (int nt = 0; nt < 16; nt++) {
                const uint2 kb2 = *(const uint2*)(Ks + ((s * 128 + nt * 8 + lr) << 4) + 4 * lc);
                mma_f16(c[nt][0], c[nt][1], c[nt][2], c[nt][3],
                        qa.x, qb.x, qa.y, qb.y, kb2.x, kb2.y);
            }
        }

        // ---- ALiBi + (diagonal-only) mask + online softmax ----
        const int kb = kt * 128 + 2 * lc;
        {
            float al0 = slope * (float)(kb - qrow0);
            float al1 = slope * (float)(kb - qrow1);
            const float st8 = 8.f * slope;
            float mx0 = -1e30f, mx1 = -1e30f;
            #pragma unroll
            for (int nt = 0; nt < 16; nt++) {
                float s0 = c[nt][0] + al0;
                float s1 = c[nt][1] + al0 + slope;
                float s2 = c[nt][2] + al1;
                float s3 = c[nt][3] + al1 + slope;
                if (kt == qt) {
                    const int k0c = kb + nt * 8, k1c = k0c + 1;
                    if (k0c > qrow0) s0 = -1e30f;
                    if (k1c > qrow0) s1 = -1e30f;
                    if (k0c > qrow1) s2 = -1e30f;
                    if (k1c > qrow1) s3 = -1e30f;
                }
                c[nt][0] = s0; c[nt][1] = s1; c[nt][2] = s2; c[nt][3] = s3;
                mx0 = fmaxf(mx0, fmaxf(s0, s1));
                mx1 = fmaxf(mx1, fmaxf(s2, s3));
                al0 += st8; al1 += st8;
            }
            mx0 = fmaxf(mx0, __shfl_xor_sync(0xffffffffu, mx0, 1));
            mx0 = fmaxf(mx0, __shfl_xor_sync(0xffffffffu, mx0, 2));
            mx1 = fmaxf(mx1, __shfl_xor_sync(0xffffffffu, mx1, 1));
            mx1 = fmaxf(mx1, __shfl_xor_sync(0xffffffffu, mx1, 2));

            const float mn0 = fmaxf(m0, mx0), mn1 = fmaxf(m1, mx1);
            const float corr0 = fexp2((m0 - mn0) * L2E);
            const float corr1 = fexp2((m1 - mn1) * L2E);
            m0 = mn0; m1 = mn1;

            float ts0 = 0.f, ts1 = 0.f;
            __half* prow0 = sa + PS_OFF + (wm + lr) * 16 + 4 * lc;
            __half* prow1 = prow0 + 8 * 16;
            #pragma unroll
            for (int nt = 0; nt < 16; nt++) {
                const float e0 = fexp2((c[nt][0] - mn0) * L2E);
                const float e1 = fexp2((c[nt][1] - mn0) * L2E);
                const float e2 = fexp2((c[nt][2] - mn1) * L2E);
                const float e3 = fexp2((c[nt][3] - mn1) * L2E);
                ts0 += e0 + e1;
                ts1 += e2 + e3;
                const int po = (nt >> 1) * 2048 + 2 * (nt & 1);
                *(__half2*)(prow0 + po) = __floats2half2_rn(e0, e1);
                *(__half2*)(prow1 + po) = __floats2half2_rn(e2, e3);
            }
            ts0 += __shfl_xor_sync(0xffffffffu, ts0, 1);
            ts0 += __shfl_xor_sync(0xffffffffu, ts0, 2);
            ts1 += __shfl_xor_sync(0xffffffffu, ts1, 1);
            ts1 += __shfl_xor_sync(0xffffffffu, ts1, 2);
            l0 = l0 * corr0 + ts0;
            l1 = l1 * corr1 + ts1;
            #pragma unroll
            for (int i = 0; i < 8; i++) {
                o[i][0] *= corr0; o[i][1] *= corr0;
                o[i][2] *= corr1; o[i][3] *= corr1;
            }
        }
        __syncthreads();       // P visible to all warps

        // ---- O += P @ V ----
        const __half* Vs = sa + VT_OFF + buf * 8192;
        #pragma unroll
        for (int s = 0; s < 8; s++) {
            const uint2 pa = *(const uint2*)(sa + PS_OFF + ((s * 128 + wm + lr) << 4) + 4 * lc);
            const uint2 pb = *(const uint2*)(sa + PS_OFF + ((s * 128 + wm + lr + 8) << 4) + 4 * lc);
            #pragma unroll
            for (int nt2 = 0; nt2 < 8; nt2++) {
                const uint2 vb = *(const uint2*)(Vs + ((s * 64 + nt2 * 8 + lr) << 4) + 4 * lc);
                mma_f16(o[nt2][0], o[nt2][1], o[nt2][2], o[nt2][3],
                        pa.x, pb.x, pa.y, pb.y, vb.x, vb.y);
            }
        }
        __syncthreads();       // all reads of KS/VT[buf] + PS done before reuse
    }

    // ---- epilogue: normalize, write k-permuted half2 (feeds GEMM2) ----
    const float inv0 = 1.f / l0, inv1 = 1.f / l1;
    __half* og = out + ((size_t)b * SEQ + qrow0) * 1024 + h * 64;
    #pragma unroll
    for (int nt2 = 0; nt2 < 8; nt2++) {
        const int col = nt2 * 8 + 2 * lc;                       // 0..63 within head
        const int cp2 = (col & ~15) + perm16h(col & 15);
        *(__half2*)(og + cp2) = __floats2half2_rn(o[nt2][0] * inv0, o[nt2][1] * inv0);
        *(__half2*)(og + 8 * 1024 + cp2) = __floats2half2_rn(o[nt2][2] * inv1, o[nt2][3] * inv1);
    }
}

// ---------------------------------------------------------------------------
extern "C" void kernel_launch(void* const* d_in, const int* in_sizes, int n_in,
                              void* d_out, int out_size)
{
    const float* x    = (const float*)d_in[0];
    // d_in[1] = mask (bool tril) — causality handled analytically
    const float* Wqkv = (const float*)d_in[2];
    const float* bqkv = (const float*)d_in[3];
    const float* Wout = (const float*)d_in[4];
    const float* bout = (const float*)d_in[5];
    float* out = (float*)d_out;

    __half *qk_p, *vt_p, *att_p, *xc_p, *wqt_p, *wot_p;
    cudaGetSymbolAddress((void**)&qk_p,  g_qk);
    cudaGetSymbolAddress((void**)&vt_p,  g_vt);
    cudaGetSymbolAddress((void**)&att_p, g_att);
    cudaGetSymbolAddress((void**)&xc_p,  g_xc);
    cudaGetSymbolAddress((void**)&wqt_p, g_wqt);
    cudaGetSymbolAddress((void**)&wot_p, g_wot);

    cudaFuncSetAttribute(gemm_f16_kernel,
                         cudaFuncAttributeMaxDynamicSharedMemorySize, GEMM_SMEM);
    cudaFuncSetAttribute(attn_f16_kernel,
                         cudaFuncAttributeMaxDynamicSharedMemorySize, ATT_SMEM);

    // 0) fp16 + pair-permute operands
    {
        const int ng = MROWS * EMB / 16;
        convert_half_perm_kernel<<<ng / 256, 256>>>(x, xc_p, ng);
    }
    transpose_half_perm_kernel<<<dim3(3 * EMB / 32, EMB / 32), dim3(32, 8)>>>(Wqkv, wqt_p, EMB, 3 * EMB);
    transpose_half_perm_kernel<<<dim3(EMB / 32, EMB / 32),     dim3(32, 8)>>>(Wout, wot_p, EMB, EMB);

    // 1) qkv = x @ W_qkv + b_qkv; q scaled+d-permuted, k d-permuted, v transposed
    gemm_f16_kernel<<<dim3(3 * EMB / 128, MROWS / 128), 128, GEMM_SMEM>>>(
        xc_p, wqt_p, bqkv, nullptr, MROWS, 3 * EMB, EMB, 1);

    // 2) attention (fp16 mma.sync, causal + ALiBi, double-buffered K/V)
    attn_f16_kernel<<<dim3(SEQ / 128, HEADS, BATCH), 256, ATT_SMEM>>>(qk_p, vt_p, att_p);

    // 3) out = att @ W_out + b_out (fp32 natural output)
    gemm_f16_kernel<<<dim3(EMB / 128, MROWS / 128), 128, GEMM_SMEM>>>(
        att_p, wot_p, bout, out, MROWS, EMB, EMB, 0);
}

// round 12
// speedup vs baseline: 1.8020x; 1.0152x over previous
#include <cuda_runtime.h>
#include <cuda_fp16.h>
#include <cstdint>
#include <math.h>

#define BATCH 4
#define SEQ   2048
#define EMB   1024
#define HEADS 16
#define HDIM  64
#define MROWS (BATCH*SEQ)   /* 8192 */
#define L2E   1.4426950408889634f

// Pair-permute within 16-half groups: pair p -> pos (p<4 ? 2p : 2(p-4)+1).
// Thread lc's two fragment pairs (lc, lc+4) land adjacent -> one LDS.64.

// Scratch (device globals: allocation-free per harness rules)
__device__ __align__(16) __half g_qk [(size_t)MROWS * 2 * EMB];          // q|k, d-permuted, q scaled
__device__ __align__(16) __half g_vt [(size_t)BATCH * HEADS * HDIM * SEQ]; // V^T, seq-permuted
__device__ __align__(16) __half g_att[(size_t)MROWS * EMB];              // attn out, k-permuted
__device__ __align__(16) __half g_xc [(size_t)MROWS * EMB];              // x, k-permuted
__device__ __align__(16) __half g_wqt[(size_t)3 * EMB * EMB];            // W_qkv^T, k-permuted
__device__ __align__(16) __half g_wot[(size_t)EMB * EMB];                // W_out^T, k-permuted

// ---------------------------------------------------------------------------
// helpers (portable PTX only)
// ---------------------------------------------------------------------------
__device__ __forceinline__ uint32_t smem_u32(const void* p) {
    uint32_t a;
    asm("{ .reg .u64 t; cvta.to.shared.u64 t, %1; cvt.u32.u64 %0, t; }" : "=r"(a) : "l"(p));
    return a;
}
__device__ __forceinline__ float fexp2(float x) {
    float y;
    asm("ex2.approx.f32 %0, %1;" : "=f"(y) : "f"(x));
    return y;
}
__device__ __forceinline__ void cp_async16(uint32_t dst, const void* src) {
    asm volatile("cp.async.cg.shared.global [%0], [%1], 16;" :: "r"(dst), "l"(src));
}
__device__ __forceinline__ void cp_commit() {
    asm volatile("cp.async.commit_group;" ::: "memory");
}
template <int N>
__device__ __forceinline__ void cp_wait() {
    asm volatile("cp.async.wait_group %0;" :: "n"(N) : "memory");
}
__device__ __forceinline__ void mma_f16(float& c0, float& c1, float& c2, float& c3,
                                        uint32_t a0, uint32_t a1, uint32_t a2, uint32_t a3,
                                        uint32_t b0, uint32_t b1) {
    asm volatile(
        "mma.sync.aligned.m16n8k16.row.col.f32.f16.f16.f32 "
        "{%0,%1,%2,%3}, {%4,%5,%6,%7}, {%8,%9}, {%0,%1,%2,%3};"
        : "+f"(c0), "+f"(c1), "+f"(c2), "+f"(c3)
        : "r"(a0), "r"(a1), "r"(a2), "r"(a3), "r"(b0), "r"(b1));
}
__device__ __forceinline__ int perm16h(int j) {   // half index j (0..15) -> permuted pos
    const int p = j >> 1;
    return ((p < 4) ? 4 * p : 4 * p - 14) + (j & 1);
}

// ---------------------------------------------------------------------------
// fp32 -> fp16, pair-permuted per 16-half group (one thread per group)
// ---------------------------------------------------------------------------
__global__ void convert_half_perm_kernel(const float* __restrict__ src,
                                         __half* __restrict__ dst, int ngroups) {
    int g = blockIdx.x * blockDim.x + threadIdx.x;
    if (g >= ngroups) return;
    const float* s = src + (size_t)g * 16;
    __half2 o[8];
    #pragma unroll
    for (int pp = 0; pp < 8; pp++) {
        const int p = (pp & 1) ? ((pp >> 1) + 4) : (pp >> 1);
        o[pp] = __floats2half2_rn(s[2 * p], s[2 * p + 1]);
    }
    *(uint4*)(dst + (size_t)g * 16)     = *(uint4*)(o);
    *(uint4*)(dst + (size_t)g * 16 + 8) = *(uint4*)(o + 4);
}

// ---------------------------------------------------------------------------
// transpose + fp16 + pair-permute: Wt[n][perm(k)] = h(W[k][n])
// ---------------------------------------------------------------------------
__global__ void transpose_half_perm_kernel(const float* __restrict__ W,
                                           __half* __restrict__ Wt, int K, int N) {
    __shared__ float t[32][33];
    const int n0 = blockIdx.x * 32, k0 = blockIdx.y * 32;
    const int x = threadIdx.x, y = threadIdx.y;  // 32 x 8
    #pragma unroll
    for (int i = 0; i < 4; i++)
        t[y + i * 8][x] = W[(size_t)(k0 + y + i * 8) * N + n0 + x];
    __syncthreads();
    const int px = (x & 16) + perm16h(x & 15);
    #pragma unroll
    for (int i = 0; i < 4; i++)
        Wt[(size_t)(n0 + y + i * 8) * K + k0 + px] = __float2half_rn(t[x][y + i * 8]);
}

// ---------------------------------------------------------------------------
// fp16 mma.sync GEMM (unchanged from R11 — at the mma.sync rate ceiling).
// ---------------------------------------------------------------------------
#define BKH 64
#define TILE_HALFS (4 * 128 * 16)     /* 8192 */
#define STAGE_HALFS (2 * TILE_HALFS)
#define NSTAGE 3
#define GEMM_SMEM (NSTAGE * STAGE_HALFS * 2)   /* 98304 B */

__global__ __launch_bounds__(128, 2)
void gemm_f16_kernel(const __half* __restrict__ A, const __half* __restrict__ Bt,
                     const float* __restrict__ bias, float* __restrict__ Cf,
                     int M, int N, int K, int mode)
{
    extern __shared__ __align__(16) __half sh[];

    const int tid  = threadIdx.x;
    const int wid  = tid >> 5;
    const int lane = tid & 31;
    const int wm   = (wid >> 1) * 64;
    const int wn   = (wid & 1) * 64;
    const int lr   = lane >> 2;
    const int lc   = lane & 3;
    const int n0   = blockIdx.x * 128;
    const int m0   = blockIdx.y * 128;
    const uint32_t smb = smem_u32(sh);

    float c[4][8][4];
    #pragma unroll
    for (int i = 0; i < 4; i++)
        #pragma unroll
        for (int j = 0; j < 8; j++)
            #pragma unroll
            for (int r = 0; r < 4; r++) c[i][j][r] = 0.f;

    auto load_stage = [&](int ch, int s) {
        const __half* Ab = A  + (size_t)m0 * K + ch * BKH;
        const __half* Bb = Bt + (size_t)n0 * K + ch * BKH;
        const uint32_t sA = smb + (uint32_t)(s * STAGE_HALFS) * 2u;
        const uint32_t sB = sA + TILE_HALFS * 2u;
        #pragma unroll
        for (int i = 0; i < 8; i++) {
            const int chk = i * 128 + tid;
            const int hh = chk & 1, row = (chk >> 1) & 127, ss = chk >> 8;
            const uint32_t off = (uint32_t)(((ss * 128 + row) * 16 + hh * 8) * 2);
            const size_t gofs = (size_t)row * K + ss * 16 + hh * 8;
            cp_async16(sA + off, Ab + gofs);
            cp_async16(sB + off, Bb + gofs);
        }
    };

    const int NCH = K / BKH;

    load_stage(0, 0); cp_commit();
    load_stage(1, 1); cp_commit();

    for (int ch = 0; ch < NCH; ch++) {
        cp_wait<1>();
        __syncthreads();
        if (ch + 2 < NCH) load_stage(ch + 2, (ch + 2) % NSTAGE);
        cp_commit();

        const __half* As = sh + (ch % NSTAGE) * STAGE_HALFS;
        const __half* Bs = As + TILE_HALFS;

        #pragma unroll
        for (int s = 0; s < 4; s++) {
            uint2 af[4][2];
            uint2 bf[8];
            #pragma unroll
            for (int mt = 0; mt < 4; mt++) {
                af[mt][0] = *(const uint2*)(As + ((s * 128 + wm + mt * 16 + lr) << 4) + 4 * lc);
                af[mt][1] = *(const uint2*)(As + ((s * 128 + wm + mt * 16 + lr + 8) << 4) + 4 * lc);
            }
            #pragma unroll
            for (int nt = 0; nt < 8; nt++)
                bf[nt] = *(const uint2*)(Bs + ((s * 128 + wn + nt * 8 + lr) << 4) + 4 * lc);
            #pragma unroll
            for (int mt = 0; mt < 4; mt++)
                #pragma unroll
                for (int nt = 0; nt < 8; nt++)
                    mma_f16(c[mt][nt][0], c[mt][nt][1], c[mt][nt][2], c[mt][nt][3],
                            af[mt][0].x, af[mt][1].x, af[mt][0].y, af[mt][1].y,
                            bf[nt].x, bf[nt].y);
        }
        __syncthreads();
    }

    if (mode == 1) {
        const int region = n0 >> 10;               // 0=q, 1=k, 2=v
        const float sc = (region == 0) ? 0.125f : 1.0f;
        #pragma unroll
        for (int nt = 0; nt < 8; nt++) {
            const int col = n0 + wn + nt * 8 + 2 * lc;
            const float b0v = bias[col], b1v = bias[col + 1];
            #pragma unroll
            for (int mt = 0; mt < 4; mt++) {
                const int r0 = m0 + wm + mt * 16 + lr;
                const float v0 = (c[mt][nt][0] + b0v) * sc;
                const float v1 = (c[mt][nt][1] + b1v) * sc;
                const float v2 = (c[mt][nt][2] + b0v) * sc;
                const float v3 = (c[mt][nt][3] + b1v) * sc;
                if (region < 2) {
                    const int cp2 = (col & ~15) + perm16h(col & 15);
                    *(__half2*)(&g_qk[(size_t)r0 * 2048 + cp2])       = __floats2half2_rn(v0, v1);
                    *(__half2*)(&g_qk[(size_t)(r0 + 8) * 2048 + cp2]) = __floats2half2_rn(v2, v3);
                } else {
                    const int d = col - 2048, hh = d >> 6, dd = d & 63;
                    const int bb = r0 >> 11, seq = r0 & 2047;
                    const int sg = seq & ~15, sj = seq & 15;
                    const int sp  = sg + perm16h(sj);
                    const int sp8 = sg + perm16h(sj + 8);
                    __half* vb = g_vt + ((size_t)(bb * HEADS + hh) * 64 + dd) * 2048;
                    vb[sp]  = __float2half_rn(v0);
                    vb[sp8] = __float2half_rn(v2);
                    vb += 2048;                    // dd+1
                    vb[sp]  = __float2half_rn(v1);
                    vb[sp8] = __float2half_rn(v3);
                }
            }
        }
    } else {
        #pragma unroll
        for (int nt = 0; nt < 8; nt++) {
            const int col = n0 + wn + nt * 8 + 2 * lc;
            const float b0v = bias[col], b1v = bias[col + 1];
            #pragma unroll
            for (int mt = 0; mt < 4; mt++) {
                const size_t r0 = (size_t)(m0 + wm + mt * 16 + lr);
                *(float2*)(&Cf[r0 * N + col]) =
                    make_float2(c[mt][nt][0] + b0v, c[mt][nt][1] + b1v);
                *(float2*)(&Cf[(r0 + 8) * N + col]) =
                    make_float2(c[mt][nt][2] + b0v, c[mt][nt][3] + b1v);
            }
        }
    }
}

// ---------------------------------------------------------------------------
// Flash attention, fp16 mma.sync, 2 CTAs/SM.
// Q fragments hoisted to registers; Q smem aliased as the P buffer (each
// warp's P stays in its own 16-row band -> no barriers around softmax).
// KV tile processed as two 64-col halves (S -> softmax -> PV per half):
// peak regs ~115, smem 80KB. 2 barriers per KV tile.
// smem halfs: QP[4][128][16] | KS 2x[4][128][16] | VT 2x[8][64][16]
// ---------------------------------------------------------------------------
#define QP_OFF 0
#define KS_OFF 8192
#define VT_OFF 24576
#define ATT_SMEM ((24576 + 16384) * 2)   /* 81920 B */

__global__ __launch_bounds__(256, 2)
void attn_f16_kernel(const __half* __restrict__ qk, const __half* __restrict__ vt,
                     __half* __restrict__ out)
{
    extern __shared__ __align__(16) __half sa[];

    const int tid  = threadIdx.x;
    const int wid  = tid >> 5;
    const int lane = tid & 31;
    const int lr   = lane >> 2;
    const int lc   = lane & 3;
    const int wm   = wid * 16;
    const int qt   = blockIdx.x;
    const int h    = blockIdx.y;
    const int b    = blockIdx.z;
    const int q0   = qt * 128;
    const float slope = fexp2(-0.5f * (float)(h + 1));
    const uint32_t smb = smem_u32(sa);

    const __half* baseQ = qk + (size_t)b * SEQ * 2048 + h * 64;
    const __half* baseK = baseQ + 1024;
    const __half* baseV = vt + (size_t)(b * HEADS + h) * 64 * 2048;

    auto load_qk = [&](const __half* g, int row0, int soff) {   // [4][128][16]
        #pragma unroll
        for (int i = 0; i < 4; i++) {
            const int chk = i * 256 + tid;
            const int hh = chk & 1, row = (chk >> 1) & 127, ss = chk >> 8;
            cp_async16(smb + (uint32_t)((soff + (ss * 128 + row) * 16 + hh * 8) * 2),
                       g + (size_t)(row0 + row) * 2048 + ss * 16 + hh * 8);
        }
    };
    auto load_vt = [&](int kt, int soff) {                      // [8][64][16]
        #pragma unroll
        for (int i = 0; i < 4; i++) {
            const int chk = i * 256 + tid;
            const int hh = chk & 1, d = (chk >> 1) & 63, ss = chk >> 7;
            cp_async16(smb + (uint32_t)((soff + (ss * 64 + d) * 16 + hh * 8) * 2),
                       baseV + (size_t)d * 2048 + kt * 128 + ss * 16 + hh * 8);
        }
    };

    load_qk(baseQ, q0, QP_OFF);
    load_qk(baseK, 0, KS_OFF);
    load_vt(0, VT_OFF);
    cp_commit();

    uint2 qf[4][2];                      // Q fragments, hoisted at kt==0
    float m0 = -1e30f, m1 = -1e30f, l0 = 0.f, l1 = 0.f;
    float o[8][4];
    #pragma unroll
    for (int i = 0; i < 8; i++)
        #pragma unroll
        for (int r = 0; r < 4; r++) o[i][r] = 0.f;

    const int qrow0 = q0 + wm + lr;
    const int qrow1 = qrow0 + 8;

    for (int kt = 0; kt <= qt; kt++) {
        const int buf = kt & 1;
        if (kt < qt) {
            load_qk(baseK, (kt + 1) * 128, KS_OFF + (buf ^ 1) * 8192);
            load_vt(kt + 1, VT_OFF + (buf ^ 1) * 8192);
        }
        cp_commit();
        cp_wait<1>();
        __syncthreads();

        if (kt == 0) {                   // hoist Q fragments (own band only)
            #pragma unroll
            for (int s = 0; s < 4; s++) {
                qf[s][0] = *(const uint2*)(sa + QP_OFF + ((s * 128 + wm + lr) << 4) + 4 * lc);
                qf[s][1] = *(const uint2*)(sa + QP_OFF + ((s * 128 + wm + lr + 8) << 4) + 4 * lc);
            }
        }

        const __half* Ks = sa + KS_OFF + buf * 8192;
        const __half* Vs = sa + VT_OFF + buf * 8192;

        #pragma unroll
        for (int hf = 0; hf < 2; hf++) {
            // ---- S half: 128q x 64k ----
            float c[8][4];
            #pragma unroll
            for (int nt = 0; nt < 8; nt++)
                #pragma unroll
                for (int r = 0; r < 4; r++) c[nt][r] = 0.f;

            #pragma unroll
            for (int s = 0; s < 4; s++) {
                #pragma unroll
                for (int nt = 0; nt < 8; nt++) {
                    const uint2 kb2 = *(const uint2*)(Ks + ((s * 128 + hf * 64 + nt * 8 + lr) << 4) + 4 * lc);
                    mma_f16(c[nt][0], c[nt][1], c[nt][2], c[nt][3],
                            qf[s][0].x, qf[s][1].x, qf[s][0].y, qf[s][1].y,
                            kb2.x, kb2.y);
                }
            }

            // ---- ALiBi + (diagonal-only) mask + online softmax over 64 cols ----
            const int kb = kt * 128 + hf * 64 + 2 * lc;
            float al0 = slope * (float)(kb - qrow0);
            float al1 = slope * (float)(kb - qrow1);
            const float st8 = 8.f * slope;
            float mx0 = -1e30f, mx1 = -1e30f;
            #pragma unroll
            for (int nt = 0; nt < 8; nt++) {
                float s0 = c[nt][0] + al0;
                float s1 = c[nt][1] + al0 + slope;
                float s2 = c[nt][2] + al1;
                float s3 = c[nt][3] + al1 + slope;
                if (kt == qt) {
                    const int k0c = kb + nt * 8, k1c = k0c + 1;
                    if (k0c > qrow0) s0 = -1e30f;
                    if (k1c > qrow0) s1 = -1e30f;
                    if (k0c > qrow1) s2 = -1e30f;
                    if (k1c > qrow1) s3 = -1e30f;
                }
                c[nt][0] = s0; c[nt][1] = s1; c[nt][2] = s2; c[nt][3] = s3;
                mx0 = fmaxf(mx0, fmaxf(s0, s1));
                mx1 = fmaxf(mx1, fmaxf(s2, s3));
                al0 += st8; al1 += st8;
            }
            mx0 = fmaxf(mx0, __shfl_xor_sync(0xffffffffu, mx0, 1));
            mx0 = fmaxf(mx0, __shfl_xor_sync(0xffffffffu, mx0, 2));
            mx1 = fmaxf(mx1, __shfl_xor_sync(0xffffffffu, mx1, 1));
            mx1 = fmaxf(mx1, __shfl_xor_sync(0xffffffffu, mx1, 2));

            const float mn0 = fmaxf(m0, mx0), mn1 = fmaxf(m1, mx1);
            const float corr0 = fexp2((m0 - mn0) * L2E);
            const float corr1 = fexp2((m1 - mn1) * L2E);
            m0 = mn0; m1 = mn1;

            float ts0 = 0.f, ts1 = 0.f;
            __half* prow0 = sa + QP_OFF + (wm + lr) * 16 + 4 * lc;
            __half* prow1 = prow0 + 8 * 16;
            #pragma unroll
            for (int nt = 0; nt < 8; nt++) {
                const float e0 = fexp2((c[nt][0] - mn0) * L2E);
                const float e1 = fexp2((c[nt][1] - mn0) * L2E);
                const float e2 = fexp2((c[nt][2] - mn1) * L2E);
                const float e3 = fexp2((c[nt][3] - mn1) * L2E);
                ts0 += e0 + e1;
                ts1 += e2 + e3;
                const int po = (nt >> 1) * 2048 + 2 * (nt & 1);
                *(__half2*)(prow0 + po) = __floats2half2_rn(e0, e1);
                *(__half2*)(prow1 + po) = __floats2half2_rn(e2, e3);
            }
            ts0 += __shfl_xor_sync(0xffffffffu, ts0, 1);
            ts0 += __shfl_xor_sync(0xffffffffu, ts0, 2);
            ts1 += __shfl_xor_sync(0xffffffffu, ts1, 1);
            ts1 += __shfl_xor_sync(0xffffffffu, ts1, 2);
            l0 = l0 * corr0 + ts0;
            l1 = l1 * corr1 + ts1;
            #pragma unroll
            for (int i = 0; i < 8; i++) {
                o[i][0] *= corr0; o[i][1] *= corr0;
                o[i][2] *= corr1; o[i][3] *= corr1;
            }

            // ---- O += P_half @ V_half (own band; no barrier needed) ----
            #pragma unroll
            for (int s = 0; s < 4; s++) {
                const uint2 pa = *(const uint2*)(sa + QP_OFF + ((s * 128 + wm + lr) << 4) + 4 * lc);
                const uint2 pb = *(const uint2*)(sa + QP_OFF + ((s * 128 + wm + lr + 8) << 4) + 4 * lc);
                #pragma unroll
                for (int nt2 = 0; nt2 < 8; nt2++) {
                    const uint2 vb = *(const uint2*)(Vs + (((hf * 4 + s) * 64 + nt2 * 8 + lr) << 4) + 4 * lc);
                    mma_f16(o[nt2][0], o[nt2][1], o[nt2][2], o[nt2][3],
                            pa.x, pb.x, pa.y, pb.y, vb.x, vb.y);
                }
            }
        }
        __syncthreads();       // all reads of KS/VT[buf] done before reuse
    }

    // ---- epilogue: normalize, write k-permuted half2 (feeds GEMM2) ----
    const float inv0 = 1.f / l0, inv1 = 1.f / l1;
    __half* og = out + ((size_t)b * SEQ + qrow0) * 1024 + h * 64;
    #pragma unroll
    for (int nt2 = 0; nt2 < 8; nt2++) {
        const int col = nt2 * 8 + 2 * lc;                       // 0..63 within head
        const int cp2 = (col & ~15) + perm16h(col & 15);
        *(__half2*)(og + cp2) = __floats2half2_rn(o[nt2][0] * inv0, o[nt2][1] * inv0);
        *(__half2*)(og + 8 * 1024 + cp2) = __floats2half2_rn(o[nt2][2] * inv1, o[nt2][3] * inv1);
    }
}

// ---------------------------------------------------------------------------
extern "C" void kernel_launch(void* const* d_in, const int* in_sizes, int n_in,
                              void* d_out, int out_size)
{
    const float* x    = (const float*)d_in[0];
    // d_in[1] = mask (bool tril) — causality handled analytically
    const float* Wqkv = (const float*)d_in[2];
    const float* bqkv = (const float*)d_in[3];
    const float* Wout = (const float*)d_in[4];
    const float* bout = (const float*)d_in[5];
    float* out = (float*)d_out;

    __half *qk_p, *vt_p, *att_p, *xc_p, *wqt_p, *wot_p;
    cudaGetSymbolAddress((void**)&qk_p,  g_qk);
    cudaGetSymbolAddress((void**)&vt_p,  g_vt);
    cudaGetSymbolAddress((void**)&att_p, g_att);
    cudaGetSymbolAddress((void**)&xc_p,  g_xc);
    cudaGetSymbolAddress((void**)&wqt_p, g_wqt);
    cudaGetSymbolAddress((void**)&wot_p, g_wot);

    cudaFuncSetAttribute(gemm_f16_kernel,
                         cudaFuncAttributeMaxDynamicSharedMemorySize, GEMM_SMEM);
    cudaFuncSetAttribute(attn_f16_kernel,
                         cudaFuncAttributeMaxDynamicSharedMemorySize, ATT_SMEM);

    // 0) fp16 + pair-permute operands
    {
        const int ng = MROWS * EMB / 16;
        convert_half_perm_kernel<<<ng / 256, 256>>>(x, xc_p, ng);
    }
    transpose_half_perm_kernel<<<dim3(3 * EMB / 32, EMB / 32), dim3(32, 8)>>>(Wqkv, wqt_p, EMB, 3 * EMB);
    transpose_half_perm_kernel<<<dim3(EMB / 32, EMB / 32),     dim3(32, 8)>>>(Wout, wot_p, EMB, EMB);

    // 1) qkv = x @ W_qkv + b_qkv; q scaled+d-permuted, k d-permuted, v transposed
    gemm_f16_kernel<<<dim3(3 * EMB / 128, MROWS / 128), 128, GEMM_SMEM>>>(
        xc_p, wqt_p, bqkv, nullptr, MROWS, 3 * EMB, EMB, 1);

    // 2) attention (fp16 mma.sync, 2 CTAs/SM, causal + ALiBi)
    attn_f16_kernel<<<dim3(SEQ / 128, HEADS, BATCH), 256, ATT_SMEM>>>(qk_p, vt_p, att_p);

    // 3) out = att @ W_out + b_out (fp32 natural output)
    gemm_f16_kernel<<<dim3(EMB / 128, MROWS / 128), 128, GEMM_SMEM>>>(
        att_p, wot_p, bout, out, MROWS, EMB, EMB, 0);
}

// round 13
// speedup vs baseline: 1.8165x; 1.0080x over previous
#include <cuda_runtime.h>
#include <cuda_fp16.h>
#include <cstdint>
#include <math.h>

#define BATCH 4
#define SEQ   2048
#define EMB   1024
#define HEADS 16
#define HDIM  64
#define MROWS (BATCH*SEQ)   /* 8192 */
#define L2E   1.4426950408889634f

// Pair-permute within 16-half groups: pair p -> pos (p<4 ? 2p : 2(p-4)+1).
// Thread lc's two fragment pairs (lc, lc+4) land adjacent -> one LDS.64.

// Scratch (device globals: allocation-free per harness rules)
__device__ __align__(16) __half g_qk [(size_t)MROWS * 2 * EMB];          // q|k, d-permuted, q scaled
__device__ __align__(16) __half g_vt [(size_t)BATCH * HEADS * HDIM * SEQ]; // V^T, seq-permuted
__device__ __align__(16) __half g_att[(size_t)MROWS * EMB];              // attn out, k-permuted
__device__ __align__(16) __half g_xc [(size_t)MROWS * EMB];              // x, k-permuted
__device__ __align__(16) __half g_wqt[(size_t)3 * EMB * EMB];            // W_qkv^T, k-permuted
__device__ __align__(16) __half g_wot[(size_t)EMB * EMB];                // W_out^T, k-permuted

// ---------------------------------------------------------------------------
// helpers (portable PTX only)
// ---------------------------------------------------------------------------
__device__ __forceinline__ uint32_t smem_u32(const void* p) {
    uint32_t a;
    asm("{ .reg .u64 t; cvta.to.shared.u64 t, %1; cvt.u32.u64 %0, t; }" : "=r"(a) : "l"(p));
    return a;
}
__device__ __forceinline__ float fexp2(float x) {
    float y;
    asm("ex2.approx.f32 %0, %1;" : "=f"(y) : "f"(x));
    return y;
}
__device__ __forceinline__ void cp_async16(uint32_t dst, const void* src) {
    asm volatile("cp.async.cg.shared.global [%0], [%1], 16;" :: "r"(dst), "l"(src));
}
__device__ __forceinline__ void cp_commit() {
    asm volatile("cp.async.commit_group;" ::: "memory");
}
template <int N>
__device__ __forceinline__ void cp_wait() {
    asm volatile("cp.async.wait_group %0;" :: "n"(N) : "memory");
}
__device__ __forceinline__ void mma_f16(float& c0, float& c1, float& c2, float& c3,
                                        uint32_t a0, uint32_t a1, uint32_t a2, uint32_t a3,
                                        uint32_t b0, uint32_t b1) {
    asm volatile(
        "mma.sync.aligned.m16n8k16.row.col.f32.f16.f16.f32 "
        "{%0,%1,%2,%3}, {%4,%5,%6,%7}, {%8,%9}, {%0,%1,%2,%3};"
        : "+f"(c0), "+f"(c1), "+f"(c2), "+f"(c3)
        : "r"(a0), "r"(a1), "r"(a2), "r"(a3), "r"(b0), "r"(b1));
}
__device__ __forceinline__ int perm16h(int j) {   // half index j (0..15) -> permuted pos
    const int p = j >> 1;
    return ((p < 4) ? 4 * p : 4 * p - 14) + (j & 1);
}

// ---------------------------------------------------------------------------
// fp32 -> fp16, pair-permuted per 16-half group (one thread per group)
// ---------------------------------------------------------------------------
__global__ void convert_half_perm_kernel(const float* __restrict__ src,
                                         __half* __restrict__ dst, int ngroups) {
    int g = blockIdx.x * blockDim.x + threadIdx.x;
    if (g >= ngroups) return;
    const float* s = src + (size_t)g * 16;
    __half2 o[8];
    #pragma unroll
    for (int pp = 0; pp < 8; pp++) {
        const int p = (pp & 1) ? ((pp >> 1) + 4) : (pp >> 1);
        o[pp] = __floats2half2_rn(s[2 * p], s[2 * p + 1]);
    }
    *(uint4*)(dst + (size_t)g * 16)     = *(uint4*)(o);
    *(uint4*)(dst + (size_t)g * 16 + 8) = *(uint4*)(o + 4);
}

// ---------------------------------------------------------------------------
// transpose + fp16 + pair-permute: Wt[n][perm(k)] = h(W[k][n])
// ---------------------------------------------------------------------------
__global__ void transpose_half_perm_kernel(const float* __restrict__ W,
                                           __half* __restrict__ Wt, int K, int N) {
    __shared__ float t[32][33];
    const int n0 = blockIdx.x * 32, k0 = blockIdx.y * 32;
    const int x = threadIdx.x, y = threadIdx.y;  // 32 x 8
    #pragma unroll
    for (int i = 0; i < 4; i++)
        t[y + i * 8][x] = W[(size_t)(k0 + y + i * 8) * N + n0 + x];
    __syncthreads();
    const int px = (x & 16) + perm16h(x & 15);
    #pragma unroll
    for (int i = 0; i < 4; i++)
        Wt[(size_t)(n0 + y + i * 8) * K + k0 + px] = __float2half_rn(t[x][y + i * 8]);
}

// ---------------------------------------------------------------------------
// fp16 mma.sync GEMM: C[M,N] = A[M,K] @ Bt[N,K]^T + bias[N]
// Mainloop unchanged (at HMMA issue ceiling). mode=1 epilogue now stages the
// output tile in the (dead) mainloop smem -> fully coalesced uint4 STGs:
//   q/k: smem [row][col-permuted], linear copy to g_qk rows.
//   v:   smem [col(d)][row seq-permuted] (transpose in smem), linear copy
//        to g_vt d-major rows. Permutes applied on cheap smem-write side.
// ---------------------------------------------------------------------------
#define BKH 64
#define TILE_HALFS (4 * 128 * 16)     /* 8192 */
#define STAGE_HALFS (2 * TILE_HALFS)
#define NSTAGE 3
#define GEMM_SMEM (NSTAGE * STAGE_HALFS * 2)   /* 98304 B */
#define ESR 136                        /* epilogue smem row stride (halfs) */

__global__ __launch_bounds__(128, 2)
void gemm_f16_kernel(const __half* __restrict__ A, const __half* __restrict__ Bt,
                     const float* __restrict__ bias, float* __restrict__ Cf,
                     int M, int N, int K, int mode)
{
    extern __shared__ __align__(16) __half sh[];

    const int tid  = threadIdx.x;
    const int wid  = tid >> 5;
    const int lane = tid & 31;
    const int wm   = (wid >> 1) * 64;
    const int wn   = (wid & 1) * 64;
    const int lr   = lane >> 2;
    const int lc   = lane & 3;
    const int n0   = blockIdx.x * 128;
    const int m0   = blockIdx.y * 128;
    const uint32_t smb = smem_u32(sh);

    float c[4][8][4];
    #pragma unroll
    for (int i = 0; i < 4; i++)
        #pragma unroll
        for (int j = 0; j < 8; j++)
            #pragma unroll
            for (int r = 0; r < 4; r++) c[i][j][r] = 0.f;

    auto load_stage = [&](int ch, int s) {
        const __half* Ab = A  + (size_t)m0 * K + ch * BKH;
        const __half* Bb = Bt + (size_t)n0 * K + ch * BKH;
        const uint32_t sA = smb + (uint32_t)(s * STAGE_HALFS) * 2u;
        const uint32_t sB = sA + TILE_HALFS * 2u;
        #pragma unroll
        for (int i = 0; i < 8; i++) {
            const int chk = i * 128 + tid;
            const int hh = chk & 1, row = (chk >> 1) & 127, ss = chk >> 8;
            const uint32_t off = (uint32_t)(((ss * 128 + row) * 16 + hh * 8) * 2);
            const size_t gofs = (size_t)row * K + ss * 16 + hh * 8;
            cp_async16(sA + off, Ab + gofs);
            cp_async16(sB + off, Bb + gofs);
        }
    };

    const int NCH = K / BKH;

    load_stage(0, 0); cp_commit();
    load_stage(1, 1); cp_commit();

    for (int ch = 0; ch < NCH; ch++) {
        cp_wait<1>();
        __syncthreads();
        if (ch + 2 < NCH) load_stage(ch + 2, (ch + 2) % NSTAGE);
        cp_commit();

        const __half* As = sh + (ch % NSTAGE) * STAGE_HALFS;
        const __half* Bs = As + TILE_HALFS;

        #pragma unroll
        for (int s = 0; s < 4; s++) {
            uint2 af[4][2];
            uint2 bf[8];
            #pragma unroll
            for (int mt = 0; mt < 4; mt++) {
                af[mt][0] = *(const uint2*)(As + ((s * 128 + wm + mt * 16 + lr) << 4) + 4 * lc);
                af[mt][1] = *(const uint2*)(As + ((s * 128 + wm + mt * 16 + lr + 8) << 4) + 4 * lc);
            }
            #pragma unroll
            for (int nt = 0; nt < 8; nt++)
                bf[nt] = *(const uint2*)(Bs + ((s * 128 + wn + nt * 8 + lr) << 4) + 4 * lc);
            #pragma unroll
            for (int mt = 0; mt < 4; mt++)
                #pragma unroll
                for (int nt = 0; nt < 8; nt++)
                    mma_f16(c[mt][nt][0], c[mt][nt][1], c[mt][nt][2], c[mt][nt][3],
                            af[mt][0].x, af[mt][1].x, af[mt][0].y, af[mt][1].y,
                            bf[nt].x, bf[nt].y);
        }
        __syncthreads();
    }
    // NOTE: final loop iteration ended with __syncthreads -> smem is free.

    if (mode == 1) {
        const int region = n0 >> 10;               // 0=q, 1=k, 2=v
        if (region < 2) {
            const float sc = (region == 0) ? 0.125f : 1.0f;
            // stage [row][col d-permuted]
            #pragma unroll
            for (int nt = 0; nt < 8; nt++) {
                const int col  = n0 + wn + nt * 8 + 2 * lc;
                const float b0v = bias[col], b1v = bias[col + 1];
                const int lcol = wn + nt * 8 + 2 * lc;
                const int scol = (lcol & ~15) + perm16h(lcol & 15);
                #pragma unroll
                for (int mt = 0; mt < 4; mt++) {
                    const int lrow = wm + mt * 16 + lr;
                    *(__half2*)&sh[lrow * ESR + scol] =
                        __floats2half2_rn((c[mt][nt][0] + b0v) * sc, (c[mt][nt][1] + b1v) * sc);
                    *(__half2*)&sh[(lrow + 8) * ESR + scol] =
                        __floats2half2_rn((c[mt][nt][2] + b0v) * sc, (c[mt][nt][3] + b1v) * sc);
                }
            }
            __syncthreads();
            const int cbase = (region == 1 ? 1024 : 0) + (n0 & 1023);
            #pragma unroll
            for (int it = 0; it < 16; it++) {
                const int id = it * 128 + tid;
                const int lrow = id >> 4, cid = id & 15;
                *(uint4*)&g_qk[(size_t)(m0 + lrow) * 2048 + cbase + cid * 8] =
                    *(const uint4*)&sh[lrow * ESR + cid * 8];
            }
        } else {
            // v: stage transposed [col(d)][row seq-permuted]
            #pragma unroll
            for (int nt = 0; nt < 8; nt++) {
                const int col  = n0 + wn + nt * 8 + 2 * lc;
                const float b0v = bias[col], b1v = bias[col + 1];
                const int lcol = wn + nt * 8 + 2 * lc;
                #pragma unroll
                for (int mt = 0; mt < 4; mt++) {
                    const int lrow = wm + mt * 16 + lr;
                    const int pr0 = (lrow & ~15) + perm16h(lrow & 15);
                    const int pr1 = (lrow & ~15) + perm16h((lrow & 15) + 8);
                    sh[lcol * ESR + pr0]       = __float2half_rn(c[mt][nt][0] + b0v);
                    sh[(lcol + 1) * ESR + pr0] = __float2half_rn(c[mt][nt][1] + b1v);
                    sh[lcol * ESR + pr1]       = __float2half_rn(c[mt][nt][2] + b0v);
                    sh[(lcol + 1) * ESR + pr1] = __float2half_rn(c[mt][nt][3] + b1v);
                }
            }
            __syncthreads();
            const int bb = m0 >> 11, seqb = m0 & 2047;
            #pragma unroll
            for (int it = 0; it < 16; it++) {
                const int id = it * 128 + tid;
                const int lcol = id >> 4, cid = id & 15;
                const int d = (n0 - 2048) + lcol, hh = d >> 6, dd = d & 63;
                *(uint4*)&g_vt[((size_t)(bb * HEADS + hh) * 64 + dd) * 2048 + seqb + cid * 8] =
                    *(const uint4*)&sh[lcol * ESR + cid * 8];
            }
        }
    } else {
        #pragma unroll
        for (int nt = 0; nt < 8; nt++) {
            const int col = n0 + wn + nt * 8 + 2 * lc;
            const float b0v = bias[col], b1v = bias[col + 1];
            #pragma unroll
            for (int mt = 0; mt < 4; mt++) {
                const size_t r0 = (size_t)(m0 + wm + mt * 16 + lr);
                *(float2*)(&Cf[r0 * N + col]) =
                    make_float2(c[mt][nt][0] + b0v, c[mt][nt][1] + b1v);
                *(float2*)(&Cf[(r0 + 8) * N + col]) =
                    make_float2(c[mt][nt][2] + b0v, c[mt][nt][3] + b1v);
            }
        }
    }
}

// ---------------------------------------------------------------------------
// Flash attention, fp16 mma.sync, 2 CTAs/SM (R12 structure) + LPT scheduling:
// longest q-tiles (big qt) launch first to shrink the multi-wave tail.
// ---------------------------------------------------------------------------
#define QP_OFF 0
#define KS_OFF 8192
#define VT_OFF 24576
#define ATT_SMEM ((24576 + 16384) * 2)   /* 81920 B */

__global__ __launch_bounds__(256, 2)
void attn_f16_kernel(const __half* __restrict__ qk, const __half* __restrict__ vt,
                     __half* __restrict__ out)
{
    extern __shared__ __align__(16) __half sa[];

    const int tid  = threadIdx.x;
    const int wid  = tid >> 5;
    const int lane = tid & 31;
    const int lr   = lane >> 2;
    const int lc   = lane & 3;
    const int wm   = wid * 16;
    const int qt   = (gridDim.x - 1) - blockIdx.x;   // LPT: heavy tiles first
    const int h    = blockIdx.y;
    const int b    = blockIdx.z;
    const int q0   = qt * 128;
    const float slope = fexp2(-0.5f * (float)(h + 1));
    const uint32_t smb = smem_u32(sa);

    const __half* baseQ = qk + (size_t)b * SEQ * 2048 + h * 64;
    const __half* baseK = baseQ + 1024;
    const __half* baseV = vt + (size_t)(b * HEADS + h) * 64 * 2048;

    auto load_qk = [&](const __half* g, int row0, int soff) {   // [4][128][16]
        #pragma unroll
        for (int i = 0; i < 4; i++) {
            const int chk = i * 256 + tid;
            const int hh = chk & 1, row = (chk >> 1) & 127, ss = chk >> 8;
            cp_async16(smb + (uint32_t)((soff + (ss * 128 + row) * 16 + hh * 8) * 2),
                       g + (size_t)(row0 + row) * 2048 + ss * 16 + hh * 8);
        }
    };
    auto load_vt = [&](int kt, int soff) {                      // [8][64][16]
        #pragma unroll
        for (int i = 0; i < 4; i++) {
            const int chk = i * 256 + tid;
            const int hh = chk & 1, d = (chk >> 1) & 63, ss = chk >> 7;
            cp_async16(smb + (uint32_t)((soff + (ss * 64 + d) * 16 + hh * 8) * 2),
                       baseV + (size_t)d * 2048 + kt * 128 + ss * 16 + hh * 8);
        }
    };

    load_qk(baseQ, q0, QP_OFF);
    load_qk(baseK, 0, KS_OFF);
    load_vt(0, VT_OFF);
    cp_commit();

    uint2 qf[4][2];                      // Q fragments, hoisted at kt==0
    float m0 = -1e30f, m1 = -1e30f, l0 = 0.f, l1 = 0.f;
    float o[8][4];
    #pragma unroll
    for (int i = 0; i < 8; i++)
        #pragma unroll
        for (int r = 0; r < 4; r++) o[i][r] = 0.f;

    const int qrow0 = q0 + wm + lr;
    const int qrow1 = qrow0 + 8;

    for (int kt = 0; kt <= qt; kt++) {
        const int buf = kt & 1;
        if (kt < qt) {
            load_qk(baseK, (kt + 1) * 128, KS_OFF + (buf ^ 1) * 8192);
            load_vt(kt + 1, VT_OFF + (buf ^ 1) * 8192);
        }
        cp_commit();
        cp_wait<1>();
        __syncthreads();

        if (kt == 0) {                   // hoist Q fragments (own band only)
            #pragma unroll
            for (int s = 0; s < 4; s++) {
                qf[s][0] = *(const uint2*)(sa + QP_OFF + ((s * 128 + wm + lr) << 4) + 4 * lc);
                qf[s][1] = *(const uint2*)(sa + QP_OFF + ((s * 128 + wm + lr + 8) << 4) + 4 * lc);
            }
        }

        const __half* Ks = sa + KS_OFF + buf * 8192;
        const __half* Vs = sa + VT_OFF + buf * 8192;

        #pragma unroll
        for (int hf = 0; hf < 2; hf++) {
            // ---- S half: 128q x 64k ----
            float c[8][4];
            #pragma unroll
            for (int nt = 0; nt < 8; nt++)
                #pragma unroll
                for (int r = 0; r < 4; r++) c[nt][r] = 0.f;

            #pragma unroll
            for (int s = 0; s < 4; s++) {
                #pragma unroll
                for (int nt = 0; nt < 8; nt++) {
                    const uint2 kb2 = *(const uint2*)(Ks + ((s * 128 + hf * 64 + nt * 8 + lr) << 4) + 4 * lc);
                    mma_f16(c[nt][0], c[nt][1], c[nt][2], c[nt][3],
                            qf[s][0].x, qf[s][1].x, qf[s][0].y, qf[s][1].y,
                            kb2.x, kb2.y);
                }
            }

            // ---- ALiBi + (diagonal-only) mask + online softmax over 64 cols ----
            const int kb = kt * 128 + hf * 64 + 2 * lc;
            float al0 = slope * (float)(kb - qrow0);
            float al1 = slope * (float)(kb - qrow1);
            const float st8 = 8.f * slope;
            float mx0 = -1e30f, mx1 = -1e30f;
            #pragma unroll
            for (int nt = 0; nt < 8; nt++) {
                float s0 = c[nt][0] + al0;
                float s1 = c[nt][1] + al0 + slope;
                float s2 = c[nt][2] + al1;
                float s3 = c[nt][3] + al1 + slope;
                if (kt == qt) {
                    const int k0c = kb + nt * 8, k1c = k0c + 1;
                    if (k0c > qrow0) s0 = -1e30f;
                    if (k1c > qrow0) s1 = -1e30f;
                    if (k0c > qrow1) s2 = -1e30f;
                    if (k1c > qrow1) s3 = -1e30f;
                }
                c[nt][0] = s0; c[nt][1] = s1; c[nt][2] = s2; c[nt][3] = s3;
                mx0 = fmaxf(mx0, fmaxf(s0, s1));
                mx1 = fmaxf(mx1, fmaxf(s2, s3));
                al0 += st8; al1 += st8;
            }
            mx0 = fmaxf(mx0, __shfl_xor_sync(0xffffffffu, mx0, 1));
            mx0 = fmaxf(mx0, __shfl_xor_sync(0xffffffffu, mx0, 2));
            mx1 = fmaxf(mx1, __shfl_xor_sync(0xffffffffu, mx1, 1));
            mx1 = fmaxf(mx1, __shfl_xor_sync(0xffffffffu, mx1, 2));

            const float mn0 = fmaxf(m0, mx0), mn1 = fmaxf(m1, mx1);
            const float corr0 = fexp2((m0 - mn0) * L2E);
            const float corr1 = fexp2((m1 - mn1) * L2E);
            m0 = mn0; m1 = mn1;

            float ts0 = 0.f, ts1 = 0.f;
            __half* prow0 = sa + QP_OFF + (wm + lr) * 16 + 4 * lc;
            __half* prow1 = prow0 + 8 * 16;
            #pragma unroll
            for (int nt = 0; nt < 8; nt++) {
                const float e0 = fexp2((c[nt][0] - mn0) * L2E);
                const float e1 = fexp2((c[nt][1] - mn0) * L2E);
                const float e2 = fexp2((c[nt][2] - mn1) * L2E);
                const float e3 = fexp2((c[nt][3] - mn1) * L2E);
                ts0 += e0 + e1;
                ts1 += e2 + e3;
                const int po = (nt >> 1) * 2048 + 2 * (nt & 1);
                *(__half2*)(prow0 + po) = __floats2half2_rn(e0, e1);
                *(__half2*)(prow1 + po) = __floats2half2_rn(e2, e3);
            }
            ts0 += __shfl_xor_sync(0xffffffffu, ts0, 1);
            ts0 += __shfl_xor_sync(0xffffffffu, ts0, 2);
            ts1 += __shfl_xor_sync(0xffffffffu, ts1, 1);
            ts1 += __shfl_xor_sync(0xffffffffu, ts1, 2);
            l0 = l0 * corr0 + ts0;
            l1 = l1 * corr1 + ts1;
            #pragma unroll
            for (int i = 0; i < 8; i++) {
                o[i][0] *= corr0; o[i][1] *= corr0;
                o[i][2] *= corr1; o[i][3] *= corr1;
            }

            // ---- O += P_half @ V_half (own band; no barrier needed) ----
            #pragma unroll
            for (int s = 0; s < 4; s++) {
                const uint2 pa = *(const uint2*)(sa + QP_OFF + ((s * 128 + wm + lr) << 4) + 4 * lc);
                const uint2 pb = *(const uint2*)(sa + QP_OFF + ((s * 128 + wm + lr + 8) << 4) + 4 * lc);
                #pragma unroll
                for (int nt2 = 0; nt2 < 8; nt2++) {
                    const uint2 vb = *(const uint2*)(Vs + (((hf * 4 + s) * 64 + nt2 * 8 + lr) << 4) + 4 * lc);
                    mma_f16(o[nt2][0], o[nt2][1], o[nt2][2], o[nt2][3],
                            pa.x, pb.x, pa.y, pb.y, vb.x, vb.y);
                }
            }
        }
        __syncthreads();       // all reads of KS/VT[buf] done before reuse
    }

    // ---- epilogue: normalize, write k-permuted half2 (feeds GEMM2) ----
    const float inv0 = 1.f / l0, inv1 = 1.f / l1;
    __half* og = out + ((size_t)b * SEQ + qrow0) * 1024 + h * 64;
    #pragma unroll
    for (int nt2 = 0; nt2 < 8; nt2++) {
        const int col = nt2 * 8 + 2 * lc;                       // 0..63 within head
        const int cp2 = (col & ~15) + perm16h(col & 15);
        *(__half2*)(og + cp2) = __floats2half2_rn(o[nt2][0] * inv0, o[nt2][1] * inv0);
        *(__half2*)(og + 8 * 1024 + cp2) = __floats2half2_rn(o[nt2][2] * inv1, o[nt2][3] * inv1);
    }
}

// ---------------------------------------------------------------------------
extern "C" void kernel_launch(void* const* d_in, const int* in_sizes, int n_in,
                              void* d_out, int out_size)
{
    const float* x    = (const float*)d_in[0];
    // d_in[1] = mask (bool tril) — causality handled analytically
    const float* Wqkv = (const float*)d_in[2];
    const float* bqkv = (const float*)d_in[3];
    const float* Wout = (const float*)d_in[4];
    const float* bout = (const float*)d_in[5];
    float* out = (float*)d_out;

    __half *qk_p, *vt_p, *att_p, *xc_p, *wqt_p, *wot_p;
    cudaGetSymbolAddress((void**)&qk_p,  g_qk);
    cudaGetSymbolAddress((void**)&vt_p,  g_vt);
    cudaGetSymbolAddress((void**)&att_p, g_att);
    cudaGetSymbolAddress((void**)&xc_p,  g_xc);
    cudaGetSymbolAddress((void**)&wqt_p, g_wqt);
    cudaGetSymbolAddress((void**)&wot_p, g_wot);

    cudaFuncSetAttribute(gemm_f16_kernel,
                         cudaFuncAttributeMaxDynamicSharedMemorySize, GEMM_SMEM);
    cudaFuncSetAttribute(attn_f16_kernel,
                         cudaFuncAttributeMaxDynamicSharedMemorySize, ATT_SMEM);

    // 0) fp16 + pair-permute operands
    {
        const int ng = MROWS * EMB / 16;
        convert_half_perm_kernel<<<ng / 256, 256>>>(x, xc_p, ng);
    }
    transpose_half_perm_kernel<<<dim3(3 * EMB / 32, EMB / 32), dim3(32, 8)>>>(Wqkv, wqt_p, EMB, 3 * EMB);
    transpose_half_perm_kernel<<<dim3(EMB / 32, EMB / 32),     dim3(32, 8)>>>(Wout, wot_p, EMB, EMB);

    // 1) qkv = x @ W_qkv + b_qkv; q scaled+d-permuted, k d-permuted, v transposed
    gemm_f16_kernel<<<dim3(3 * EMB / 128, MROWS / 128), 128, GEMM_SMEM>>>(
        xc_p, wqt_p, bqkv, nullptr, MROWS, 3 * EMB, EMB, 1);

    // 2) attention (fp16 mma.sync, 2 CTAs/SM, LPT order, causal + ALiBi)
    attn_f16_kernel<<<dim3(SEQ / 128, HEADS, BATCH), 256, ATT_SMEM>>>(qk_p, vt_p, att_p);

    // 3) out = att @ W_out + b_out (fp32 natural output)
    gemm_f16_kernel<<<dim3(EMB / 128, MROWS / 128), 128, GEMM_SMEM>>>(
        att_p, wot_p, bout, out, MROWS, EMB, EMB, 0);
}